// round 3
// baseline (speedup 1.0000x reference)
#include <cuda_runtime.h>
#include <math.h>
#include <cstdint>

// ---------------- problem constants ----------------
constexpr int Bc = 2, Sc = 1024, Dc = 1024, Hc = 16, Lc = 9, Wc = 1024, Pc = 128, Vc = 256;
constexpr int DH = Dc / Hc;          // 64
constexpr int BS = Bc * Sc;          // 2048 rows

typedef unsigned long long ull;

// ---------------- device scratch (allocation-free: static globals) ----------------
__device__ float g_x   [BS * Dc];            // residual stream
__device__ float g_h   [BS * Dc];            // LN output
__device__ float g_qkv [BS * 3 * Dc];        // self-attn qkv
__device__ float g_caq [BS * Dc];            // cross-attn q
__device__ float g_cakv[Bc * Pc * 2 * Dc];   // cross-attn k,v
__device__ float g_sc  [(long)Bc * Hc * Sc * Sc]; // attention scores (reused for CA)
__device__ float g_ao  [BS * Dc];            // attention output (pre-proj)
__device__ float g_ffn [BS * 4 * Dc];        // ffn hidden
__device__ int   g_pidx[BS];                 // cumsum of patch boundaries

// ---------------- reductions ----------------
__device__ __forceinline__ float block_sum(float v) {
    __shared__ float sh[32];
    int lane = threadIdx.x & 31, w = threadIdx.x >> 5;
    int nw = blockDim.x >> 5;
    #pragma unroll
    for (int o = 16; o; o >>= 1) v += __shfl_xor_sync(0xffffffffu, v, o);
    __syncthreads();
    if (lane == 0) sh[w] = v;
    __syncthreads();
    if (threadIdx.x == 0) {
        float t = 0.f;
        for (int i = 0; i < nw; i++) t += sh[i];
        sh[0] = t;
    }
    __syncthreads();
    return sh[0];
}

__device__ __forceinline__ float block_max(float v) {
    __shared__ float sh[32];
    int lane = threadIdx.x & 31, w = threadIdx.x >> 5;
    int nw = blockDim.x >> 5;
    #pragma unroll
    for (int o = 16; o; o >>= 1) v = fmaxf(v, __shfl_xor_sync(0xffffffffu, v, o));
    __syncthreads();
    if (lane == 0) sh[w] = v;
    __syncthreads();
    if (threadIdx.x == 0) {
        float t = -1e30f;
        for (int i = 0; i < nw; i++) t = fmaxf(t, sh[i]);
        sh[0] = t;
    }
    __syncthreads();
    return sh[0];
}

// packed f32x2 helpers
__device__ __forceinline__ ull dup_f32x2(float a) {
    ull r;
    unsigned au = __float_as_uint(a);
    asm("mov.b64 %0, {%1, %1};" : "=l"(r) : "r"(au));
    return r;
}
__device__ __forceinline__ void fma_f32x2(ull& acc, ull a, ull b) {
    asm("fma.rn.f32x2 %0, %1, %2, %0;" : "+l"(acc) : "l"(a), "l"(b));
}

// ---------------- generic SGEMM (FFMA2 inner loop) ----------------
// C[m,n] = scale * sum_k A[m,k] * (BT ? B[n,k] : B[k,n])   (+bias[n]) (+gelu) (+res)
// Batched: per-z pointer offset = (z/nlo)*hi + (z%nlo)*lo  (covers (b,h) batching)
// EPI: 0 = none, 1 = +bias, 2 = +bias then GELU, 3 = +bias +residual
template<int EPI, bool BT, int BN_, int TN_>
__global__ __launch_bounds__(256, 2)
void gemm_k(const float* __restrict__ A, int lda, long sAhi, long sAlo, int nloA,
            const float* __restrict__ Bm, int ldb, long sBhi, long sBlo, int nloB,
            const float* __restrict__ bias,
            const float* __restrict__ Res,
            float* __restrict__ C, int ldc, long sChi, long sClo, int nloC,
            int K, float scale)
{
    constexpr int BM = 128, BK = 16, TM = 8;
    constexpr int TN2 = TN_ / 2;
    const int tid = threadIdx.x;
    const int z = blockIdx.z;
    A  += (long)(z / nloA) * sAhi + (long)(z % nloA) * sAlo;
    Bm += (long)(z / nloB) * sBhi + (long)(z % nloB) * sBlo;
    const long coff = (long)(z / nloC) * sChi + (long)(z % nloC) * sClo;
    C += coff;
    const float* res = (EPI == 3) ? Res + coff : nullptr;

    const int m0 = blockIdx.y * BM;
    const int n0 = blockIdx.x * BN_;

    __shared__ float As[BK][BM + 4];
    __shared__ float Bs[BK][BN_ + 4];

    ull acc2[TM][TN2];
    #pragma unroll
    for (int i = 0; i < TM; i++)
        #pragma unroll
        for (int j = 0; j < TN2; j++) acc2[i][j] = 0ull;

    const int ty = tid >> 4;  // 0..15 -> M
    const int tx = tid & 15;  // 0..15 -> N

    for (int k0 = 0; k0 < K; k0 += BK) {
        // ---- load A tile [BM x BK], store transposed
        {
            int r = tid >> 1;
            int c = (tid & 1) * 8;
            const float* src = A + (long)(m0 + r) * lda + (k0 + c);
            float4 v0 = *(const float4*)src;
            float4 v1 = *(const float4*)(src + 4);
            As[c + 0][r] = v0.x; As[c + 1][r] = v0.y; As[c + 2][r] = v0.z; As[c + 3][r] = v0.w;
            As[c + 4][r] = v1.x; As[c + 5][r] = v1.y; As[c + 6][r] = v1.z; As[c + 7][r] = v1.w;
        }
        // ---- load B tile
        if constexpr (BT) {
            if constexpr (BN_ == 128) {
                int r = tid >> 1;
                int c = (tid & 1) * 8;
                const float* src = Bm + (long)(n0 + r) * ldb + (k0 + c);
                float4 v0 = *(const float4*)src;
                float4 v1 = *(const float4*)(src + 4);
                Bs[c + 0][r] = v0.x; Bs[c + 1][r] = v0.y; Bs[c + 2][r] = v0.z; Bs[c + 3][r] = v0.w;
                Bs[c + 4][r] = v1.x; Bs[c + 5][r] = v1.y; Bs[c + 6][r] = v1.z; Bs[c + 7][r] = v1.w;
            } else {
                int r = tid >> 2;
                int c = (tid & 3) * 4;
                float4 v = *(const float4*)(Bm + (long)(n0 + r) * ldb + (k0 + c));
                Bs[c + 0][r] = v.x; Bs[c + 1][r] = v.y; Bs[c + 2][r] = v.z; Bs[c + 3][r] = v.w;
            }
        } else {
            if constexpr (BN_ == 64) {
                int r = tid >> 4;          // k
                int c = (tid & 15) * 4;    // n
                float4 v = *(const float4*)(Bm + (long)(k0 + r) * ldb + (n0 + c));
                *(float4*)&Bs[r][c] = v;
            } else {
                int r = tid >> 4;
                int c = (tid & 15) * 8;
                const float* src = Bm + (long)(k0 + r) * ldb + (n0 + c);
                *(float4*)&Bs[r][c]     = *(const float4*)src;
                *(float4*)&Bs[r][c + 4] = *(const float4*)(src + 4);
            }
        }
        __syncthreads();

        #pragma unroll
        for (int k = 0; k < BK; k++) {
            float a[TM];
            *(float4*)&a[0] = *(const float4*)&As[k][ty * TM];
            *(float4*)&a[4] = *(const float4*)&As[k][ty * TM + 4];
            // b as packed f32x2 pairs (rows of Bs are 16B-aligned: stride BN_+4)
            ull b2[TN2];
            {
                ulonglong2 q0 = *(const ulonglong2*)&Bs[k][tx * TN_];
                b2[0] = q0.x; b2[1] = q0.y;
                if constexpr (TN2 == 4) {
                    ulonglong2 q1 = *(const ulonglong2*)&Bs[k][tx * TN_ + 4];
                    b2[2] = q1.x; b2[3] = q1.y;
                }
            }
            #pragma unroll
            for (int i = 0; i < TM; i++) {
                ull a2 = dup_f32x2(a[i]);
                #pragma unroll
                for (int j = 0; j < TN2; j++)
                    fma_f32x2(acc2[i][j], a2, b2[j]);
            }
        }
        __syncthreads();
    }

    // ---- epilogue
    #pragma unroll
    for (int i = 0; i < TM; i++) {
        int m = m0 + ty * TM + i;
        float* crow = C + (long)m * ldc + n0 + tx * TN_;
        #pragma unroll
        for (int j4 = 0; j4 < TN_; j4 += 4) {
            float4 o;
            float* po = &o.x;
            #pragma unroll
            for (int j = 0; j < 4; j++) {
                float2 pr = *(float2*)&acc2[i][(j4 + j) >> 1];
                float av = ((j & 1) == 0) ? pr.x : pr.y;
                float v = av * scale;
                if (EPI >= 1) v += bias[n0 + tx * TN_ + j4 + j];
                if (EPI == 2) v = 0.5f * v * (1.f + erff(v * 0.70710678118654752f));
                po[j] = v;
            }
            if (EPI == 3) {
                float4 rv = *(const float4*)(res + (long)m * ldc + n0 + tx * TN_ + j4);
                o.x += rv.x; o.y += rv.y; o.z += rv.z; o.w += rv.w;
            }
            *(float4*)(crow + j4) = o;
        }
    }
}

// ---------------- embedding ----------------
__global__ void embed_k(const int* __restrict__ seq, const float* __restrict__ bemb,
                        const float* __restrict__ pemb, float* __restrict__ x)
{
    int r = blockIdx.x;          // b*S + s
    int s = r % Sc;
    int tok = seq[r];
    int c = threadIdx.x * 4;
    float4 e = *(const float4*)(bemb + (long)tok * Dc + c);
    float4 p = *(const float4*)(pemb + (long)s * Dc + c);
    e.x += p.x; e.y += p.y; e.z += p.z; e.w += p.w;
    *(float4*)(x + (long)r * Dc + c) = e;
}

// ---------------- layernorm (row-per-block, D=1024, 256 threads) ----------------
__global__ void ln_k(const float* __restrict__ x, const float* __restrict__ g,
                     const float* __restrict__ b, float* __restrict__ out)
{
    const int row = blockIdx.x;
    const int tid = threadIdx.x;
    const float* xr = x + (long)row * Dc;
    float4 v = *(const float4*)(xr + tid * 4);
    float s = v.x + v.y + v.z + v.w;
    float tot = block_sum(s);
    float m = tot * (1.f / Dc);
    float dx0 = v.x - m, dx1 = v.y - m, dx2 = v.z - m, dx3 = v.w - m;
    float q = dx0 * dx0 + dx1 * dx1 + dx2 * dx2 + dx3 * dx3;
    float totq = block_sum(q);
    float rs = rsqrtf(totq * (1.f / Dc) + 1e-5f);
    float4 gg = *(const float4*)(g + tid * 4);
    float4 bb = *(const float4*)(b + tid * 4);
    float4 o;
    o.x = dx0 * rs * gg.x + bb.x;
    o.y = dx1 * rs * gg.y + bb.y;
    o.z = dx2 * rs * gg.z + bb.z;
    o.w = dx3 * rs * gg.w + bb.w;
    *(float4*)(out + (long)row * Dc + tid * 4) = o;
}

// ---------------- self-attn softmax (causal window) ----------------
__global__ void smax_sa(float* __restrict__ sc)
{
    const int i = blockIdx.x;     // query position
    const int z = blockIdx.y;     // b*H + h
    float* row = sc + ((long)z * Sc + i) * Sc;
    const int tid = threadIdx.x;  // 256
    int lo = i - Wc + 1; if (lo < 0) lo = 0;
    const int hi = i;
    float v[4];
    float mx = -1e30f;
    #pragma unroll
    for (int t = 0; t < 4; t++) {
        int j = tid + t * 256;
        bool ok = (j >= lo) && (j <= hi);
        v[t] = ok ? row[j] : -1e30f;
        mx = fmaxf(mx, v[t]);
    }
    mx = block_max(mx);
    float s = 0.f;
    #pragma unroll
    for (int t = 0; t < 4; t++) {
        int j = tid + t * 256;
        bool ok = (j >= lo) && (j <= hi);
        v[t] = ok ? expf(v[t] - mx) : 0.f;
        s += v[t];
    }
    s = block_sum(s);
    float inv = 1.f / s;
    #pragma unroll
    for (int t = 0; t < 4; t++)
        row[tid + t * 256] = v[t] * inv;
}

// ---------------- cross-attn softmax (patch mask) ----------------
__global__ void smax_ca(float* __restrict__ sc, const int* __restrict__ pidx)
{
    const int i = blockIdx.x;
    const int z = blockIdx.y;
    const int b = z / Hc;
    float* row = sc + ((long)z * Sc + i) * Pc;
    const int tid = threadIdx.x;  // 128
    const int lim = pidx[b * Sc + i];
    bool ok = tid <= lim;
    float v = ok ? row[tid] : -1e30f;
    float mx = block_max(v);
    float e = ok ? expf(v - mx) : 0.f;
    float s = block_sum(e);
    row[tid] = e / s;
}

// ---------------- inclusive cumsum of patch boundaries ----------------
__global__ void cumsum_k(const int* __restrict__ bd, int* __restrict__ pidx)
{
    __shared__ int s[Sc];
    const int b = blockIdx.x, t = threadIdx.x;  // 1024 threads
    s[t] = bd[b * Sc + t];
    __syncthreads();
    for (int off = 1; off < Sc; off <<= 1) {
        int v = (t >= off) ? s[t - off] : 0;
        __syncthreads();
        s[t] += v;
        __syncthreads();
    }
    pidx[b * Sc + t] = s[t];
}

// ---------------- launcher ----------------
extern "C" void kernel_launch(void* const* d_in, const int* in_sizes, int n_in,
                              void* d_out, int out_size)
{
    const int*   byte_seq  = (const int*)  d_in[0];
    const float* patch_rep = (const float*)d_in[1];
    const int*   patch_bd  = (const int*)  d_in[2];
    const float* byte_emb  = (const float*)d_in[3];
    const float* pos_emb   = (const float*)d_in[4];
    const float* sa_in_w   = (const float*)d_in[5];
    const float* sa_in_b   = (const float*)d_in[6];
    const float* sa_out_w  = (const float*)d_in[7];
    const float* sa_out_b  = (const float*)d_in[8];
    const float* ca_in_w   = (const float*)d_in[9];
    const float* ca_in_b   = (const float*)d_in[10];
    const float* ca_out_w  = (const float*)d_in[11];
    const float* ca_out_b  = (const float*)d_in[12];
    const float* ffn_w1    = (const float*)d_in[13];
    const float* ffn_b1    = (const float*)d_in[14];
    const float* ffn_w2    = (const float*)d_in[15];
    const float* ffn_b2    = (const float*)d_in[16];
    const float* ln_g      = (const float*)d_in[17];
    const float* ln_b      = (const float*)d_in[18];
    const float* norm_g    = (const float*)d_in[19];
    const float* norm_b    = (const float*)d_in[20];
    const float* out_w     = (const float*)d_in[21];
    float* out = (float*)d_out;

    float *gx, *gh, *gqkv, *gcaq, *gcakv, *gsc, *gao, *gffn;
    int* gpidx;
    cudaGetSymbolAddress((void**)&gx,    g_x);
    cudaGetSymbolAddress((void**)&gh,    g_h);
    cudaGetSymbolAddress((void**)&gqkv,  g_qkv);
    cudaGetSymbolAddress((void**)&gcaq,  g_caq);
    cudaGetSymbolAddress((void**)&gcakv, g_cakv);
    cudaGetSymbolAddress((void**)&gsc,   g_sc);
    cudaGetSymbolAddress((void**)&gao,   g_ao);
    cudaGetSymbolAddress((void**)&gffn,  g_ffn);
    cudaGetSymbolAddress((void**)&gpidx, g_pidx);

    // embedding + patch index cumsum
    embed_k<<<BS, 256>>>(byte_seq, byte_emb, pos_emb, gx);
    cumsum_k<<<Bc, Sc>>>(patch_bd, gpidx);

    for (int l = 0; l < Lc; l++) {
        // ===== self-attention =====
        ln_k<<<BS, 256>>>(gx, ln_g + (long)(l * 3 + 0) * Dc, ln_b + (long)(l * 3 + 0) * Dc, gh);

        // QKV: [BS, D] @ [3D, D]^T
        gemm_k<1, true, 128, 8><<<dim3(3 * Dc / 128, BS / 128, 1), 256>>>(
            gh, Dc, 0, 0, 1,
            sa_in_w + (long)l * 3 * Dc * Dc, Dc, 0, 0, 1,
            sa_in_b + (long)l * 3 * Dc, nullptr,
            gqkv, 3 * Dc, 0, 0, 1, Dc, 1.f);

        // scores[z=b*H+h]: Q @ K^T / 8
        gemm_k<0, true, 128, 8><<<dim3(Sc / 128, Sc / 128, Bc * Hc), 256>>>(
            gqkv,      3 * Dc, (long)Sc * 3 * Dc, DH, Hc,
            gqkv + Dc, 3 * Dc, (long)Sc * 3 * Dc, DH, Hc,
            nullptr, nullptr,
            gsc, Sc, (long)Sc * Sc, 0, 1,
            DH, 0.125f);

        smax_sa<<<dim3(Sc, Bc * Hc), 256>>>(gsc);

        // attn @ V
        gemm_k<0, false, 64, 4><<<dim3(1, Sc / 128, Bc * Hc), 256>>>(
            gsc, Sc, (long)Sc * Sc, 0, 1,
            gqkv + 2 * Dc, 3 * Dc, (long)Sc * 3 * Dc, DH, Hc,
            nullptr, nullptr,
            gao, Dc, (long)Sc * Dc, DH, Hc,
            Sc, 1.f);

        // out proj + residual
        gemm_k<3, true, 128, 8><<<dim3(Dc / 128, BS / 128, 1), 256>>>(
            gao, Dc, 0, 0, 1,
            sa_out_w + (long)l * Dc * Dc, Dc, 0, 0, 1,
            sa_out_b + (long)l * Dc, gx,
            gx, Dc, 0, 0, 1, Dc, 1.f);

        // ===== cross-attention =====
        ln_k<<<BS, 256>>>(gx, ln_g + (long)(l * 3 + 1) * Dc, ln_b + (long)(l * 3 + 1) * Dc, gh);

        // Q proj (rows 0:D of ca_in_w)
        gemm_k<1, true, 128, 8><<<dim3(Dc / 128, BS / 128, 1), 256>>>(
            gh, Dc, 0, 0, 1,
            ca_in_w + (long)l * 3 * Dc * Dc, Dc, 0, 0, 1,
            ca_in_b + (long)l * 3 * Dc, nullptr,
            gcaq, Dc, 0, 0, 1, Dc, 1.f);

        // KV proj on patch reps (rows D:3D of ca_in_w), M = B*P = 256
        gemm_k<1, true, 128, 8><<<dim3(2 * Dc / 128, (Bc * Pc) / 128, 1), 256>>>(
            patch_rep, Dc, 0, 0, 1,
            ca_in_w + (long)l * 3 * Dc * Dc + (long)Dc * Dc, Dc, 0, 0, 1,
            ca_in_b + (long)l * 3 * Dc + Dc, nullptr,
            gcakv, 2 * Dc, 0, 0, 1, Dc, 1.f);

        // CA scores: [S, P] per (b,h)
        gemm_k<0, true, 128, 8><<<dim3(Pc / 128, Sc / 128, Bc * Hc), 256>>>(
            gcaq,  Dc,     (long)Sc * Dc,     DH, Hc,
            gcakv, 2 * Dc, (long)Pc * 2 * Dc, DH, Hc,
            nullptr, nullptr,
            gsc, Pc, (long)Sc * Pc, 0, 1,
            DH, 0.125f);

        smax_ca<<<dim3(Sc, Bc * Hc), 128>>>(gsc, gpidx);

        // CA attn @ V (K = P = 128)
        gemm_k<0, false, 64, 4><<<dim3(1, Sc / 128, Bc * Hc), 256>>>(
            gsc, Pc, (long)Sc * Pc, 0, 1,
            gcakv + Dc, 2 * Dc, (long)Pc * 2 * Dc, DH, Hc,
            nullptr, nullptr,
            gao, Dc, (long)Sc * Dc, DH, Hc,
            Pc, 1.f);

        // CA out proj + residual
        gemm_k<3, true, 128, 8><<<dim3(Dc / 128, BS / 128, 1), 256>>>(
            gao, Dc, 0, 0, 1,
            ca_out_w + (long)l * Dc * Dc, Dc, 0, 0, 1,
            ca_out_b + (long)l * Dc, gx,
            gx, Dc, 0, 0, 1, Dc, 1.f);

        // ===== FFN =====
        ln_k<<<BS, 256>>>(gx, ln_g + (long)(l * 3 + 2) * Dc, ln_b + (long)(l * 3 + 2) * Dc, gh);

        // FFN1 + GELU
        gemm_k<2, true, 128, 8><<<dim3(4 * Dc / 128, BS / 128, 1), 256>>>(
            gh, Dc, 0, 0, 1,
            ffn_w1 + (long)l * 4 * Dc * Dc, Dc, 0, 0, 1,
            ffn_b1 + (long)l * 4 * Dc, nullptr,
            gffn, 4 * Dc, 0, 0, 1, Dc, 1.f);

        // FFN2 + residual
        gemm_k<3, true, 128, 8><<<dim3(Dc / 128, BS / 128, 1), 256>>>(
            gffn, 4 * Dc, 0, 0, 1,
            ffn_w2 + (long)l * Dc * 4 * Dc, 4 * Dc, 0, 0, 1,
            ffn_b2 + (long)l * Dc, gx,
            gx, Dc, 0, 0, 1, 4 * Dc, 1.f);
    }

    // final LN + vocab projection (no bias)
    ln_k<<<BS, 256>>>(gx, norm_g, norm_b, gh);
    gemm_k<0, true, 128, 8><<<dim3(Vc / 128, BS / 128, 1), 256>>>(
        gh, Dc, 0, 0, 1,
        out_w, Dc, 0, 0, 1,
        nullptr, nullptr,
        out, Vc, 0, 0, 1, Dc, 1.f);
}

// round 5
// speedup vs baseline: 1.4191x; 1.4191x over previous
#include <cuda_runtime.h>
#include <cuda_bf16.h>
#include <math.h>
#include <cstdint>

// ---------------- problem constants ----------------
constexpr int Bc = 2, Sc = 1024, Dc = 1024, Hc = 16, Lc = 9, Wc = 1024, Pc = 128, Vc = 256;
constexpr int DH = Dc / Hc;          // 64
constexpr int BS = Bc * Sc;          // 2048 rows

typedef unsigned long long ull;

// ---------------- device scratch (allocation-free: static globals) ----------------
__device__ float g_x   [BS * Dc];
__device__ float g_h   [BS * Dc];
__device__ float g_qkv [BS * 3 * Dc];
__device__ float g_caq [BS * Dc];
__device__ float g_cakv[Bc * Pc * 2 * Dc];
__device__ float g_sc  [(long)Bc * Hc * Sc * Sc];
__device__ float g_ao  [BS * Dc];
__device__ float g_ffn [BS * 4 * Dc];
__device__ int   g_pidx[BS];

// ---------------- reductions ----------------
__device__ __forceinline__ float block_sum(float v) {
    __shared__ float sh[32];
    int lane = threadIdx.x & 31, w = threadIdx.x >> 5;
    int nw = blockDim.x >> 5;
    #pragma unroll
    for (int o = 16; o; o >>= 1) v += __shfl_xor_sync(0xffffffffu, v, o);
    __syncthreads();
    if (lane == 0) sh[w] = v;
    __syncthreads();
    if (threadIdx.x == 0) {
        float t = 0.f;
        for (int i = 0; i < nw; i++) t += sh[i];
        sh[0] = t;
    }
    __syncthreads();
    return sh[0];
}

__device__ __forceinline__ float block_max(float v) {
    __shared__ float sh[32];
    int lane = threadIdx.x & 31, w = threadIdx.x >> 5;
    int nw = blockDim.x >> 5;
    #pragma unroll
    for (int o = 16; o; o >>= 1) v = fmaxf(v, __shfl_xor_sync(0xffffffffu, v, o));
    __syncthreads();
    if (lane == 0) sh[w] = v;
    __syncthreads();
    if (threadIdx.x == 0) {
        float t = -1e30f;
        for (int i = 0; i < nw; i++) t = fmaxf(t, sh[i]);
        sh[0] = t;
    }
    __syncthreads();
    return sh[0];
}

// ================= bf16x3 mma.sync GEMM =================
__device__ __forceinline__ uint32_t s2u(const void* p) {
    return (uint32_t)__cvta_generic_to_shared(p);
}

#define LDSM4(R, addr) \
    asm volatile("ldmatrix.sync.aligned.m8n8.x4.shared.b16 {%0,%1,%2,%3}, [%4];" \
        : "=r"((R)[0]), "=r"((R)[1]), "=r"((R)[2]), "=r"((R)[3]) : "r"(addr))

#define MMA16816(d, a, b0, b1) \
    asm volatile("mma.sync.aligned.m16n8k16.row.col.f32.bf16.bf16.f32 " \
        "{%0,%1,%2,%3}, {%4,%5,%6,%7}, {%8,%9}, {%0,%1,%2,%3};" \
        : "+f"((d)[0]), "+f"((d)[1]), "+f"((d)[2]), "+f"((d)[3]) \
        : "r"((a)[0]), "r"((a)[1]), "r"((a)[2]), "r"((a)[3]), "r"(b0), "r"(b1))

__device__ __forceinline__ void pack4(float4 v, uint2& h, uint2& l) {
    __nv_bfloat162 h01 = __floats2bfloat162_rn(v.x, v.y);
    __nv_bfloat162 h23 = __floats2bfloat162_rn(v.z, v.w);
    float2 f01 = __bfloat1622float2(h01);
    float2 f23 = __bfloat1622float2(h23);
    __nv_bfloat162 l01 = __floats2bfloat162_rn(v.x - f01.x, v.y - f01.y);
    __nv_bfloat162 l23 = __floats2bfloat162_rn(v.z - f23.x, v.w - f23.y);
    h.x = *(uint32_t*)&h01; h.y = *(uint32_t*)&h23;
    l.x = *(uint32_t*)&l01; l.y = *(uint32_t*)&l23;
}

// C[M,N] = A[M,K] @ B[N,K]^T (+bias)(+gelu)(+res); row-major packed; M%128==0, N%64==0, K%32==0
// EPI: 0 none, 1 +bias, 2 +bias+gelu, 3 +bias+res
template<int EPI>
__global__ __launch_bounds__(128)
void gemm_tc(const float* __restrict__ A, const float* __restrict__ Bm,
             const float* __restrict__ bias, const float* __restrict__ Res,
             float* __restrict__ C, int N, int K)
{
    constexpr int RS = 40;  // smem row stride in bf16 (80B): LDSM conflict-free
    __shared__ __align__(16) __nv_bfloat16 sAh[128 * RS], sAl[128 * RS];
    __shared__ __align__(16) __nv_bfloat16 sBh[64 * RS],  sBl[64 * RS];

    const int tid = threadIdx.x, lane = tid & 31, wid = tid >> 5;
    const int wm = wid >> 1, wn = wid & 1;           // 2x2 warp grid
    const int m0 = blockIdx.y * 128, n0 = blockIdx.x * 64;

    float acc[4][4][4];
    #pragma unroll
    for (int i = 0; i < 4; i++)
        #pragma unroll
        for (int j = 0; j < 4; j++)
            #pragma unroll
            for (int q = 0; q < 4; q++) acc[i][j][q] = 0.f;

    const int lrow = lane & 15, lko = (lane >> 4) * 8;  // ldmatrix addressing

    for (int k0 = 0; k0 < K; k0 += 32) {
        // ---- A tile: one 32-wide row per thread, convert fp32 -> bf16 hi/lo
        {
            const float* ap = A + (size_t)(m0 + tid) * K + k0;
            uint4* dh = (uint4*)&sAh[tid * RS];
            uint4* dl = (uint4*)&sAl[tid * RS];
            #pragma unroll
            for (int f = 0; f < 4; f++) {
                float4 v0 = *(const float4*)(ap + f * 8);
                float4 v1 = *(const float4*)(ap + f * 8 + 4);
                uint2 h0, l0, h1, l1;
                pack4(v0, h0, l0); pack4(v1, h1, l1);
                dh[f] = make_uint4(h0.x, h0.y, h1.x, h1.y);
                dl[f] = make_uint4(l0.x, l0.y, l1.x, l1.y);
            }
        }
        // ---- B tile: half row (16 k) per thread
        {
            int r = tid >> 1, ko = (tid & 1) * 16;
            const float* bp = Bm + (size_t)(n0 + r) * K + k0 + ko;
            uint4* dh = (uint4*)&sBh[r * RS + ko];
            uint4* dl = (uint4*)&sBl[r * RS + ko];
            #pragma unroll
            for (int f = 0; f < 2; f++) {
                float4 v0 = *(const float4*)(bp + f * 8);
                float4 v1 = *(const float4*)(bp + f * 8 + 4);
                uint2 h0, l0, h1, l1;
                pack4(v0, h0, l0); pack4(v1, h1, l1);
                dh[f] = make_uint4(h0.x, h0.y, h1.x, h1.y);
                dl[f] = make_uint4(l0.x, l0.y, l1.x, l1.y);
            }
        }
        __syncthreads();

        #pragma unroll
        for (int kk = 0; kk < 32; kk += 16) {
            uint32_t Ah[4][4], Bh[2][4];
            #pragma unroll
            for (int mt = 0; mt < 4; mt++)
                LDSM4(Ah[mt], s2u(&sAh[(wm * 64 + mt * 16 + lrow) * RS + kk + lko]));
            #pragma unroll
            for (int p = 0; p < 2; p++)
                LDSM4(Bh[p], s2u(&sBh[(wn * 32 + p * 16 + lrow) * RS + kk + lko]));

            // pass 1: hi*hi
            #pragma unroll
            for (int mt = 0; mt < 4; mt++)
                #pragma unroll
                for (int p = 0; p < 2; p++) {
                    MMA16816(acc[mt][2 * p + 0], Ah[mt], Bh[p][0], Bh[p][2]);
                    MMA16816(acc[mt][2 * p + 1], Ah[mt], Bh[p][1], Bh[p][3]);
                }

            // pass 2: hi(A) * lo(B)
            uint32_t Bl[2][4];
            #pragma unroll
            for (int p = 0; p < 2; p++)
                LDSM4(Bl[p], s2u(&sBl[(wn * 32 + p * 16 + lrow) * RS + kk + lko]));
            #pragma unroll
            for (int mt = 0; mt < 4; mt++)
                #pragma unroll
                for (int p = 0; p < 2; p++) {
                    MMA16816(acc[mt][2 * p + 0], Ah[mt], Bl[p][0], Bl[p][2]);
                    MMA16816(acc[mt][2 * p + 1], Ah[mt], Bl[p][1], Bl[p][3]);
                }

            // pass 3: lo(A) * hi(B)
            uint32_t Al[4][4];
            #pragma unroll
            for (int mt = 0; mt < 4; mt++)
                LDSM4(Al[mt], s2u(&sAl[(wm * 64 + mt * 16 + lrow) * RS + kk + lko]));
            #pragma unroll
            for (int mt = 0; mt < 4; mt++)
                #pragma unroll
                for (int p = 0; p < 2; p++) {
                    MMA16816(acc[mt][2 * p + 0], Al[mt], Bh[p][0], Bh[p][2]);
                    MMA16816(acc[mt][2 * p + 1], Al[mt], Bh[p][1], Bh[p][3]);
                }
        }
        __syncthreads();
    }

    // ---- epilogue
    const int rb = lane >> 2, cbl = (lane & 3) * 2;
    #pragma unroll
    for (int mt = 0; mt < 4; mt++) {
        #pragma unroll
        for (int half = 0; half < 2; half++) {
            int r = m0 + wm * 64 + mt * 16 + rb + half * 8;
            float* crow = C + (size_t)r * N;
            const float* rrow = (EPI == 3) ? (Res + (size_t)r * N) : nullptr;
            #pragma unroll
            for (int nt = 0; nt < 4; nt++) {
                int cc = n0 + wn * 32 + nt * 8 + cbl;
                float x0 = acc[mt][nt][half * 2 + 0];
                float x1 = acc[mt][nt][half * 2 + 1];
                if (EPI >= 1) { x0 += bias[cc]; x1 += bias[cc + 1]; }
                if (EPI == 2) {
                    x0 = 0.5f * x0 * (1.f + erff(x0 * 0.70710678118654752f));
                    x1 = 0.5f * x1 * (1.f + erff(x1 * 0.70710678118654752f));
                }
                if (EPI == 3) {
                    float2 rv = *(const float2*)(rrow + cc);
                    x0 += rv.x; x1 += rv.y;
                }
                float2 o = make_float2(x0, x1);
                *(float2*)(crow + cc) = o;
            }
        }
    }
}

// ---------------- scalar SGEMM (attention GEMMs) ----------------
__device__ __forceinline__ ull dup_f32x2(float a) {
    ull r;
    unsigned au = __float_as_uint(a);
    asm("mov.b64 %0, {%1, %1};" : "=l"(r) : "r"(au));
    return r;
}
__device__ __forceinline__ void fma_f32x2(ull& acc, ull a, ull b) {
    asm("fma.rn.f32x2 %0, %1, %2, %0;" : "+l"(acc) : "l"(a), "l"(b));
}

template<int EPI, bool BT, int BN_, int TN_>
__global__ __launch_bounds__(256, 2)
void gemm_k(const float* __restrict__ A, int lda, long sAhi, long sAlo, int nloA,
            const float* __restrict__ Bm, int ldb, long sBhi, long sBlo, int nloB,
            const float* __restrict__ bias,
            const float* __restrict__ Res,
            float* __restrict__ C, int ldc, long sChi, long sClo, int nloC,
            int K, float scale)
{
    constexpr int BM = 128, BK = 16, TM = 8;
    constexpr int TN2 = TN_ / 2;
    const int tid = threadIdx.x;
    const int z = blockIdx.z;
    A  += (long)(z / nloA) * sAhi + (long)(z % nloA) * sAlo;
    Bm += (long)(z / nloB) * sBhi + (long)(z % nloB) * sBlo;
    const long coff = (long)(z / nloC) * sChi + (long)(z % nloC) * sClo;
    C += coff;
    const float* res = (EPI == 3) ? Res + coff : nullptr;

    const int m0 = blockIdx.y * BM;
    const int n0 = blockIdx.x * BN_;

    __shared__ float As[BK][BM + 4];
    __shared__ float Bs[BK][BN_ + 4];

    ull acc2[TM][TN2];
    #pragma unroll
    for (int i = 0; i < TM; i++)
        #pragma unroll
        for (int j = 0; j < TN2; j++) acc2[i][j] = 0ull;

    const int ty = tid >> 4;
    const int tx = tid & 15;

    for (int k0 = 0; k0 < K; k0 += BK) {
        {
            int r = tid >> 1;
            int c = (tid & 1) * 8;
            const float* src = A + (long)(m0 + r) * lda + (k0 + c);
            float4 v0 = *(const float4*)src;
            float4 v1 = *(const float4*)(src + 4);
            As[c + 0][r] = v0.x; As[c + 1][r] = v0.y; As[c + 2][r] = v0.z; As[c + 3][r] = v0.w;
            As[c + 4][r] = v1.x; As[c + 5][r] = v1.y; As[c + 6][r] = v1.z; As[c + 7][r] = v1.w;
        }
        if constexpr (BT) {
            if constexpr (BN_ == 128) {
                int r = tid >> 1;
                int c = (tid & 1) * 8;
                const float* src = Bm + (long)(n0 + r) * ldb + (k0 + c);
                float4 v0 = *(const float4*)src;
                float4 v1 = *(const float4*)(src + 4);
                Bs[c + 0][r] = v0.x; Bs[c + 1][r] = v0.y; Bs[c + 2][r] = v0.z; Bs[c + 3][r] = v0.w;
                Bs[c + 4][r] = v1.x; Bs[c + 5][r] = v1.y; Bs[c + 6][r] = v1.z; Bs[c + 7][r] = v1.w;
            } else {
                int r = tid >> 2;
                int c = (tid & 3) * 4;
                float4 v = *(const float4*)(Bm + (long)(n0 + r) * ldb + (k0 + c));
                Bs[c + 0][r] = v.x; Bs[c + 1][r] = v.y; Bs[c + 2][r] = v.z; Bs[c + 3][r] = v.w;
            }
        } else {
            if constexpr (BN_ == 64) {
                int r = tid >> 4;
                int c = (tid & 15) * 4;
                float4 v = *(const float4*)(Bm + (long)(k0 + r) * ldb + (n0 + c));
                *(float4*)&Bs[r][c] = v;
            } else {
                int r = tid >> 4;
                int c = (tid & 15) * 8;
                const float* src = Bm + (long)(k0 + r) * ldb + (n0 + c);
                *(float4*)&Bs[r][c]     = *(const float4*)src;
                *(float4*)&Bs[r][c + 4] = *(const float4*)(src + 4);
            }
        }
        __syncthreads();

        #pragma unroll
        for (int k = 0; k < BK; k++) {
            float a[TM];
            *(float4*)&a[0] = *(const float4*)&As[k][ty * TM];
            *(float4*)&a[4] = *(const float4*)&As[k][ty * TM + 4];
            ull b2[TN2];
            {
                ulonglong2 q0 = *(const ulonglong2*)&Bs[k][tx * TN_];
                b2[0] = q0.x; b2[1] = q0.y;
                if constexpr (TN2 == 4) {
                    ulonglong2 q1 = *(const ulonglong2*)&Bs[k][tx * TN_ + 4];
                    b2[2] = q1.x; b2[3] = q1.y;
                }
            }
            #pragma unroll
            for (int i = 0; i < TM; i++) {
                ull a2 = dup_f32x2(a[i]);
                #pragma unroll
                for (int j = 0; j < TN2; j++)
                    fma_f32x2(acc2[i][j], a2, b2[j]);
            }
        }
        __syncthreads();
    }

    #pragma unroll
    for (int i = 0; i < TM; i++) {
        int m = m0 + ty * TM + i;
        float* crow = C + (long)m * ldc + n0 + tx * TN_;
        #pragma unroll
        for (int j4 = 0; j4 < TN_; j4 += 4) {
            float4 o;
            float* po = &o.x;
            #pragma unroll
            for (int j = 0; j < 4; j++) {
                float2 pr = *(float2*)&acc2[i][(j4 + j) >> 1];
                float av = ((j & 1) == 0) ? pr.x : pr.y;
                float v = av * scale;
                if (EPI >= 1) v += bias[n0 + tx * TN_ + j4 + j];
                if (EPI == 2) v = 0.5f * v * (1.f + erff(v * 0.70710678118654752f));
                po[j] = v;
            }
            if (EPI == 3) {
                float4 rv = *(const float4*)(res + (long)m * ldc + n0 + tx * TN_ + j4);
                o.x += rv.x; o.y += rv.y; o.z += rv.z; o.w += rv.w;
            }
            *(float4*)(crow + j4) = o;
        }
    }
}

// ---------------- embedding ----------------
__global__ void embed_k(const int* __restrict__ seq, const float* __restrict__ bemb,
                        const float* __restrict__ pemb, float* __restrict__ x)
{
    int r = blockIdx.x;
    int s = r % Sc;
    int tok = seq[r];
    int c = threadIdx.x * 4;
    float4 e = *(const float4*)(bemb + (long)tok * Dc + c);
    float4 p = *(const float4*)(pemb + (long)s * Dc + c);
    e.x += p.x; e.y += p.y; e.z += p.z; e.w += p.w;
    *(float4*)(x + (long)r * Dc + c) = e;
}

// ---------------- layernorm ----------------
__global__ void ln_k(const float* __restrict__ x, const float* __restrict__ g,
                     const float* __restrict__ b, float* __restrict__ out)
{
    const int row = blockIdx.x;
    const int tid = threadIdx.x;
    const float* xr = x + (long)row * Dc;
    float4 v = *(const float4*)(xr + tid * 4);
    float s = v.x + v.y + v.z + v.w;
    float tot = block_sum(s);
    float m = tot * (1.f / Dc);
    float dx0 = v.x - m, dx1 = v.y - m, dx2 = v.z - m, dx3 = v.w - m;
    float q = dx0 * dx0 + dx1 * dx1 + dx2 * dx2 + dx3 * dx3;
    float totq = block_sum(q);
    float rs = rsqrtf(totq * (1.f / Dc) + 1e-5f);
    float4 gg = *(const float4*)(g + tid * 4);
    float4 bb = *(const float4*)(b + tid * 4);
    float4 o;
    o.x = dx0 * rs * gg.x + bb.x;
    o.y = dx1 * rs * gg.y + bb.y;
    o.z = dx2 * rs * gg.z + bb.z;
    o.w = dx3 * rs * gg.w + bb.w;
    *(float4*)(out + (long)row * Dc + tid * 4) = o;
}

// ---------------- self-attn softmax (causal window) ----------------
__global__ void smax_sa(float* __restrict__ sc)
{
    const int i = blockIdx.x;
    const int z = blockIdx.y;
    float* row = sc + ((long)z * Sc + i) * Sc;
    const int tid = threadIdx.x;
    int lo = i - Wc + 1; if (lo < 0) lo = 0;
    const int hi = i;
    float v[4];
    float mx = -1e30f;
    #pragma unroll
    for (int t = 0; t < 4; t++) {
        int j = tid + t * 256;
        bool ok = (j >= lo) && (j <= hi);
        v[t] = ok ? row[j] : -1e30f;
        mx = fmaxf(mx, v[t]);
    }
    mx = block_max(mx);
    float s = 0.f;
    #pragma unroll
    for (int t = 0; t < 4; t++) {
        int j = tid + t * 256;
        bool ok = (j >= lo) && (j <= hi);
        v[t] = ok ? expf(v[t] - mx) : 0.f;
        s += v[t];
    }
    s = block_sum(s);
    float inv = 1.f / s;
    #pragma unroll
    for (int t = 0; t < 4; t++)
        row[tid + t * 256] = v[t] * inv;
}

// ---------------- cross-attn softmax (patch mask) ----------------
__global__ void smax_ca(float* __restrict__ sc, const int* __restrict__ pidx)
{
    const int i = blockIdx.x;
    const int z = blockIdx.y;
    const int b = z / Hc;
    float* row = sc + ((long)z * Sc + i) * Pc;
    const int tid = threadIdx.x;
    const int lim = pidx[b * Sc + i];
    bool ok = tid <= lim;
    float v = ok ? row[tid] : -1e30f;
    float mx = block_max(v);
    float e = ok ? expf(v - mx) : 0.f;
    float s = block_sum(e);
    row[tid] = e / s;
}

// ---------------- inclusive cumsum of patch boundaries ----------------
__global__ void cumsum_k(const int* __restrict__ bd, int* __restrict__ pidx)
{
    __shared__ int s[Sc];
    const int b = blockIdx.x, t = threadIdx.x;
    s[t] = bd[b * Sc + t];
    __syncthreads();
    for (int off = 1; off < Sc; off <<= 1) {
        int v = (t >= off) ? s[t - off] : 0;
        __syncthreads();
        s[t] += v;
        __syncthreads();
    }
    pidx[b * Sc + t] = s[t];
}

// ---------------- launcher ----------------
extern "C" void kernel_launch(void* const* d_in, const int* in_sizes, int n_in,
                              void* d_out, int out_size)
{
    const int*   byte_seq  = (const int*)  d_in[0];
    const float* patch_rep = (const float*)d_in[1];
    const int*   patch_bd  = (const int*)  d_in[2];
    const float* byte_emb  = (const float*)d_in[3];
    const float* pos_emb   = (const float*)d_in[4];
    const float* sa_in_w   = (const float*)d_in[5];
    const float* sa_in_b   = (const float*)d_in[6];
    const float* sa_out_w  = (const float*)d_in[7];
    const float* sa_out_b  = (const float*)d_in[8];
    const float* ca_in_w   = (const float*)d_in[9];
    const float* ca_in_b   = (const float*)d_in[10];
    const float* ca_out_w  = (const float*)d_in[11];
    const float* ca_out_b  = (const float*)d_in[12];
    const float* ffn_w1    = (const float*)d_in[13];
    const float* ffn_b1    = (const float*)d_in[14];
    const float* ffn_w2    = (const float*)d_in[15];
    const float* ffn_b2    = (const float*)d_in[16];
    const float* ln_g      = (const float*)d_in[17];
    const float* ln_b      = (const float*)d_in[18];
    const float* norm_g    = (const float*)d_in[19];
    const float* norm_b    = (const float*)d_in[20];
    const float* out_w     = (const float*)d_in[21];
    float* out = (float*)d_out;

    float *gx, *gh, *gqkv, *gcaq, *gcakv, *gsc, *gao, *gffn;
    int* gpidx;
    cudaGetSymbolAddress((void**)&gx,    g_x);
    cudaGetSymbolAddress((void**)&gh,    g_h);
    cudaGetSymbolAddress((void**)&gqkv,  g_qkv);
    cudaGetSymbolAddress((void**)&gcaq,  g_caq);
    cudaGetSymbolAddress((void**)&gcakv, g_cakv);
    cudaGetSymbolAddress((void**)&gsc,   g_sc);
    cudaGetSymbolAddress((void**)&gao,   g_ao);
    cudaGetSymbolAddress((void**)&gffn,  g_ffn);
    cudaGetSymbolAddress((void**)&gpidx, g_pidx);

    embed_k<<<BS, 256>>>(byte_seq, byte_emb, pos_emb, gx);
    cumsum_k<<<Bc, Sc>>>(patch_bd, gpidx);

    for (int l = 0; l < Lc; l++) {
        // ===== self-attention =====
        ln_k<<<BS, 256>>>(gx, ln_g + (long)(l * 3 + 0) * Dc, ln_b + (long)(l * 3 + 0) * Dc, gh);

        // QKV
        gemm_tc<1><<<dim3(3 * Dc / 64, BS / 128), 128>>>(
            gh, sa_in_w + (long)l * 3 * Dc * Dc, sa_in_b + (long)l * 3 * Dc, nullptr,
            gqkv, 3 * Dc, Dc);

        // scores: Q @ K^T / 8   (scalar, strided per-head)
        gemm_k<0, true, 128, 8><<<dim3(Sc / 128, Sc / 128, Bc * Hc), 256>>>(
            gqkv,      3 * Dc, (long)Sc * 3 * Dc, DH, Hc,
            gqkv + Dc, 3 * Dc, (long)Sc * 3 * Dc, DH, Hc,
            nullptr, nullptr,
            gsc, Sc, (long)Sc * Sc, 0, 1,
            DH, 0.125f);

        smax_sa<<<dim3(Sc, Bc * Hc), 256>>>(gsc);

        // attn @ V
        gemm_k<0, false, 64, 4><<<dim3(1, Sc / 128, Bc * Hc), 256>>>(
            gsc, Sc, (long)Sc * Sc, 0, 1,
            gqkv + 2 * Dc, 3 * Dc, (long)Sc * 3 * Dc, DH, Hc,
            nullptr, nullptr,
            gao, Dc, (long)Sc * Dc, DH, Hc,
            Sc, 1.f);

        // out proj + residual
        gemm_tc<3><<<dim3(Dc / 64, BS / 128), 128>>>(
            gao, sa_out_w + (long)l * Dc * Dc, sa_out_b + (long)l * Dc, gx,
            gx, Dc, Dc);

        // ===== cross-attention =====
        ln_k<<<BS, 256>>>(gx, ln_g + (long)(l * 3 + 1) * Dc, ln_b + (long)(l * 3 + 1) * Dc, gh);

        gemm_tc<1><<<dim3(Dc / 64, BS / 128), 128>>>(
            gh, ca_in_w + (long)l * 3 * Dc * Dc, ca_in_b + (long)l * 3 * Dc, nullptr,
            gcaq, Dc, Dc);

        gemm_tc<1><<<dim3(2 * Dc / 64, (Bc * Pc) / 128), 128>>>(
            patch_rep, ca_in_w + (long)l * 3 * Dc * Dc + (long)Dc * Dc,
            ca_in_b + (long)l * 3 * Dc + Dc, nullptr,
            gcakv, 2 * Dc, Dc);

        // CA scores
        gemm_k<0, true, 128, 8><<<dim3(Pc / 128, Sc / 128, Bc * Hc), 256>>>(
            gcaq,  Dc,     (long)Sc * Dc,     DH, Hc,
            gcakv, 2 * Dc, (long)Pc * 2 * Dc, DH, Hc,
            nullptr, nullptr,
            gsc, Pc, (long)Sc * Pc, 0, 1,
            DH, 0.125f);

        smax_ca<<<dim3(Sc, Bc * Hc), 128>>>(gsc, gpidx);

        gemm_k<0, false, 64, 4><<<dim3(1, Sc / 128, Bc * Hc), 256>>>(
            gsc, Pc, (long)Sc * Pc, 0, 1,
            gcakv + Dc, 2 * Dc, (long)Pc * 2 * Dc, DH, Hc,
            nullptr, nullptr,
            gao, Dc, (long)Sc * Dc, DH, Hc,
            Pc, 1.f);

        gemm_tc<3><<<dim3(Dc / 64, BS / 128), 128>>>(
            gao, ca_out_w + (long)l * Dc * Dc, ca_out_b + (long)l * Dc, gx,
            gx, Dc, Dc);

        // ===== FFN =====
        ln_k<<<BS, 256>>>(gx, ln_g + (long)(l * 3 + 2) * Dc, ln_b + (long)(l * 3 + 2) * Dc, gh);

        gemm_tc<2><<<dim3(4 * Dc / 64, BS / 128), 128>>>(
            gh, ffn_w1 + (long)l * 4 * Dc * Dc, ffn_b1 + (long)l * 4 * Dc, nullptr,
            gffn, 4 * Dc, Dc);

        gemm_tc<3><<<dim3(Dc / 64, BS / 128), 128>>>(
            gffn, ffn_w2 + (long)l * Dc * 4 * Dc, ffn_b2 + (long)l * Dc, gx,
            gx, Dc, 4 * Dc);
    }

    // final LN + vocab projection
    ln_k<<<BS, 256>>>(gx, norm_g, norm_b, gh);
    gemm_tc<0><<<dim3(Vc / 64, BS / 128), 128>>>(
        gh, out_w, nullptr, nullptr,
        out, Vc, Dc);
}

// round 6
// speedup vs baseline: 1.4480x; 1.0204x over previous
#include <cuda_runtime.h>
#include <cuda_bf16.h>
#include <math.h>
#include <cstdint>

// ---------------- problem constants ----------------
constexpr int Bc = 2, Sc = 1024, Dc = 1024, Hc = 16, Lc = 9, Wc = 1024, Pc = 128, Vc = 256;
constexpr int DH = Dc / Hc;          // 64
constexpr int BS = Bc * Sc;          // 2048 rows

typedef unsigned long long ull;

// ---------------- device scratch ----------------
__device__ float g_x   [BS * Dc];
__device__ float g_h   [BS * Dc];
__device__ float g_qkv [BS * 3 * Dc];
__device__ float g_caq [BS * Dc];
__device__ float g_cakv[Bc * Pc * 2 * Dc];
__device__ float g_sc  [(long)Bc * Hc * Sc * Sc];
__device__ float g_ao  [BS * Dc];
__device__ float g_ffn [BS * 4 * Dc];
__device__ int   g_pidx[BS];

// ---------------- reductions ----------------
__device__ __forceinline__ float block_sum(float v) {
    __shared__ float sh[32];
    int lane = threadIdx.x & 31, w = threadIdx.x >> 5;
    int nw = blockDim.x >> 5;
    #pragma unroll
    for (int o = 16; o; o >>= 1) v += __shfl_xor_sync(0xffffffffu, v, o);
    __syncthreads();
    if (lane == 0) sh[w] = v;
    __syncthreads();
    if (threadIdx.x == 0) {
        float t = 0.f;
        for (int i = 0; i < nw; i++) t += sh[i];
        sh[0] = t;
    }
    __syncthreads();
    return sh[0];
}

__device__ __forceinline__ float block_max(float v) {
    __shared__ float sh[32];
    int lane = threadIdx.x & 31, w = threadIdx.x >> 5;
    int nw = blockDim.x >> 5;
    #pragma unroll
    for (int o = 16; o; o >>= 1) v = fmaxf(v, __shfl_xor_sync(0xffffffffu, v, o));
    __syncthreads();
    if (lane == 0) sh[w] = v;
    __syncthreads();
    if (threadIdx.x == 0) {
        float t = -1e30f;
        for (int i = 0; i < nw; i++) t = fmaxf(t, sh[i]);
        sh[0] = t;
    }
    __syncthreads();
    return sh[0];
}

// ================= bf16x3 mma.sync GEMM =================
__device__ __forceinline__ uint32_t s2u(const void* p) {
    return (uint32_t)__cvta_generic_to_shared(p);
}

#define LDSM4(R, addr) \
    asm volatile("ldmatrix.sync.aligned.m8n8.x4.shared.b16 {%0,%1,%2,%3}, [%4];" \
        : "=r"((R)[0]), "=r"((R)[1]), "=r"((R)[2]), "=r"((R)[3]) : "r"(addr))

#define MMA16816(d, a, b0, b1) \
    asm volatile("mma.sync.aligned.m16n8k16.row.col.f32.bf16.bf16.f32 " \
        "{%0,%1,%2,%3}, {%4,%5,%6,%7}, {%8,%9}, {%0,%1,%2,%3};" \
        : "+f"((d)[0]), "+f"((d)[1]), "+f"((d)[2]), "+f"((d)[3]) \
        : "r"((a)[0]), "r"((a)[1]), "r"((a)[2]), "r"((a)[3]), "r"(b0), "r"(b1))

__device__ __forceinline__ void pack4(float4 v, uint2& h, uint2& l) {
    __nv_bfloat162 h01 = __floats2bfloat162_rn(v.x, v.y);
    __nv_bfloat162 h23 = __floats2bfloat162_rn(v.z, v.w);
    float2 f01 = __bfloat1622float2(h01);
    float2 f23 = __bfloat1622float2(h23);
    __nv_bfloat162 l01 = __floats2bfloat162_rn(v.x - f01.x, v.y - f01.y);
    __nv_bfloat162 l23 = __floats2bfloat162_rn(v.z - f23.x, v.w - f23.y);
    h.x = *(uint32_t*)&h01; h.y = *(uint32_t*)&h23;
    l.x = *(uint32_t*)&l01; l.y = *(uint32_t*)&l23;
}

// C = scale*(A[M,K] @ B[N,K]^T) (+bias)(+gelu)(+res); batched via (z/nlo)*hi+(z%nlo)*lo
// CTA tile 128x128, BK=32, 4 warps (2x2), warp tile 64x64.
// EPI: 0 none, 1 +bias, 2 +bias+gelu, 3 +bias+res
template<int EPI>
__global__ __launch_bounds__(128)
void gemm_tc(const float* __restrict__ A, int lda, long hiA, long loA, int nloA,
             const float* __restrict__ Bm, int ldb, long hiB, long loB, int nloB,
             const float* __restrict__ bias, const float* __restrict__ Res,
             float* __restrict__ C, int ldc, long hiC, long loC, int nloC,
             int K, float scale)
{
    constexpr int RS = 40;  // smem row stride in bf16 (80B)
    __shared__ __align__(16) __nv_bfloat16 sAh[128 * RS], sAl[128 * RS];
    __shared__ __align__(16) __nv_bfloat16 sBh[128 * RS], sBl[128 * RS];

    const int tid = threadIdx.x, lane = tid & 31, wid = tid >> 5;
    const int wm = wid >> 1, wn = wid & 1;
    const int z = blockIdx.z;
    A  += (long)(z / nloA) * hiA + (long)(z % nloA) * loA;
    Bm += (long)(z / nloB) * hiB + (long)(z % nloB) * loB;
    const long coff = (long)(z / nloC) * hiC + (long)(z % nloC) * loC;

    const int m0 = blockIdx.y * 128, n0 = blockIdx.x * 128;

    float acc[4][8][4];
    #pragma unroll
    for (int i = 0; i < 4; i++)
        #pragma unroll
        for (int j = 0; j < 8; j++)
            #pragma unroll
            for (int q = 0; q < 4; q++) acc[i][j][q] = 0.f;

    const int lrow = lane & 15, lko = (lane >> 4) * 8;
    const float* arow = A + (size_t)(m0 + tid) * lda;
    const float* brow = Bm + (size_t)(n0 + tid) * ldb;

    for (int k0 = 0; k0 < K; k0 += 32) {
        // ---- A tile: one 32-wide row per thread, fp32 -> bf16 hi/lo
        {
            const float* ap = arow + k0;
            uint4* dh = (uint4*)&sAh[tid * RS];
            uint4* dl = (uint4*)&sAl[tid * RS];
            #pragma unroll
            for (int f = 0; f < 4; f++) {
                float4 v0 = *(const float4*)(ap + f * 8);
                float4 v1 = *(const float4*)(ap + f * 8 + 4);
                uint2 h0, l0, h1, l1;
                pack4(v0, h0, l0); pack4(v1, h1, l1);
                dh[f] = make_uint4(h0.x, h0.y, h1.x, h1.y);
                dl[f] = make_uint4(l0.x, l0.y, l1.x, l1.y);
            }
        }
        // ---- B tile: one 32-wide row per thread
        {
            const float* bp = brow + k0;
            uint4* dh = (uint4*)&sBh[tid * RS];
            uint4* dl = (uint4*)&sBl[tid * RS];
            #pragma unroll
            for (int f = 0; f < 4; f++) {
                float4 v0 = *(const float4*)(bp + f * 8);
                float4 v1 = *(const float4*)(bp + f * 8 + 4);
                uint2 h0, l0, h1, l1;
                pack4(v0, h0, l0); pack4(v1, h1, l1);
                dh[f] = make_uint4(h0.x, h0.y, h1.x, h1.y);
                dl[f] = make_uint4(l0.x, l0.y, l1.x, l1.y);
            }
        }
        __syncthreads();

        #pragma unroll
        for (int kk = 0; kk < 32; kk += 16) {
            uint32_t Ah[4][4], Al[4][4];
            #pragma unroll
            for (int mt = 0; mt < 4; mt++)
                LDSM4(Ah[mt], s2u(&sAh[(wm * 64 + mt * 16 + lrow) * RS + kk + lko]));
            #pragma unroll
            for (int mt = 0; mt < 4; mt++)
                LDSM4(Al[mt], s2u(&sAl[(wm * 64 + mt * 16 + lrow) * RS + kk + lko]));

            #pragma unroll
            for (int p = 0; p < 4; p++) {
                uint32_t Bh[4], Bl[4];
                LDSM4(Bh, s2u(&sBh[(wn * 64 + p * 16 + lrow) * RS + kk + lko]));
                LDSM4(Bl, s2u(&sBl[(wn * 64 + p * 16 + lrow) * RS + kk + lko]));
                #pragma unroll
                for (int mt = 0; mt < 4; mt++) {
                    MMA16816(acc[mt][2 * p + 0], Ah[mt], Bh[0], Bh[2]);
                    MMA16816(acc[mt][2 * p + 1], Ah[mt], Bh[1], Bh[3]);
                    MMA16816(acc[mt][2 * p + 0], Ah[mt], Bl[0], Bl[2]);
                    MMA16816(acc[mt][2 * p + 1], Ah[mt], Bl[1], Bl[3]);
                    MMA16816(acc[mt][2 * p + 0], Al[mt], Bh[0], Bh[2]);
                    MMA16816(acc[mt][2 * p + 1], Al[mt], Bh[1], Bh[3]);
                }
            }
        }
        __syncthreads();
    }

    // ---- epilogue
    float* Cb = C + coff;
    const float* Rb = (EPI == 3) ? (Res + coff) : nullptr;
    const int rb = lane >> 2, cbl = (lane & 3) * 2;
    #pragma unroll
    for (int mt = 0; mt < 4; mt++) {
        #pragma unroll
        for (int half = 0; half < 2; half++) {
            int r = m0 + wm * 64 + mt * 16 + rb + half * 8;
            float* crow = Cb + (size_t)r * ldc;
            const float* rrow = (EPI == 3) ? (Rb + (size_t)r * ldc) : nullptr;
            #pragma unroll
            for (int j = 0; j < 8; j++) {
                int cc = n0 + wn * 64 + (j >> 1) * 16 + (j & 1) * 8 + cbl;
                float x0 = acc[mt][j][half * 2 + 0] * scale;
                float x1 = acc[mt][j][half * 2 + 1] * scale;
                if (EPI >= 1) { x0 += bias[cc]; x1 += bias[cc + 1]; }
                if (EPI == 2) {
                    x0 = 0.5f * x0 * (1.f + erff(x0 * 0.70710678118654752f));
                    x1 = 0.5f * x1 * (1.f + erff(x1 * 0.70710678118654752f));
                }
                if (EPI == 3) {
                    float2 rv = *(const float2*)(rrow + cc);
                    x0 += rv.x; x1 += rv.y;
                }
                *(float2*)(crow + cc) = make_float2(x0, x1);
            }
        }
    }
}

// ---------------- scalar SGEMM (attn @ V only) ----------------
__device__ __forceinline__ ull dup_f32x2(float a) {
    ull r;
    unsigned au = __float_as_uint(a);
    asm("mov.b64 %0, {%1, %1};" : "=l"(r) : "r"(au));
    return r;
}
__device__ __forceinline__ void fma_f32x2(ull& acc, ull a, ull b) {
    asm("fma.rn.f32x2 %0, %1, %2, %0;" : "+l"(acc) : "l"(a), "l"(b));
}

// C[m,n] = sum_k A[m,k] * B[k,n]; BN=64, TN=4
__global__ __launch_bounds__(256, 2)
void gemm_av(const float* __restrict__ A, int lda, long sAhi,
             const float* __restrict__ Bm, int ldb, long sBhi, long sBlo, int nloB,
             float* __restrict__ C, int ldc, long sChi, long sClo, int nloC,
             int K)
{
    constexpr int BM = 128, BK = 16, TM = 8, BN_ = 64, TN_ = 4, TN2 = 2;
    const int tid = threadIdx.x;
    const int z = blockIdx.z;
    A  += (long)z * sAhi;
    Bm += (long)(z / nloB) * sBhi + (long)(z % nloB) * sBlo;
    C  += (long)(z / nloC) * sChi + (long)(z % nloC) * sClo;

    const int m0 = blockIdx.y * BM;
    const int n0 = blockIdx.x * BN_;

    __shared__ float As[BK][BM + 4];
    __shared__ float Bs[BK][BN_ + 4];

    ull acc2[TM][TN2];
    #pragma unroll
    for (int i = 0; i < TM; i++)
        #pragma unroll
        for (int j = 0; j < TN2; j++) acc2[i][j] = 0ull;

    const int ty = tid >> 4;
    const int tx = tid & 15;

    for (int k0 = 0; k0 < K; k0 += BK) {
        {
            int r = tid >> 1;
            int c = (tid & 1) * 8;
            const float* src = A + (long)(m0 + r) * lda + (k0 + c);
            float4 v0 = *(const float4*)src;
            float4 v1 = *(const float4*)(src + 4);
            As[c + 0][r] = v0.x; As[c + 1][r] = v0.y; As[c + 2][r] = v0.z; As[c + 3][r] = v0.w;
            As[c + 4][r] = v1.x; As[c + 5][r] = v1.y; As[c + 6][r] = v1.z; As[c + 7][r] = v1.w;
        }
        {
            int r = tid >> 4;
            int c = (tid & 15) * 4;
            float4 v = *(const float4*)(Bm + (long)(k0 + r) * ldb + (n0 + c));
            *(float4*)&Bs[r][c] = v;
        }
        __syncthreads();

        #pragma unroll
        for (int k = 0; k < BK; k++) {
            float a[TM];
            *(float4*)&a[0] = *(const float4*)&As[k][ty * TM];
            *(float4*)&a[4] = *(const float4*)&As[k][ty * TM + 4];
            ull b2[TN2];
            {
                ulonglong2 q0 = *(const ulonglong2*)&Bs[k][tx * TN_];
                b2[0] = q0.x; b2[1] = q0.y;
            }
            #pragma unroll
            for (int i = 0; i < TM; i++) {
                ull a2 = dup_f32x2(a[i]);
                #pragma unroll
                for (int j = 0; j < TN2; j++)
                    fma_f32x2(acc2[i][j], a2, b2[j]);
            }
        }
        __syncthreads();
    }

    #pragma unroll
    for (int i = 0; i < TM; i++) {
        int m = m0 + ty * TM + i;
        float* crow = C + (long)m * ldc + n0 + tx * TN_;
        *(float4*)crow = make_float4(
            ((float2*)&acc2[i][0])->x, ((float2*)&acc2[i][0])->y,
            ((float2*)&acc2[i][1])->x, ((float2*)&acc2[i][1])->y);
    }
}

// ---------------- embedding ----------------
__global__ void embed_k(const int* __restrict__ seq, const float* __restrict__ bemb,
                        const float* __restrict__ pemb, float* __restrict__ x)
{
    int r = blockIdx.x;
    int s = r % Sc;
    int tok = seq[r];
    int c = threadIdx.x * 4;
    float4 e = *(const float4*)(bemb + (long)tok * Dc + c);
    float4 p = *(const float4*)(pemb + (long)s * Dc + c);
    e.x += p.x; e.y += p.y; e.z += p.z; e.w += p.w;
    *(float4*)(x + (long)r * Dc + c) = e;
}

// ---------------- layernorm ----------------
__global__ void ln_k(const float* __restrict__ x, const float* __restrict__ g,
                     const float* __restrict__ b, float* __restrict__ out)
{
    const int row = blockIdx.x;
    const int tid = threadIdx.x;
    const float* xr = x + (long)row * Dc;
    float4 v = *(const float4*)(xr + tid * 4);
    float s = v.x + v.y + v.z + v.w;
    float tot = block_sum(s);
    float m = tot * (1.f / Dc);
    float dx0 = v.x - m, dx1 = v.y - m, dx2 = v.z - m, dx3 = v.w - m;
    float q = dx0 * dx0 + dx1 * dx1 + dx2 * dx2 + dx3 * dx3;
    float totq = block_sum(q);
    float rs = rsqrtf(totq * (1.f / Dc) + 1e-5f);
    float4 gg = *(const float4*)(g + tid * 4);
    float4 bb = *(const float4*)(b + tid * 4);
    float4 o;
    o.x = dx0 * rs * gg.x + bb.x;
    o.y = dx1 * rs * gg.y + bb.y;
    o.z = dx2 * rs * gg.z + bb.z;
    o.w = dx3 * rs * gg.w + bb.w;
    *(float4*)(out + (long)row * Dc + tid * 4) = o;
}

// ---------------- self-attn softmax (causal window) ----------------
__global__ void smax_sa(float* __restrict__ sc)
{
    const int i = blockIdx.x;
    const int z = blockIdx.y;
    float* row = sc + ((long)z * Sc + i) * Sc;
    const int tid = threadIdx.x;
    int lo = i - Wc + 1; if (lo < 0) lo = 0;
    const int hi = i;
    float v[4];
    float mx = -1e30f;
    #pragma unroll
    for (int t = 0; t < 4; t++) {
        int j = tid + t * 256;
        bool ok = (j >= lo) && (j <= hi);
        v[t] = ok ? row[j] : -1e30f;
        mx = fmaxf(mx, v[t]);
    }
    mx = block_max(mx);
    float s = 0.f;
    #pragma unroll
    for (int t = 0; t < 4; t++) {
        int j = tid + t * 256;
        bool ok = (j >= lo) && (j <= hi);
        v[t] = ok ? expf(v[t] - mx) : 0.f;
        s += v[t];
    }
    s = block_sum(s);
    float inv = 1.f / s;
    #pragma unroll
    for (int t = 0; t < 4; t++)
        row[tid + t * 256] = v[t] * inv;
}

// ---------------- cross-attn softmax (patch mask) ----------------
__global__ void smax_ca(float* __restrict__ sc, const int* __restrict__ pidx)
{
    const int i = blockIdx.x;
    const int z = blockIdx.y;
    const int b = z / Hc;
    float* row = sc + ((long)z * Sc + i) * Pc;
    const int tid = threadIdx.x;
    const int lim = pidx[b * Sc + i];
    bool ok = tid <= lim;
    float v = ok ? row[tid] : -1e30f;
    float mx = block_max(v);
    float e = ok ? expf(v - mx) : 0.f;
    float s = block_sum(e);
    row[tid] = e / s;
}

// ---------------- inclusive cumsum of patch boundaries ----------------
__global__ void cumsum_k(const int* __restrict__ bd, int* __restrict__ pidx)
{
    __shared__ int s[Sc];
    const int b = blockIdx.x, t = threadIdx.x;
    s[t] = bd[b * Sc + t];
    __syncthreads();
    for (int off = 1; off < Sc; off <<= 1) {
        int v = (t >= off) ? s[t - off] : 0;
        __syncthreads();
        s[t] += v;
        __syncthreads();
    }
    pidx[b * Sc + t] = s[t];
}

// ---------------- launcher ----------------
extern "C" void kernel_launch(void* const* d_in, const int* in_sizes, int n_in,
                              void* d_out, int out_size)
{
    const int*   byte_seq  = (const int*)  d_in[0];
    const float* patch_rep = (const float*)d_in[1];
    const int*   patch_bd  = (const int*)  d_in[2];
    const float* byte_emb  = (const float*)d_in[3];
    const float* pos_emb   = (const float*)d_in[4];
    const float* sa_in_w   = (const float*)d_in[5];
    const float* sa_in_b   = (const float*)d_in[6];
    const float* sa_out_w  = (const float*)d_in[7];
    const float* sa_out_b  = (const float*)d_in[8];
    const float* ca_in_w   = (const float*)d_in[9];
    const float* ca_in_b   = (const float*)d_in[10];
    const float* ca_out_w  = (const float*)d_in[11];
    const float* ca_out_b  = (const float*)d_in[12];
    const float* ffn_w1    = (const float*)d_in[13];
    const float* ffn_b1    = (const float*)d_in[14];
    const float* ffn_w2    = (const float*)d_in[15];
    const float* ffn_b2    = (const float*)d_in[16];
    const float* ln_g      = (const float*)d_in[17];
    const float* ln_b      = (const float*)d_in[18];
    const float* norm_g    = (const float*)d_in[19];
    const float* norm_b    = (const float*)d_in[20];
    const float* out_w     = (const float*)d_in[21];
    float* out = (float*)d_out;

    float *gx, *gh, *gqkv, *gcaq, *gcakv, *gsc, *gao, *gffn;
    int* gpidx;
    cudaGetSymbolAddress((void**)&gx,    g_x);
    cudaGetSymbolAddress((void**)&gh,    g_h);
    cudaGetSymbolAddress((void**)&gqkv,  g_qkv);
    cudaGetSymbolAddress((void**)&gcaq,  g_caq);
    cudaGetSymbolAddress((void**)&gcakv, g_cakv);
    cudaGetSymbolAddress((void**)&gsc,   g_sc);
    cudaGetSymbolAddress((void**)&gao,   g_ao);
    cudaGetSymbolAddress((void**)&gffn,  g_ffn);
    cudaGetSymbolAddress((void**)&gpidx, g_pidx);

    embed_k<<<BS, 256>>>(byte_seq, byte_emb, pos_emb, gx);
    cumsum_k<<<Bc, Sc>>>(patch_bd, gpidx);

    for (int l = 0; l < Lc; l++) {
        // ===== self-attention =====
        ln_k<<<BS, 256>>>(gx, ln_g + (long)(l * 3 + 0) * Dc, ln_b + (long)(l * 3 + 0) * Dc, gh);

        // QKV
        gemm_tc<1><<<dim3(3 * Dc / 128, BS / 128), 128>>>(
            gh, Dc, 0, 0, 1,
            sa_in_w + (long)l * 3 * Dc * Dc, Dc, 0, 0, 1,
            sa_in_b + (long)l * 3 * Dc, nullptr,
            gqkv, 3 * Dc, 0, 0, 1, Dc, 1.f);

        // scores: Q @ K^T / 8  (tensor path, batched per (b,h), K=64)
        gemm_tc<0><<<dim3(Sc / 128, Sc / 128, Bc * Hc), 128>>>(
            gqkv,      3 * Dc, (long)Sc * 3 * Dc, DH, Hc,
            gqkv + Dc, 3 * Dc, (long)Sc * 3 * Dc, DH, Hc,
            nullptr, nullptr,
            gsc, Sc, (long)Sc * Sc, 0, 1,
            DH, 0.125f);

        smax_sa<<<dim3(Sc, Bc * Hc), 256>>>(gsc);

        // attn @ V (scalar)
        gemm_av<<<dim3(1, Sc / 128, Bc * Hc), 256>>>(
            gsc, Sc, (long)Sc * Sc,
            gqkv + 2 * Dc, 3 * Dc, (long)Sc * 3 * Dc, DH, Hc,
            gao, Dc, (long)Sc * Dc, DH, Hc,
            Sc);

        // out proj + residual
        gemm_tc<3><<<dim3(Dc / 128, BS / 128), 128>>>(
            gao, Dc, 0, 0, 1,
            sa_out_w + (long)l * Dc * Dc, Dc, 0, 0, 1,
            sa_out_b + (long)l * Dc, gx,
            gx, Dc, 0, 0, 1, Dc, 1.f);

        // ===== cross-attention =====
        ln_k<<<BS, 256>>>(gx, ln_g + (long)(l * 3 + 1) * Dc, ln_b + (long)(l * 3 + 1) * Dc, gh);

        gemm_tc<1><<<dim3(Dc / 128, BS / 128), 128>>>(
            gh, Dc, 0, 0, 1,
            ca_in_w + (long)l * 3 * Dc * Dc, Dc, 0, 0, 1,
            ca_in_b + (long)l * 3 * Dc, nullptr,
            gcaq, Dc, 0, 0, 1, Dc, 1.f);

        gemm_tc<1><<<dim3(2 * Dc / 128, (Bc * Pc) / 128), 128>>>(
            patch_rep, Dc, 0, 0, 1,
            ca_in_w + (long)l * 3 * Dc * Dc + (long)Dc * Dc, Dc, 0, 0, 1,
            ca_in_b + (long)l * 3 * Dc + Dc, nullptr,
            gcakv, 2 * Dc, 0, 0, 1, Dc, 1.f);

        // CA scores (tensor path, N=128, K=64)
        gemm_tc<0><<<dim3(Pc / 128, Sc / 128, Bc * Hc), 128>>>(
            gcaq,  Dc,     (long)Sc * Dc,     DH, Hc,
            gcakv, 2 * Dc, (long)Pc * 2 * Dc, DH, Hc,
            nullptr, nullptr,
            gsc, Pc, (long)Sc * Pc, 0, 1,
            DH, 0.125f);

        smax_ca<<<dim3(Sc, Bc * Hc), 128>>>(gsc, gpidx);

        gemm_av<<<dim3(1, Sc / 128, Bc * Hc), 256>>>(
            gsc, Pc, (long)Sc * Pc,
            gcakv + Dc, 2 * Dc, (long)Pc * 2 * Dc, DH, Hc,
            gao, Dc, (long)Sc * Dc, DH, Hc,
            Pc);

        gemm_tc<3><<<dim3(Dc / 128, BS / 128), 128>>>(
            gao, Dc, 0, 0, 1,
            ca_out_w + (long)l * Dc * Dc, Dc, 0, 0, 1,
            ca_out_b + (long)l * Dc, gx,
            gx, Dc, 0, 0, 1, Dc, 1.f);

        // ===== FFN =====
        ln_k<<<BS, 256>>>(gx, ln_g + (long)(l * 3 + 2) * Dc, ln_b + (long)(l * 3 + 2) * Dc, gh);

        gemm_tc<2><<<dim3(4 * Dc / 128, BS / 128), 128>>>(
            gh, Dc, 0, 0, 1,
            ffn_w1 + (long)l * 4 * Dc * Dc, Dc, 0, 0, 1,
            ffn_b1 + (long)l * 4 * Dc, nullptr,
            gffn, 4 * Dc, 0, 0, 1, Dc, 1.f);

        gemm_tc<3><<<dim3(Dc / 128, BS / 128), 128>>>(
            gffn, 4 * Dc, 0, 0, 1,
            ffn_w2 + (long)l * Dc * 4 * Dc, 4 * Dc, 0, 0, 1,
            ffn_b2 + (long)l * Dc, gx,
            gx, Dc, 0, 0, 1, 4 * Dc, 1.f);
    }

    // final LN + vocab projection
    ln_k<<<BS, 256>>>(gx, norm_g, norm_b, gh);
    gemm_tc<0><<<dim3(Vc / 128, BS / 128), 128>>>(
        gh, Dc, 0, 0, 1,
        out_w, Dc, 0, 0, 1,
        nullptr, nullptr,
        out, Vc, 0, 0, 1, Dc, 1.f);
}

// round 7
// speedup vs baseline: 1.5799x; 1.0911x over previous
#include <cuda_runtime.h>
#include <cuda_bf16.h>
#include <math.h>
#include <cstdint>

// ---------------- problem constants ----------------
constexpr int Bc = 2, Sc = 1024, Dc = 1024, Hc = 16, Lc = 9, Wc = 1024, Pc = 128, Vc = 256;
constexpr int DH = Dc / Hc;          // 64
constexpr int BS = Bc * Sc;          // 2048 rows

typedef unsigned long long ull;
typedef __nv_bfloat16 bf16;

// ---------------- device scratch ----------------
__device__ float g_x   [BS * Dc];
__device__ float g_qkv [BS * 3 * Dc];
__device__ float g_caq [BS * Dc];
__device__ float g_cakv[Bc * Pc * 2 * Dc];
__device__ float g_sc  [(long)Bc * Hc * Sc * Sc];
__device__ float g_ao  [BS * Dc];
__device__ float g_ffn [BS * 4 * Dc];
__device__ int   g_pidx[BS];

// bf16 hi/lo planes
// weights mega-buffer offsets (elements)
constexpr long OFF_SAIN  = 0;
constexpr long OFF_SAOUT = OFF_SAIN  + (long)Lc * 3 * Dc * Dc;   // 28311552
constexpr long OFF_CAIN  = OFF_SAOUT + (long)Lc * Dc * Dc;       // 37748736
constexpr long OFF_CAOUT = OFF_CAIN  + (long)Lc * 3 * Dc * Dc;   // 66060288
constexpr long OFF_FFN1  = OFF_CAOUT + (long)Lc * Dc * Dc;       // 75497472
constexpr long OFF_FFN2  = OFF_FFN1  + (long)Lc * 4 * Dc * Dc;   // 113246208
constexpr long OFF_OUTW  = OFF_FFN2  + (long)Lc * 4 * Dc * Dc;   // 150994944
constexpr long W_TOTAL   = OFF_OUTW  + (long)Vc * Dc;            // 151257088

__device__ bf16 g_whi[W_TOTAL];
__device__ bf16 g_wlo[W_TOTAL];

__device__ bf16 g_hh [BS * Dc],        g_hl [BS * Dc];          // LN output planes
__device__ bf16 g_qh [BS * 3 * Dc],    g_ql [BS * 3 * Dc];      // qkv planes
__device__ bf16 g_cqh[BS * Dc],        g_cql[BS * Dc];          // CA q planes
__device__ bf16 g_ckh[Bc * Pc * 2 * Dc], g_ckl[Bc * Pc * 2 * Dc]; // CA kv planes
__device__ bf16 g_fh [BS * 4 * Dc],    g_fl [BS * 4 * Dc];      // ffn hidden planes
__device__ bf16 g_prh[Bc * Pc * Dc],   g_prl[Bc * Pc * Dc];     // patch_rep planes

// ---------------- reductions ----------------
__device__ __forceinline__ float block_sum(float v) {
    __shared__ float sh[32];
    int lane = threadIdx.x & 31, w = threadIdx.x >> 5;
    int nw = blockDim.x >> 5;
    #pragma unroll
    for (int o = 16; o; o >>= 1) v += __shfl_xor_sync(0xffffffffu, v, o);
    __syncthreads();
    if (lane == 0) sh[w] = v;
    __syncthreads();
    if (threadIdx.x == 0) {
        float t = 0.f;
        for (int i = 0; i < nw; i++) t += sh[i];
        sh[0] = t;
    }
    __syncthreads();
    return sh[0];
}

__device__ __forceinline__ float block_max(float v) {
    __shared__ float sh[32];
    int lane = threadIdx.x & 31, w = threadIdx.x >> 5;
    int nw = blockDim.x >> 5;
    #pragma unroll
    for (int o = 16; o; o >>= 1) v = fmaxf(v, __shfl_xor_sync(0xffffffffu, v, o));
    __syncthreads();
    if (lane == 0) sh[w] = v;
    __syncthreads();
    if (threadIdx.x == 0) {
        float t = -1e30f;
        for (int i = 0; i < nw; i++) t = fmaxf(t, sh[i]);
        sh[0] = t;
    }
    __syncthreads();
    return sh[0];
}

// ================= helpers =================
__device__ __forceinline__ uint32_t s2u(const void* p) {
    return (uint32_t)__cvta_generic_to_shared(p);
}
__device__ __forceinline__ void cp16(uint32_t dst, const void* src) {
    asm volatile("cp.async.cg.shared.global [%0], [%1], 16;" :: "r"(dst), "l"(src));
}

#define LDSM4(R, addr) \
    asm volatile("ldmatrix.sync.aligned.m8n8.x4.shared.b16 {%0,%1,%2,%3}, [%4];" \
        : "=r"((R)[0]), "=r"((R)[1]), "=r"((R)[2]), "=r"((R)[3]) : "r"(addr))

#define MMA16816(d, a, b0, b1) \
    asm volatile("mma.sync.aligned.m16n8k16.row.col.f32.bf16.bf16.f32 " \
        "{%0,%1,%2,%3}, {%4,%5,%6,%7}, {%8,%9}, {%0,%1,%2,%3};" \
        : "+f"((d)[0]), "+f"((d)[1]), "+f"((d)[2]), "+f"((d)[3]) \
        : "r"((a)[0]), "r"((a)[1]), "r"((a)[2]), "r"((a)[3]), "r"(b0), "r"(b1))

__device__ __forceinline__ void split2(float x0, float x1, uint32_t& h, uint32_t& l) {
    __nv_bfloat162 hh = __floats2bfloat162_rn(x0, x1);
    float2 hf = __bfloat1622float2(hh);
    __nv_bfloat162 ll = __floats2bfloat162_rn(x0 - hf.x, x1 - hf.y);
    h = *(uint32_t*)&hh; l = *(uint32_t*)&ll;
}

// ================= pipelined bf16x3 mma.sync GEMM =================
// C = scale*(A @ B^T); A,B given as bf16 hi/lo planes; CTA 128x128, BK=32, 4 warps 64x64.
// EPI: 0 none, 1 +bias, 2 +bias+gelu, 3 +bias+res.  OUTBF: also write C hi/lo planes.
constexpr int RS = 40;                       // smem row stride (bf16 elems), 80B
constexpr int TCS = 2 * 4 * 128 * RS * 2;    // dynamic smem bytes = 81920

template<int EPI, bool OUTBF>
__global__ __launch_bounds__(128, 2)
void gemm_tc(const bf16* __restrict__ Ah, const bf16* __restrict__ Al, int lda, long hiA, long loA, int nloA,
             const bf16* __restrict__ Bh, const bf16* __restrict__ Bl, int ldb, long hiB, long loB, int nloB,
             const float* __restrict__ bias, const float* __restrict__ Res,
             float* __restrict__ C, bf16* __restrict__ Chi, bf16* __restrict__ Clo,
             int ldc, long hiC, long loC, int nloC, int K, float scale)
{
    extern __shared__ __align__(16) bf16 sbuf[];   // [2][4][128*RS]

    const int tid = threadIdx.x, lane = tid & 31, wid = tid >> 5;
    const int wm = wid >> 1, wn = wid & 1;
    const int z = blockIdx.z;
    Ah += (long)(z / nloA) * hiA + (long)(z % nloA) * loA;
    Al += (long)(z / nloA) * hiA + (long)(z % nloA) * loA;
    Bh += (long)(z / nloB) * hiB + (long)(z % nloB) * loB;
    Bl += (long)(z / nloB) * hiB + (long)(z % nloB) * loB;
    const long coff = (long)(z / nloC) * hiC + (long)(z % nloC) * loC;

    const int m0 = blockIdx.y * 128, n0 = blockIdx.x * 128;
    const uint32_t sbase = s2u(sbuf);

    const bf16* pA[4];
    pA[0] = Ah + (size_t)(m0 + tid) * lda;
    pA[1] = Al + (size_t)(m0 + tid) * lda;
    pA[2] = Bh + (size_t)(n0 + tid) * ldb;
    pA[3] = Bl + (size_t)(n0 + tid) * ldb;

    float acc[4][8][4];
    #pragma unroll
    for (int i = 0; i < 4; i++)
        #pragma unroll
        for (int j = 0; j < 8; j++)
            #pragma unroll
            for (int q = 0; q < 4; q++) acc[i][j][q] = 0.f;

    const int nk = K / 32;

    // issue chunk `c` into buffer c&1
    auto issue = [&](int c) {
        uint32_t base = sbase + (uint32_t)(c & 1) * (4 * 128 * RS * 2);
        #pragma unroll
        for (int t = 0; t < 4; t++) {
            uint32_t dst = base + (uint32_t)(t * 128 + tid) * (RS * 2);
            const bf16* src = pA[t] + c * 32;
            #pragma unroll
            for (int q = 0; q < 4; q++)
                cp16(dst + q * 16, src + q * 8);
        }
        asm volatile("cp.async.commit_group;");
    };

    issue(0);

    const int lrow = lane & 15, lko = (lane >> 4) * 8;

    for (int k0 = 0; k0 < nk; k0++) {
        asm volatile("cp.async.wait_group 0;");
        __syncthreads();                       // chunk k0 visible; all warps done with prev MMA
        if (k0 + 1 < nk) issue(k0 + 1);        // overlaps with MMA below

        const bf16* bAh = sbuf + (size_t)(k0 & 1) * (4 * 128 * RS) + 0 * 128 * RS;
        const bf16* bAl = bAh + 128 * RS;
        const bf16* bBh = bAh + 2 * 128 * RS;
        const bf16* bBl = bAh + 3 * 128 * RS;

        #pragma unroll
        for (int kk = 0; kk < 32; kk += 16) {
            uint32_t Afh[4][4], Afl[4][4];
            #pragma unroll
            for (int mt = 0; mt < 4; mt++)
                LDSM4(Afh[mt], s2u(&bAh[(wm * 64 + mt * 16 + lrow) * RS + kk + lko]));
            #pragma unroll
            for (int mt = 0; mt < 4; mt++)
                LDSM4(Afl[mt], s2u(&bAl[(wm * 64 + mt * 16 + lrow) * RS + kk + lko]));

            #pragma unroll
            for (int p = 0; p < 4; p++) {
                uint32_t Bfh[4], Bfl[4];
                LDSM4(Bfh, s2u(&bBh[(wn * 64 + p * 16 + lrow) * RS + kk + lko]));
                LDSM4(Bfl, s2u(&bBl[(wn * 64 + p * 16 + lrow) * RS + kk + lko]));
                #pragma unroll
                for (int mt = 0; mt < 4; mt++) {
                    MMA16816(acc[mt][2 * p + 0], Afh[mt], Bfh[0], Bfh[2]);
                    MMA16816(acc[mt][2 * p + 1], Afh[mt], Bfh[1], Bfh[3]);
                    MMA16816(acc[mt][2 * p + 0], Afh[mt], Bfl[0], Bfl[2]);
                    MMA16816(acc[mt][2 * p + 1], Afh[mt], Bfl[1], Bfl[3]);
                    MMA16816(acc[mt][2 * p + 0], Afl[mt], Bfh[0], Bfh[2]);
                    MMA16816(acc[mt][2 * p + 1], Afl[mt], Bfh[1], Bfh[3]);
                }
            }
        }
    }

    // ---- epilogue
    float* Cb = C + coff;
    const float* Rb = (EPI == 3) ? (Res + coff) : nullptr;
    bf16* Hb = OUTBF ? (Chi + coff) : nullptr;
    bf16* Lb = OUTBF ? (Clo + coff) : nullptr;
    const int rb = lane >> 2, cbl = (lane & 3) * 2;
    #pragma unroll
    for (int mt = 0; mt < 4; mt++) {
        #pragma unroll
        for (int half = 0; half < 2; half++) {
            int r = m0 + wm * 64 + mt * 16 + rb + half * 8;
            float* crow = Cb + (size_t)r * ldc;
            const float* rrow = (EPI == 3) ? (Rb + (size_t)r * ldc) : nullptr;
            #pragma unroll
            for (int j = 0; j < 8; j++) {
                int cc = n0 + wn * 64 + (j >> 1) * 16 + (j & 1) * 8 + cbl;
                float x0 = acc[mt][j][half * 2 + 0] * scale;
                float x1 = acc[mt][j][half * 2 + 1] * scale;
                if (EPI >= 1) { x0 += bias[cc]; x1 += bias[cc + 1]; }
                if (EPI == 2) {
                    x0 = 0.5f * x0 * (1.f + erff(x0 * 0.70710678118654752f));
                    x1 = 0.5f * x1 * (1.f + erff(x1 * 0.70710678118654752f));
                }
                if (EPI == 3) {
                    float2 rv = *(const float2*)(rrow + cc);
                    x0 += rv.x; x1 += rv.y;
                }
                *(float2*)(crow + cc) = make_float2(x0, x1);
                if (OUTBF) {
                    uint32_t h, l;
                    split2(x0, x1, h, l);
                    *(uint32_t*)(Hb + (size_t)r * ldc + cc) = h;
                    *(uint32_t*)(Lb + (size_t)r * ldc + cc) = l;
                }
            }
        }
    }
}

// ---------------- scalar SGEMM (attn @ V only) ----------------
__device__ __forceinline__ ull dup_f32x2(float a) {
    ull r;
    unsigned au = __float_as_uint(a);
    asm("mov.b64 %0, {%1, %1};" : "=l"(r) : "r"(au));
    return r;
}
__device__ __forceinline__ void fma_f32x2(ull& acc, ull a, ull b) {
    asm("fma.rn.f32x2 %0, %1, %2, %0;" : "+l"(acc) : "l"(a), "l"(b));
}

__global__ __launch_bounds__(256, 2)
void gemm_av(const float* __restrict__ A, int lda, long sAhi,
             const float* __restrict__ Bm, int ldb, long sBhi, long sBlo, int nloB,
             float* __restrict__ C, int ldc, long sChi, long sClo, int nloC,
             int K)
{
    constexpr int BM = 128, BK = 16, TM = 8, BN_ = 64, TN_ = 4, TN2 = 2;
    const int tid = threadIdx.x;
    const int z = blockIdx.z;
    A  += (long)z * sAhi;
    Bm += (long)(z / nloB) * sBhi + (long)(z % nloB) * sBlo;
    C  += (long)(z / nloC) * sChi + (long)(z % nloC) * sClo;

    const int m0 = blockIdx.y * BM;
    const int n0 = blockIdx.x * BN_;

    __shared__ float As[BK][BM + 4];
    __shared__ float Bs[BK][BN_ + 4];

    ull acc2[TM][TN2];
    #pragma unroll
    for (int i = 0; i < TM; i++)
        #pragma unroll
        for (int j = 0; j < TN2; j++) acc2[i][j] = 0ull;

    const int ty = tid >> 4;
    const int tx = tid & 15;

    for (int k0 = 0; k0 < K; k0 += BK) {
        {
            int r = tid >> 1;
            int c = (tid & 1) * 8;
            const float* src = A + (long)(m0 + r) * lda + (k0 + c);
            float4 v0 = *(const float4*)src;
            float4 v1 = *(const float4*)(src + 4);
            As[c + 0][r] = v0.x; As[c + 1][r] = v0.y; As[c + 2][r] = v0.z; As[c + 3][r] = v0.w;
            As[c + 4][r] = v1.x; As[c + 5][r] = v1.y; As[c + 6][r] = v1.z; As[c + 7][r] = v1.w;
        }
        {
            int r = tid >> 4;
            int c = (tid & 15) * 4;
            float4 v = *(const float4*)(Bm + (long)(k0 + r) * ldb + (n0 + c));
            *(float4*)&Bs[r][c] = v;
        }
        __syncthreads();

        #pragma unroll
        for (int k = 0; k < BK; k++) {
            float a[TM];
            *(float4*)&a[0] = *(const float4*)&As[k][ty * TM];
            *(float4*)&a[4] = *(const float4*)&As[k][ty * TM + 4];
            ull b2[TN2];
            {
                ulonglong2 q0 = *(const ulonglong2*)&Bs[k][tx * TN_];
                b2[0] = q0.x; b2[1] = q0.y;
            }
            #pragma unroll
            for (int i = 0; i < TM; i++) {
                ull a2 = dup_f32x2(a[i]);
                #pragma unroll
                for (int j = 0; j < TN2; j++)
                    fma_f32x2(acc2[i][j], a2, b2[j]);
            }
        }
        __syncthreads();
    }

    #pragma unroll
    for (int i = 0; i < TM; i++) {
        int m = m0 + ty * TM + i;
        float* crow = C + (long)m * ldc + n0 + tx * TN_;
        *(float4*)crow = make_float4(
            ((float2*)&acc2[i][0])->x, ((float2*)&acc2[i][0])->y,
            ((float2*)&acc2[i][1])->x, ((float2*)&acc2[i][1])->y);
    }
}

// ---------------- fp32 -> bf16 hi/lo conversion ----------------
__global__ void cvt_k(const float* __restrict__ x, bf16* __restrict__ hi,
                      bf16* __restrict__ lo, long n)
{
    long i = ((long)blockIdx.x * blockDim.x + threadIdx.x) * 4;
    if (i >= n) return;
    float4 v = *(const float4*)(x + i);
    uint32_t h0, l0, h1, l1;
    split2(v.x, v.y, h0, l0);
    split2(v.z, v.w, h1, l1);
    *(uint2*)(hi + i) = make_uint2(h0, h1);
    *(uint2*)(lo + i) = make_uint2(l0, l1);
}

// ---------------- embedding ----------------
__global__ void embed_k(const int* __restrict__ seq, const float* __restrict__ bemb,
                        const float* __restrict__ pemb, float* __restrict__ x)
{
    int r = blockIdx.x;
    int s = r % Sc;
    int tok = seq[r];
    int c = threadIdx.x * 4;
    float4 e = *(const float4*)(bemb + (long)tok * Dc + c);
    float4 p = *(const float4*)(pemb + (long)s * Dc + c);
    e.x += p.x; e.y += p.y; e.z += p.z; e.w += p.w;
    *(float4*)(x + (long)r * Dc + c) = e;
}

// ---------------- layernorm -> bf16 hi/lo planes ----------------
__global__ void ln_k(const float* __restrict__ x, const float* __restrict__ g,
                     const float* __restrict__ b, bf16* __restrict__ hi,
                     bf16* __restrict__ lo)
{
    const int row = blockIdx.x;
    const int tid = threadIdx.x;
    const float* xr = x + (long)row * Dc;
    float4 v = *(const float4*)(xr + tid * 4);
    float s = v.x + v.y + v.z + v.w;
    float tot = block_sum(s);
    float m = tot * (1.f / Dc);
    float dx0 = v.x - m, dx1 = v.y - m, dx2 = v.z - m, dx3 = v.w - m;
    float q = dx0 * dx0 + dx1 * dx1 + dx2 * dx2 + dx3 * dx3;
    float totq = block_sum(q);
    float rs = rsqrtf(totq * (1.f / Dc) + 1e-5f);
    float4 gg = *(const float4*)(g + tid * 4);
    float4 bb = *(const float4*)(b + tid * 4);
    float o0 = dx0 * rs * gg.x + bb.x;
    float o1 = dx1 * rs * gg.y + bb.y;
    float o2 = dx2 * rs * gg.z + bb.z;
    float o3 = dx3 * rs * gg.w + bb.w;
    uint32_t h0, l0, h1, l1;
    split2(o0, o1, h0, l0);
    split2(o2, o3, h1, l1);
    *(uint2*)(hi + (long)row * Dc + tid * 4) = make_uint2(h0, h1);
    *(uint2*)(lo + (long)row * Dc + tid * 4) = make_uint2(l0, l1);
}

// ---------------- self-attn softmax (causal window) ----------------
__global__ void smax_sa(float* __restrict__ sc)
{
    const int i = blockIdx.x;
    const int z = blockIdx.y;
    float* row = sc + ((long)z * Sc + i) * Sc;
    const int tid = threadIdx.x;
    int lo = i - Wc + 1; if (lo < 0) lo = 0;
    const int hi = i;
    float v[4];
    float mx = -1e30f;
    #pragma unroll
    for (int t = 0; t < 4; t++) {
        int j = tid + t * 256;
        bool ok = (j >= lo) && (j <= hi);
        v[t] = ok ? row[j] : -1e30f;
        mx = fmaxf(mx, v[t]);
    }
    mx = block_max(mx);
    float s = 0.f;
    #pragma unroll
    for (int t = 0; t < 4; t++) {
        int j = tid + t * 256;
        bool ok = (j >= lo) && (j <= hi);
        v[t] = ok ? expf(v[t] - mx) : 0.f;
        s += v[t];
    }
    s = block_sum(s);
    float inv = 1.f / s;
    #pragma unroll
    for (int t = 0; t < 4; t++)
        row[tid + t * 256] = v[t] * inv;
}

// ---------------- cross-attn softmax ----------------
__global__ void smax_ca(float* __restrict__ sc, const int* __restrict__ pidx)
{
    const int i = blockIdx.x;
    const int z = blockIdx.y;
    const int b = z / Hc;
    float* row = sc + ((long)z * Sc + i) * Pc;
    const int tid = threadIdx.x;
    const int lim = pidx[b * Sc + i];
    bool ok = tid <= lim;
    float v = ok ? row[tid] : -1e30f;
    float mx = block_max(v);
    float e = ok ? expf(v - mx) : 0.f;
    float s = block_sum(e);
    row[tid] = e / s;
}

// ---------------- inclusive cumsum ----------------
__global__ void cumsum_k(const int* __restrict__ bd, int* __restrict__ pidx)
{
    __shared__ int s[Sc];
    const int b = blockIdx.x, t = threadIdx.x;
    s[t] = bd[b * Sc + t];
    __syncthreads();
    for (int off = 1; off < Sc; off <<= 1) {
        int v = (t >= off) ? s[t - off] : 0;
        __syncthreads();
        s[t] += v;
        __syncthreads();
    }
    pidx[b * Sc + t] = s[t];
}

// ---------------- launcher ----------------
extern "C" void kernel_launch(void* const* d_in, const int* in_sizes, int n_in,
                              void* d_out, int out_size)
{
    const int*   byte_seq  = (const int*)  d_in[0];
    const float* patch_rep = (const float*)d_in[1];
    const int*   patch_bd  = (const int*)  d_in[2];
    const float* byte_emb  = (const float*)d_in[3];
    const float* pos_emb   = (const float*)d_in[4];
    const float* sa_in_w   = (const float*)d_in[5];
    const float* sa_in_b   = (const float*)d_in[6];
    const float* sa_out_w  = (const float*)d_in[7];
    const float* sa_out_b  = (const float*)d_in[8];
    const float* ca_in_w   = (const float*)d_in[9];
    const float* ca_in_b   = (const float*)d_in[10];
    const float* ca_out_w  = (const float*)d_in[11];
    const float* ca_out_b  = (const float*)d_in[12];
    const float* ffn_w1    = (const float*)d_in[13];
    const float* ffn_b1    = (const float*)d_in[14];
    const float* ffn_w2    = (const float*)d_in[15];
    const float* ffn_b2    = (const float*)d_in[16];
    const float* ln_g      = (const float*)d_in[17];
    const float* ln_b      = (const float*)d_in[18];
    const float* norm_g    = (const float*)d_in[19];
    const float* norm_b    = (const float*)d_in[20];
    const float* out_w     = (const float*)d_in[21];
    float* out = (float*)d_out;

    float *gx, *gqkv, *gcaq, *gcakv, *gsc, *gao, *gffn;
    int* gpidx;
    bf16 *whi, *wlo, *hh, *hl, *qh, *ql, *cqh, *cql, *ckh, *ckl, *fh, *fl, *prh, *prl;
    cudaGetSymbolAddress((void**)&gx,    g_x);
    cudaGetSymbolAddress((void**)&gqkv,  g_qkv);
    cudaGetSymbolAddress((void**)&gcaq,  g_caq);
    cudaGetSymbolAddress((void**)&gcakv, g_cakv);
    cudaGetSymbolAddress((void**)&gsc,   g_sc);
    cudaGetSymbolAddress((void**)&gao,   g_ao);
    cudaGetSymbolAddress((void**)&gffn,  g_ffn);
    cudaGetSymbolAddress((void**)&gpidx, g_pidx);
    cudaGetSymbolAddress((void**)&whi, g_whi);
    cudaGetSymbolAddress((void**)&wlo, g_wlo);
    cudaGetSymbolAddress((void**)&hh,  g_hh);
    cudaGetSymbolAddress((void**)&hl,  g_hl);
    cudaGetSymbolAddress((void**)&qh,  g_qh);
    cudaGetSymbolAddress((void**)&ql,  g_ql);
    cudaGetSymbolAddress((void**)&cqh, g_cqh);
    cudaGetSymbolAddress((void**)&cql, g_cql);
    cudaGetSymbolAddress((void**)&ckh, g_ckh);
    cudaGetSymbolAddress((void**)&ckl, g_ckl);
    cudaGetSymbolAddress((void**)&fh,  g_fh);
    cudaGetSymbolAddress((void**)&fl,  g_fl);
    cudaGetSymbolAddress((void**)&prh, g_prh);
    cudaGetSymbolAddress((void**)&prl, g_prl);

    cudaFuncSetAttribute(gemm_tc<0, false>, cudaFuncAttributeMaxDynamicSharedMemorySize, TCS);
    cudaFuncSetAttribute(gemm_tc<1, true>,  cudaFuncAttributeMaxDynamicSharedMemorySize, TCS);
    cudaFuncSetAttribute(gemm_tc<2, true>,  cudaFuncAttributeMaxDynamicSharedMemorySize, TCS);
    cudaFuncSetAttribute(gemm_tc<3, false>, cudaFuncAttributeMaxDynamicSharedMemorySize, TCS);

    // weight + patch_rep conversion
    auto cvt = [&](const float* src, bf16* dh, bf16* dl, long n) {
        cvt_k<<<(unsigned)((n / 4 + 255) / 256), 256>>>(src, dh, dl, n);
    };
    cvt(sa_in_w,  whi + OFF_SAIN,  wlo + OFF_SAIN,  (long)Lc * 3 * Dc * Dc);
    cvt(sa_out_w, whi + OFF_SAOUT, wlo + OFF_SAOUT, (long)Lc * Dc * Dc);
    cvt(ca_in_w,  whi + OFF_CAIN,  wlo + OFF_CAIN,  (long)Lc * 3 * Dc * Dc);
    cvt(ca_out_w, whi + OFF_CAOUT, wlo + OFF_CAOUT, (long)Lc * Dc * Dc);
    cvt(ffn_w1,   whi + OFF_FFN1,  wlo + OFF_FFN1,  (long)Lc * 4 * Dc * Dc);
    cvt(ffn_w2,   whi + OFF_FFN2,  wlo + OFF_FFN2,  (long)Lc * 4 * Dc * Dc);
    cvt(out_w,    whi + OFF_OUTW,  wlo + OFF_OUTW,  (long)Vc * Dc);
    cvt(patch_rep, prh, prl, (long)Bc * Pc * Dc);

    embed_k<<<BS, 256>>>(byte_seq, byte_emb, pos_emb, gx);
    cumsum_k<<<Bc, Sc>>>(patch_bd, gpidx);

    for (int l = 0; l < Lc; l++) {
        // ===== self-attention =====
        ln_k<<<BS, 256>>>(gx, ln_g + (long)(l * 3 + 0) * Dc, ln_b + (long)(l * 3 + 0) * Dc, hh, hl);

        // QKV: fp32 out + bf16 planes
        gemm_tc<1, true><<<dim3(3 * Dc / 128, BS / 128), 128, TCS>>>(
            hh, hl, Dc, 0, 0, 1,
            whi + OFF_SAIN + (long)l * 3 * Dc * Dc, wlo + OFF_SAIN + (long)l * 3 * Dc * Dc, Dc, 0, 0, 1,
            sa_in_b + (long)l * 3 * Dc, nullptr,
            gqkv, qh, ql, 3 * Dc, 0, 0, 1, Dc, 1.f);

        // scores: Q @ K^T / 8
        gemm_tc<0, false><<<dim3(Sc / 128, Sc / 128, Bc * Hc), 128, TCS>>>(
            qh,      ql,      3 * Dc, (long)Sc * 3 * Dc, DH, Hc,
            qh + Dc, ql + Dc, 3 * Dc, (long)Sc * 3 * Dc, DH, Hc,
            nullptr, nullptr,
            gsc, nullptr, nullptr, Sc, (long)Sc * Sc, 0, 1,
            DH, 0.125f);

        smax_sa<<<dim3(Sc, Bc * Hc), 256>>>(gsc);

        gemm_av<<<dim3(1, Sc / 128, Bc * Hc), 256>>>(
            gsc, Sc, (long)Sc * Sc,
            gqkv + 2 * Dc, 3 * Dc, (long)Sc * 3 * Dc, DH, Hc,
            gao, Dc, (long)Sc * Dc, DH, Hc,
            Sc);

        // out proj + residual (A = gao: convert planes first)
        cvt(gao, cqh, cql, (long)BS * Dc);
        gemm_tc<3, false><<<dim3(Dc / 128, BS / 128), 128, TCS>>>(
            cqh, cql, Dc, 0, 0, 1,
            whi + OFF_SAOUT + (long)l * Dc * Dc, wlo + OFF_SAOUT + (long)l * Dc * Dc, Dc, 0, 0, 1,
            sa_out_b + (long)l * Dc, gx,
            gx, nullptr, nullptr, Dc, 0, 0, 1, Dc, 1.f);

        // ===== cross-attention =====
        ln_k<<<BS, 256>>>(gx, ln_g + (long)(l * 3 + 1) * Dc, ln_b + (long)(l * 3 + 1) * Dc, hh, hl);

        gemm_tc<1, true><<<dim3(Dc / 128, BS / 128), 128, TCS>>>(
            hh, hl, Dc, 0, 0, 1,
            whi + OFF_CAIN + (long)l * 3 * Dc * Dc, wlo + OFF_CAIN + (long)l * 3 * Dc * Dc, Dc, 0, 0, 1,
            ca_in_b + (long)l * 3 * Dc, nullptr,
            gcaq, cqh, cql, Dc, 0, 0, 1, Dc, 1.f);

        gemm_tc<1, true><<<dim3(2 * Dc / 128, (Bc * Pc) / 128), 128, TCS>>>(
            prh, prl, Dc, 0, 0, 1,
            whi + OFF_CAIN + (long)l * 3 * Dc * Dc + (long)Dc * Dc,
            wlo + OFF_CAIN + (long)l * 3 * Dc * Dc + (long)Dc * Dc, Dc, 0, 0, 1,
            ca_in_b + (long)l * 3 * Dc + Dc, nullptr,
            gcakv, ckh, ckl, 2 * Dc, 0, 0, 1, Dc, 1.f);

        // CA scores
        gemm_tc<0, false><<<dim3(Pc / 128, Sc / 128, Bc * Hc), 128, TCS>>>(
            cqh, cql, Dc,     (long)Sc * Dc,     DH, Hc,
            ckh, ckl, 2 * Dc, (long)Pc * 2 * Dc, DH, Hc,
            nullptr, nullptr,
            gsc, nullptr, nullptr, Pc, (long)Sc * Pc, 0, 1,
            DH, 0.125f);

        smax_ca<<<dim3(Sc, Bc * Hc), 128>>>(gsc, gpidx);

        gemm_av<<<dim3(1, Sc / 128, Bc * Hc), 256>>>(
            gsc, Pc, (long)Sc * Pc,
            gcakv + Dc, 2 * Dc, (long)Pc * 2 * Dc, DH, Hc,
            gao, Dc, (long)Sc * Dc, DH, Hc,
            Pc);

        cvt(gao, cqh, cql, (long)BS * Dc);
        gemm_tc<3, false><<<dim3(Dc / 128, BS / 128), 128, TCS>>>(
            cqh, cql, Dc, 0, 0, 1,
            whi + OFF_CAOUT + (long)l * Dc * Dc, wlo + OFF_CAOUT + (long)l * Dc * Dc, Dc, 0, 0, 1,
            ca_out_b + (long)l * Dc, gx,
            gx, nullptr, nullptr, Dc, 0, 0, 1, Dc, 1.f);

        // ===== FFN =====
        ln_k<<<BS, 256>>>(gx, ln_g + (long)(l * 3 + 2) * Dc, ln_b + (long)(l * 3 + 2) * Dc, hh, hl);

        gemm_tc<2, true><<<dim3(4 * Dc / 128, BS / 128), 128, TCS>>>(
            hh, hl, Dc, 0, 0, 1,
            whi + OFF_FFN1 + (long)l * 4 * Dc * Dc, wlo + OFF_FFN1 + (long)l * 4 * Dc * Dc, Dc, 0, 0, 1,
            ffn_b1 + (long)l * 4 * Dc, nullptr,
            gffn, fh, fl, 4 * Dc, 0, 0, 1, Dc, 1.f);

        gemm_tc<3, false><<<dim3(Dc / 128, BS / 128), 128, TCS>>>(
            fh, fl, 4 * Dc, 0, 0, 1,
            whi + OFF_FFN2 + (long)l * Dc * 4 * Dc, wlo + OFF_FFN2 + (long)l * Dc * 4 * Dc, 4 * Dc, 0, 0, 1,
            ffn_b2 + (long)l * Dc, gx,
            gx, nullptr, nullptr, Dc, 0, 0, 1, 4 * Dc, 1.f);
    }

    // final LN + vocab projection
    ln_k<<<BS, 256>>>(gx, norm_g, norm_b, hh, hl);
    gemm_tc<0, false><<<dim3(Vc / 128, BS / 128), 128, TCS>>>(
        hh, hl, Dc, 0, 0, 1,
        whi + OFF_OUTW, wlo + OFF_OUTW, Dc, 0, 0, 1,
        nullptr, nullptr,
        out, nullptr, nullptr, Vc, 0, 0, 1, Dc, 1.f);
}

// round 10
// speedup vs baseline: 1.6882x; 1.0685x over previous
#include <cuda_runtime.h>
#include <cuda_bf16.h>
#include <math.h>
#include <cstdint>

// ---------------- problem constants ----------------
constexpr int Bc = 2, Sc = 1024, Dc = 1024, Hc = 16, Lc = 9, Wc = 1024, Pc = 128, Vc = 256;
constexpr int DH = Dc / Hc;          // 64
constexpr int BS = Bc * Sc;          // 2048 rows

typedef unsigned long long ull;
typedef __nv_bfloat16 bf16;

// ---------------- device scratch ----------------
__device__ float g_x [BS * Dc];                       // residual stream (fp32)
__device__ float g_sc[(long)Bc * Hc * Sc * Sc];       // pre-softmax scores (fp32)
__device__ int   g_pidx[BS];

// weights mega-buffer offsets (elements)
constexpr long OFF_SAIN  = 0;
constexpr long OFF_SAOUT = OFF_SAIN  + (long)Lc * 3 * Dc * Dc;
constexpr long OFF_CAIN  = OFF_SAOUT + (long)Lc * Dc * Dc;
constexpr long OFF_CAOUT = OFF_CAIN  + (long)Lc * 3 * Dc * Dc;
constexpr long OFF_FFN1  = OFF_CAOUT + (long)Lc * Dc * Dc;
constexpr long OFF_FFN2  = OFF_FFN1  + (long)Lc * 4 * Dc * Dc;
constexpr long OFF_OUTW  = OFF_FFN2  + (long)Lc * 4 * Dc * Dc;
constexpr long W_TOTAL   = OFF_OUTW  + (long)Vc * Dc;

__device__ bf16 g_whi[W_TOTAL];
__device__ bf16 g_wlo[W_TOTAL];

__device__ bf16 g_hh [BS * Dc],          g_hl [BS * Dc];            // LN output planes
__device__ bf16 g_qh [BS * 3 * Dc],      g_ql [BS * 3 * Dc];        // qkv planes
__device__ bf16 g_cqh[BS * Dc],          g_cql[BS * Dc];            // CA q / attn-out planes
__device__ bf16 g_ckh[Bc * Pc * 2 * Dc], g_ckl[Bc * Pc * 2 * Dc];   // CA kv planes
__device__ bf16 g_fh [BS * 4 * Dc],      g_fl [BS * 4 * Dc];        // ffn hidden planes
__device__ bf16 g_prh[Bc * Pc * Dc],     g_prl[Bc * Pc * Dc];       // patch_rep planes
__device__ bf16 g_sph[(long)Bc * Hc * Sc * Sc];                     // softmax P planes
__device__ bf16 g_spl[(long)Bc * Hc * Sc * Sc];

// ---------------- reductions ----------------
__device__ __forceinline__ float block_sum(float v) {
    __shared__ float sh[32];
    int lane = threadIdx.x & 31, w = threadIdx.x >> 5;
    int nw = blockDim.x >> 5;
    #pragma unroll
    for (int o = 16; o; o >>= 1) v += __shfl_xor_sync(0xffffffffu, v, o);
    __syncthreads();
    if (lane == 0) sh[w] = v;
    __syncthreads();
    if (threadIdx.x == 0) {
        float t = 0.f;
        for (int i = 0; i < nw; i++) t += sh[i];
        sh[0] = t;
    }
    __syncthreads();
    return sh[0];
}

__device__ __forceinline__ float block_max(float v) {
    __shared__ float sh[32];
    int lane = threadIdx.x & 31, w = threadIdx.x >> 5;
    int nw = blockDim.x >> 5;
    #pragma unroll
    for (int o = 16; o; o >>= 1) v = fmaxf(v, __shfl_xor_sync(0xffffffffu, v, o));
    __syncthreads();
    if (lane == 0) sh[w] = v;
    __syncthreads();
    if (threadIdx.x == 0) {
        float t = -1e30f;
        for (int i = 0; i < nw; i++) t = fmaxf(t, sh[i]);
        sh[0] = t;
    }
    __syncthreads();
    return sh[0];
}

// ================= helpers =================
__device__ __forceinline__ uint32_t s2u(const void* p) {
    return (uint32_t)__cvta_generic_to_shared(p);
}
__device__ __forceinline__ void cp16(uint32_t dst, const void* src) {
    asm volatile("cp.async.cg.shared.global [%0], [%1], 16;" :: "r"(dst), "l"(src));
}

#define LDSM4(R, addr) \
    asm volatile("ldmatrix.sync.aligned.m8n8.x4.shared.b16 {%0,%1,%2,%3}, [%4];" \
        : "=r"((R)[0]), "=r"((R)[1]), "=r"((R)[2]), "=r"((R)[3]) : "r"(addr))

#define LDSM4T(R, addr) \
    asm volatile("ldmatrix.sync.aligned.m8n8.x4.trans.shared.b16 {%0,%1,%2,%3}, [%4];" \
        : "=r"((R)[0]), "=r"((R)[1]), "=r"((R)[2]), "=r"((R)[3]) : "r"(addr))

#define MMA16816(d, a, b0, b1) \
    asm volatile("mma.sync.aligned.m16n8k16.row.col.f32.bf16.bf16.f32 " \
        "{%0,%1,%2,%3}, {%4,%5,%6,%7}, {%8,%9}, {%0,%1,%2,%3};" \
        : "+f"((d)[0]), "+f"((d)[1]), "+f"((d)[2]), "+f"((d)[3]) \
        : "r"((a)[0]), "r"((a)[1]), "r"((a)[2]), "r"((a)[3]), "r"(b0), "r"(b1))

__device__ __forceinline__ void split2(float x0, float x1, uint32_t& h, uint32_t& l) {
    __nv_bfloat162 hh = __floats2bfloat162_rn(x0, x1);
    float2 hf = __bfloat1622float2(hh);
    __nv_bfloat162 ll = __floats2bfloat162_rn(x0 - hf.x, x1 - hf.y);
    h = *(uint32_t*)&hh; l = *(uint32_t*)&ll;
}

// ================= pipelined bf16x3 mma.sync GEMM (A @ B^T) =================
constexpr int RS = 40;
constexpr int TCS = 2 * 4 * 128 * RS * 2;    // 81920 bytes

template<int EPI, bool OUTBF>
__global__ __launch_bounds__(128, 2)
void gemm_tc(const bf16* __restrict__ Ah, const bf16* __restrict__ Al, int lda, long hiA, long loA, int nloA,
             const bf16* __restrict__ Bh, const bf16* __restrict__ Bl, int ldb, long hiB, long loB, int nloB,
             const float* __restrict__ bias, const float* __restrict__ Res,
             float* __restrict__ C, bf16* __restrict__ Chi, bf16* __restrict__ Clo,
             int ldc, long hiC, long loC, int nloC, int K, float scale, int tri)
{
    extern __shared__ __align__(16) bf16 sbuf[];

    const int m0 = blockIdx.y * 128, n0 = blockIdx.x * 128;
    if (tri && n0 > m0 + 127) return;      // fully-masked upper tile

    const int tid = threadIdx.x, lane = tid & 31, wid = tid >> 5;
    const int wm = wid >> 1, wn = wid & 1;
    const int z = blockIdx.z;
    Ah += (long)(z / nloA) * hiA + (long)(z % nloA) * loA;
    Al += (long)(z / nloA) * hiA + (long)(z % nloA) * loA;
    Bh += (long)(z / nloB) * hiB + (long)(z % nloB) * loB;
    Bl += (long)(z / nloB) * hiB + (long)(z % nloB) * loB;
    const long coff = (long)(z / nloC) * hiC + (long)(z % nloC) * loC;

    const uint32_t sbase = s2u(sbuf);
    const bf16* pA[4];
    pA[0] = Ah + (size_t)(m0 + tid) * lda;
    pA[1] = Al + (size_t)(m0 + tid) * lda;
    pA[2] = Bh + (size_t)(n0 + tid) * ldb;
    pA[3] = Bl + (size_t)(n0 + tid) * ldb;

    float acc[4][8][4];
    #pragma unroll
    for (int i = 0; i < 4; i++)
        #pragma unroll
        for (int j = 0; j < 8; j++)
            #pragma unroll
            for (int q = 0; q < 4; q++) acc[i][j][q] = 0.f;

    const int nk = K / 32;

    auto issue = [&](int c) {
        uint32_t base = sbase + (uint32_t)(c & 1) * (4 * 128 * RS * 2);
        #pragma unroll
        for (int t = 0; t < 4; t++) {
            uint32_t dst = base + (uint32_t)(t * 128 + tid) * (RS * 2);
            const bf16* src = pA[t] + c * 32;
            #pragma unroll
            for (int q = 0; q < 4; q++)
                cp16(dst + q * 16, src + q * 8);
        }
        asm volatile("cp.async.commit_group;");
    };

    issue(0);

    const int lrow = lane & 15, lko = (lane >> 4) * 8;

    for (int k0 = 0; k0 < nk; k0++) {
        asm volatile("cp.async.wait_group 0;");
        __syncthreads();
        if (k0 + 1 < nk) issue(k0 + 1);

        const bf16* bAh = sbuf + (size_t)(k0 & 1) * (4 * 128 * RS);
        const bf16* bAl = bAh + 128 * RS;
        const bf16* bBh = bAh + 2 * 128 * RS;
        const bf16* bBl = bAh + 3 * 128 * RS;

        #pragma unroll
        for (int kk = 0; kk < 32; kk += 16) {
            uint32_t Afh[4][4], Afl[4][4];
            #pragma unroll
            for (int mt = 0; mt < 4; mt++)
                LDSM4(Afh[mt], s2u(&bAh[(wm * 64 + mt * 16 + lrow) * RS + kk + lko]));
            #pragma unroll
            for (int mt = 0; mt < 4; mt++)
                LDSM4(Afl[mt], s2u(&bAl[(wm * 64 + mt * 16 + lrow) * RS + kk + lko]));

            #pragma unroll
            for (int p = 0; p < 4; p++) {
                uint32_t Bfh[4], Bfl[4];
                LDSM4(Bfh, s2u(&bBh[(wn * 64 + p * 16 + lrow) * RS + kk + lko]));
                LDSM4(Bfl, s2u(&bBl[(wn * 64 + p * 16 + lrow) * RS + kk + lko]));
                #pragma unroll
                for (int mt = 0; mt < 4; mt++) {
                    MMA16816(acc[mt][2 * p + 0], Afh[mt], Bfh[0], Bfh[2]);
                    MMA16816(acc[mt][2 * p + 1], Afh[mt], Bfh[1], Bfh[3]);
                    MMA16816(acc[mt][2 * p + 0], Afh[mt], Bfl[0], Bfl[2]);
                    MMA16816(acc[mt][2 * p + 1], Afh[mt], Bfl[1], Bfl[3]);
                    MMA16816(acc[mt][2 * p + 0], Afl[mt], Bfh[0], Bfh[2]);
                    MMA16816(acc[mt][2 * p + 1], Afl[mt], Bfh[1], Bfh[3]);
                }
            }
        }
    }

    // ---- epilogue
    float* Cb = C ? (C + coff) : nullptr;
    const float* Rb = (EPI == 3) ? (Res + coff) : nullptr;
    bf16* Hb = OUTBF ? (Chi + coff) : nullptr;
    bf16* Lb = OUTBF ? (Clo + coff) : nullptr;
    const int rb = lane >> 2, cbl = (lane & 3) * 2;
    #pragma unroll
    for (int mt = 0; mt < 4; mt++) {
        #pragma unroll
        for (int half = 0; half < 2; half++) {
            int r = m0 + wm * 64 + mt * 16 + rb + half * 8;
            #pragma unroll
            for (int j = 0; j < 8; j++) {
                int cc = n0 + wn * 64 + (j >> 1) * 16 + (j & 1) * 8 + cbl;
                float x0 = acc[mt][j][half * 2 + 0] * scale;
                float x1 = acc[mt][j][half * 2 + 1] * scale;
                if (EPI >= 1) { x0 += bias[cc]; x1 += bias[cc + 1]; }
                if (EPI == 2) {
                    x0 = 0.5f * x0 * (1.f + erff(x0 * 0.70710678118654752f));
                    x1 = 0.5f * x1 * (1.f + erff(x1 * 0.70710678118654752f));
                }
                if (EPI == 3) {
                    float2 rv = *(const float2*)(Rb + (size_t)r * ldc + cc);
                    x0 += rv.x; x1 += rv.y;
                }
                if (Cb) *(float2*)(Cb + (size_t)r * ldc + cc) = make_float2(x0, x1);
                if (OUTBF) {
                    uint32_t h, l;
                    split2(x0, x1, h, l);
                    *(uint32_t*)(Hb + (size_t)r * ldc + cc) = h;
                    *(uint32_t*)(Lb + (size_t)r * ldc + cc) = l;
                }
            }
        }
    }
}

// ================= P @ V tensor GEMM (B non-transposed, trans-ldmatrix) =================
// C[128 x 64] per CTA; 4 warps (2x2), warp tile 64x32; K chunks of 32, double-buffered.
constexpr int RSN = 72;                                   // V smem row stride (bf16)
constexpr int PV_BUFE = 2 * 128 * RS + 2 * 32 * RSN;      // elements per buffer = 14848
constexpr int PVS = 2 * PV_BUFE * 2;                      // bytes = 59392

template<bool TRI>
__global__ __launch_bounds__(128, 2)
void gemm_pv(const bf16* __restrict__ Ph, const bf16* __restrict__ Pl, int lda, long strideAz,
             const bf16* __restrict__ Vh, const bf16* __restrict__ Vl, int ldb, long hiB, long loB, int nloB,
             bf16* __restrict__ Chi, bf16* __restrict__ Clo, int ldc, long hiC, long loC, int nloC,
             int K)
{
    extern __shared__ __align__(16) bf16 sbuf[];

    const int tid = threadIdx.x, lane = tid & 31, wid = tid >> 5;
    const int wm = wid >> 1, wn = wid & 1;
    const int z = blockIdx.z;
    const int m0 = blockIdx.y * 128;

    Ph += (long)z * strideAz;
    Pl += (long)z * strideAz;
    Vh += (long)(z / nloB) * hiB + (long)(z % nloB) * loB;
    Vl += (long)(z / nloB) * hiB + (long)(z % nloB) * loB;
    const long coff = (long)(z / nloC) * hiC + (long)(z % nloC) * loC;

    const uint32_t sbase = s2u(sbuf);
    const bf16* pAh = Ph + (size_t)(m0 + tid) * lda;
    const bf16* pAl = Pl + (size_t)(m0 + tid) * lda;
    const int vr = tid >> 2, vsub = tid & 3;
    const int vplane = vsub >> 1, vhalf = vsub & 1;
    const bf16* pV = (vplane ? Vl : Vh);

    float acc[4][4][4];
    #pragma unroll
    for (int i = 0; i < 4; i++)
        #pragma unroll
        for (int j = 0; j < 4; j++)
            #pragma unroll
            for (int q = 0; q < 4; q++) acc[i][j][q] = 0.f;

    const int nk = TRI ? (m0 / 32 + 4) : (K / 32);

    auto issue = [&](int c) {
        uint32_t base = sbase + (uint32_t)(c & 1) * (PV_BUFE * 2);
        // A (P) planes: thread = one row, 32 k x 2 planes
        {
            uint32_t dA = base + (uint32_t)tid * (RS * 2);
            const bf16* sa = pAh + c * 32;
            const bf16* sl = pAl + c * 32;
            #pragma unroll
            for (int q = 0; q < 4; q++) {
                cp16(dA + q * 16, sa + q * 8);
                cp16(dA + 128 * RS * 2 + q * 16, sl + q * 8);
            }
        }
        // V: 32 rows x 64 n x 2 planes; each thread owns one (row, plane, half) = 32 elems = 64B
        {
            uint32_t dV = base + (uint32_t)(2 * 128 * RS + vplane * 32 * RSN + vr * RSN + vhalf * 32) * 2;
            const bf16* sv = pV + (size_t)(c * 32 + vr) * ldb + vhalf * 32;
            #pragma unroll
            for (int q = 0; q < 4; q++)
                cp16(dV + q * 16, sv + q * 8);
        }
        asm volatile("cp.async.commit_group;");
    };

    issue(0);

    const int lrow = lane & 15, lko = (lane >> 4) * 8;
    const int tkrow = (lane & 7) + ((lane >> 4) << 3);
    const int tncol = ((lane >> 3) & 1) * 8;

    for (int k0 = 0; k0 < nk; k0++) {
        asm volatile("cp.async.wait_group 0;");
        __syncthreads();
        if (k0 + 1 < nk) issue(k0 + 1);

        const bf16* bAh = sbuf + (size_t)(k0 & 1) * PV_BUFE;
        const bf16* bAl = bAh + 128 * RS;
        const bf16* bVh = bAh + 2 * 128 * RS;
        const bf16* bVl = bVh + 32 * RSN;

        #pragma unroll
        for (int kk = 0; kk < 32; kk += 16) {
            uint32_t Afh[4][4], Afl[4][4];
            #pragma unroll
            for (int mt = 0; mt < 4; mt++)
                LDSM4(Afh[mt], s2u(&bAh[(wm * 64 + mt * 16 + lrow) * RS + kk + lko]));
            #pragma unroll
            for (int mt = 0; mt < 4; mt++)
                LDSM4(Afl[mt], s2u(&bAl[(wm * 64 + mt * 16 + lrow) * RS + kk + lko]));

            #pragma unroll
            for (int p = 0; p < 2; p++) {
                uint32_t Bfh[4], Bfl[4];
                LDSM4T(Bfh, s2u(&bVh[(kk + tkrow) * RSN + wn * 32 + p * 16 + tncol]));
                LDSM4T(Bfl, s2u(&bVl[(kk + tkrow) * RSN + wn * 32 + p * 16 + tncol]));
                #pragma unroll
                for (int mt = 0; mt < 4; mt++) {
                    MMA16816(acc[mt][2 * p + 0], Afh[mt], Bfh[0], Bfh[2]);
                    MMA16816(acc[mt][2 * p + 1], Afh[mt], Bfh[1], Bfh[3]);
                    MMA16816(acc[mt][2 * p + 0], Afh[mt], Bfl[0], Bfl[2]);
                    MMA16816(acc[mt][2 * p + 1], Afh[mt], Bfl[1], Bfl[3]);
                    MMA16816(acc[mt][2 * p + 0], Afl[mt], Bfh[0], Bfh[2]);
                    MMA16816(acc[mt][2 * p + 1], Afl[mt], Bfh[1], Bfh[3]);
                }
            }
        }
    }

    // ---- epilogue: bf16 hi/lo planes only
    bf16* Hb = Chi + coff;
    bf16* Lb = Clo + coff;
    const int rb = lane >> 2, cbl = (lane & 3) * 2;
    #pragma unroll
    for (int mt = 0; mt < 4; mt++) {
        #pragma unroll
        for (int half = 0; half < 2; half++) {
            int r = m0 + wm * 64 + mt * 16 + rb + half * 8;
            #pragma unroll
            for (int j = 0; j < 4; j++) {
                int cc = wn * 32 + (j >> 1) * 16 + (j & 1) * 8 + cbl;
                float x0 = acc[mt][j][half * 2 + 0];
                float x1 = acc[mt][j][half * 2 + 1];
                uint32_t h, l;
                split2(x0, x1, h, l);
                *(uint32_t*)(Hb + (size_t)r * ldc + cc) = h;
                *(uint32_t*)(Lb + (size_t)r * ldc + cc) = l;
            }
        }
    }
}

// ---------------- fp32 -> bf16 hi/lo conversion ----------------
__global__ void cvt_k(const float* __restrict__ x, bf16* __restrict__ hi,
                      bf16* __restrict__ lo, long n)
{
    long i = ((long)blockIdx.x * blockDim.x + threadIdx.x) * 4;
    if (i >= n) return;
    float4 v = *(const float4*)(x + i);
    uint32_t h0, l0, h1, l1;
    split2(v.x, v.y, h0, l0);
    split2(v.z, v.w, h1, l1);
    *(uint2*)(hi + i) = make_uint2(h0, h1);
    *(uint2*)(lo + i) = make_uint2(l0, l1);
}

// ---------------- embedding ----------------
__global__ void embed_k(const int* __restrict__ seq, const float* __restrict__ bemb,
                        const float* __restrict__ pemb, float* __restrict__ x)
{
    int r = blockIdx.x;
    int s = r % Sc;
    int tok = seq[r];
    int c = threadIdx.x * 4;
    float4 e = *(const float4*)(bemb + (long)tok * Dc + c);
    float4 p = *(const float4*)(pemb + (long)s * Dc + c);
    e.x += p.x; e.y += p.y; e.z += p.z; e.w += p.w;
    *(float4*)(x + (long)r * Dc + c) = e;
}

// ---------------- layernorm -> bf16 hi/lo planes ----------------
__global__ void ln_k(const float* __restrict__ x, const float* __restrict__ g,
                     const float* __restrict__ b, bf16* __restrict__ hi,
                     bf16* __restrict__ lo)
{
    const int row = blockIdx.x;
    const int tid = threadIdx.x;
    const float* xr = x + (long)row * Dc;
    float4 v = *(const float4*)(xr + tid * 4);
    float s = v.x + v.y + v.z + v.w;
    float tot = block_sum(s);
    float m = tot * (1.f / Dc);
    float dx0 = v.x - m, dx1 = v.y - m, dx2 = v.z - m, dx3 = v.w - m;
    float q = dx0 * dx0 + dx1 * dx1 + dx2 * dx2 + dx3 * dx3;
    float totq = block_sum(q);
    float rs = rsqrtf(totq * (1.f / Dc) + 1e-5f);
    float4 gg = *(const float4*)(g + tid * 4);
    float4 bb = *(const float4*)(b + tid * 4);
    float o0 = dx0 * rs * gg.x + bb.x;
    float o1 = dx1 * rs * gg.y + bb.y;
    float o2 = dx2 * rs * gg.z + bb.z;
    float o3 = dx3 * rs * gg.w + bb.w;
    uint32_t h0, l0, h1, l1;
    split2(o0, o1, h0, l0);
    split2(o2, o3, h1, l1);
    *(uint2*)(hi + (long)row * Dc + tid * 4) = make_uint2(h0, h1);
    *(uint2*)(lo + (long)row * Dc + tid * 4) = make_uint2(l0, l1);
}

// ---------------- self-attn softmax (causal; W==S) -> bf16 P planes ----------------
__global__ void smax_sa(const float* __restrict__ sc, bf16* __restrict__ ph,
                        bf16* __restrict__ pl)
{
    const int i = blockIdx.x;
    const int z = blockIdx.y;
    const float* row = sc + ((long)z * Sc + i) * Sc;
    const int tid = threadIdx.x;     // 256
    const int j0 = tid * 4;
    float v[4] = {-1e30f, -1e30f, -1e30f, -1e30f};
    if (j0 <= i) {
        float4 v4 = *(const float4*)(row + j0);
        v[0] = v4.x; v[1] = v4.y; v[2] = v4.z; v[3] = v4.w;
    }
    float mx = -1e30f;
    #pragma unroll
    for (int e = 0; e < 4; e++) {
        if (j0 + e > i) v[e] = -1e30f;
        mx = fmaxf(mx, v[e]);
    }
    mx = block_max(mx);
    float s = 0.f;
    #pragma unroll
    for (int e = 0; e < 4; e++) {
        v[e] = (j0 + e <= i) ? expf(v[e] - mx) : 0.f;
        s += v[e];
    }
    s = block_sum(s);
    float inv = 1.f / s;
    uint32_t h0, l0, h1, l1;
    split2(v[0] * inv, v[1] * inv, h0, l0);
    split2(v[2] * inv, v[3] * inv, h1, l1);
    long base = ((long)z * Sc + i) * Sc + j0;
    *(uint2*)(ph + base) = make_uint2(h0, h1);
    *(uint2*)(pl + base) = make_uint2(l0, l1);
}

// ---------------- cross-attn softmax -> bf16 P planes ----------------
__global__ void smax_ca(const float* __restrict__ sc, const int* __restrict__ pidx,
                        bf16* __restrict__ ph, bf16* __restrict__ pl)
{
    const int i = blockIdx.x;
    const int z = blockIdx.y;
    const int b = z / Hc;
    const float* row = sc + ((long)z * Sc + i) * Pc;
    const int tid = threadIdx.x;     // 64
    const int j0 = tid * 2;
    const int lim = pidx[b * Sc + i];
    float2 v2 = *(const float2*)(row + j0);
    float v0 = (j0 <= lim)     ? v2.x : -1e30f;
    float v1 = (j0 + 1 <= lim) ? v2.y : -1e30f;
    float mx = block_max(fmaxf(v0, v1));
    v0 = (j0 <= lim)     ? expf(v0 - mx) : 0.f;
    v1 = (j0 + 1 <= lim) ? expf(v1 - mx) : 0.f;
    float s = block_sum(v0 + v1);
    float inv = 1.f / s;
    uint32_t h, l;
    split2(v0 * inv, v1 * inv, h, l);
    long base = ((long)z * Sc + i) * Pc + j0;
    *(uint32_t*)(ph + base) = h;
    *(uint32_t*)(pl + base) = l;
}

// ---------------- inclusive cumsum ----------------
__global__ void cumsum_k(const int* __restrict__ bd, int* __restrict__ pidx)
{
    __shared__ int s[Sc];
    const int b = blockIdx.x, t = threadIdx.x;
    s[t] = bd[b * Sc + t];
    __syncthreads();
    for (int off = 1; off < Sc; off <<= 1) {
        int v = (t >= off) ? s[t - off] : 0;
        __syncthreads();
        s[t] += v;
        __syncthreads();
    }
    pidx[b * Sc + t] = s[t];
}

// ---------------- launcher ----------------
extern "C" void kernel_launch(void* const* d_in, const int* in_sizes, int n_in,
                              void* d_out, int out_size)
{
    const int*   byte_seq  = (const int*)  d_in[0];
    const float* patch_rep = (const float*)d_in[1];
    const int*   patch_bd  = (const int*)  d_in[2];
    const float* byte_emb  = (const float*)d_in[3];
    const float* pos_emb   = (const float*)d_in[4];
    const float* sa_in_w   = (const float*)d_in[5];
    const float* sa_in_b   = (const float*)d_in[6];
    const float* sa_out_w  = (const float*)d_in[7];
    const float* sa_out_b  = (const float*)d_in[8];
    const float* ca_in_w   = (const float*)d_in[9];
    const float* ca_in_b   = (const float*)d_in[10];
    const float* ca_out_w  = (const float*)d_in[11];
    const float* ca_out_b  = (const float*)d_in[12];
    const float* ffn_w1    = (const float*)d_in[13];
    const float* ffn_b1    = (const float*)d_in[14];
    const float* ffn_w2    = (const float*)d_in[15];
    const float* ffn_b2    = (const float*)d_in[16];
    const float* ln_g      = (const float*)d_in[17];
    const float* ln_b      = (const float*)d_in[18];
    const float* norm_g    = (const float*)d_in[19];
    const float* norm_b    = (const float*)d_in[20];
    const float* out_w     = (const float*)d_in[21];
    float* out = (float*)d_out;

    float *gx, *gsc;
    int* gpidx;
    bf16 *whi, *wlo, *hh, *hl, *qh, *ql, *cqh, *cql, *ckh, *ckl, *fh, *fl, *prh, *prl, *sph, *spl;
    cudaGetSymbolAddress((void**)&gx,   g_x);
    cudaGetSymbolAddress((void**)&gsc,  g_sc);
    cudaGetSymbolAddress((void**)&gpidx, g_pidx);
    cudaGetSymbolAddress((void**)&whi, g_whi);
    cudaGetSymbolAddress((void**)&wlo, g_wlo);
    cudaGetSymbolAddress((void**)&hh,  g_hh);
    cudaGetSymbolAddress((void**)&hl,  g_hl);
    cudaGetSymbolAddress((void**)&qh,  g_qh);
    cudaGetSymbolAddress((void**)&ql,  g_ql);
    cudaGetSymbolAddress((void**)&cqh, g_cqh);
    cudaGetSymbolAddress((void**)&cql, g_cql);
    cudaGetSymbolAddress((void**)&ckh, g_ckh);
    cudaGetSymbolAddress((void**)&ckl, g_ckl);
    cudaGetSymbolAddress((void**)&fh,  g_fh);
    cudaGetSymbolAddress((void**)&fl,  g_fl);
    cudaGetSymbolAddress((void**)&prh, g_prh);
    cudaGetSymbolAddress((void**)&prl, g_prl);
    cudaGetSymbolAddress((void**)&sph, g_sph);
    cudaGetSymbolAddress((void**)&spl, g_spl);

    cudaFuncSetAttribute(gemm_tc<0, false>, cudaFuncAttributeMaxDynamicSharedMemorySize, TCS);
    cudaFuncSetAttribute(gemm_tc<1, true>,  cudaFuncAttributeMaxDynamicSharedMemorySize, TCS);
    cudaFuncSetAttribute(gemm_tc<2, true>,  cudaFuncAttributeMaxDynamicSharedMemorySize, TCS);
    cudaFuncSetAttribute(gemm_tc<3, false>, cudaFuncAttributeMaxDynamicSharedMemorySize, TCS);
    cudaFuncSetAttribute(gemm_pv<true>,  cudaFuncAttributeMaxDynamicSharedMemorySize, PVS);
    cudaFuncSetAttribute(gemm_pv<false>, cudaFuncAttributeMaxDynamicSharedMemorySize, PVS);

    auto cvt = [&](const float* src, bf16* dh, bf16* dl, long n) {
        cvt_k<<<(unsigned)((n / 4 + 255) / 256), 256>>>(src, dh, dl, n);
    };
    cvt(sa_in_w,  whi + OFF_SAIN,  wlo + OFF_SAIN,  (long)Lc * 3 * Dc * Dc);
    cvt(sa_out_w, whi + OFF_SAOUT, wlo + OFF_SAOUT, (long)Lc * Dc * Dc);
    cvt(ca_in_w,  whi + OFF_CAIN,  wlo + OFF_CAIN,  (long)Lc * 3 * Dc * Dc);
    cvt(ca_out_w, whi + OFF_CAOUT, wlo + OFF_CAOUT, (long)Lc * Dc * Dc);
    cvt(ffn_w1,   whi + OFF_FFN1,  wlo + OFF_FFN1,  (long)Lc * 4 * Dc * Dc);
    cvt(ffn_w2,   whi + OFF_FFN2,  wlo + OFF_FFN2,  (long)Lc * 4 * Dc * Dc);
    cvt(out_w,    whi + OFF_OUTW,  wlo + OFF_OUTW,  (long)Vc * Dc);
    cvt(patch_rep, prh, prl, (long)Bc * Pc * Dc);

    embed_k<<<BS, 256>>>(byte_seq, byte_emb, pos_emb, gx);
    cumsum_k<<<Bc, Sc>>>(patch_bd, gpidx);

    for (int l = 0; l < Lc; l++) {
        // ===== self-attention =====
        ln_k<<<BS, 256>>>(gx, ln_g + (long)(l * 3 + 0) * Dc, ln_b + (long)(l * 3 + 0) * Dc, hh, hl);

        // QKV -> bf16 planes only
        gemm_tc<1, true><<<dim3(3 * Dc / 128, BS / 128), 128, TCS>>>(
            hh, hl, Dc, 0, 0, 1,
            whi + OFF_SAIN + (long)l * 3 * Dc * Dc, wlo + OFF_SAIN + (long)l * 3 * Dc * Dc, Dc, 0, 0, 1,
            sa_in_b + (long)l * 3 * Dc, nullptr,
            nullptr, qh, ql, 3 * Dc, 0, 0, 1, Dc, 1.f, 0);

        // scores (triangular skip)
        gemm_tc<0, false><<<dim3(Sc / 128, Sc / 128, Bc * Hc), 128, TCS>>>(
            qh,      ql,      3 * Dc, (long)Sc * 3 * Dc, DH, Hc,
            qh + Dc, ql + Dc, 3 * Dc, (long)Sc * 3 * Dc, DH, Hc,
            nullptr, nullptr,
            gsc, nullptr, nullptr, Sc, (long)Sc * Sc, 0, 1,
            DH, 0.125f, 1);

        smax_sa<<<dim3(Sc, Bc * Hc), 256>>>(gsc, sph, spl);

        // P @ V (tensor, triangular K-cap) -> attn-out planes
        gemm_pv<true><<<dim3(1, Sc / 128, Bc * Hc), 128, PVS>>>(
            sph, spl, Sc, (long)Sc * Sc,
            qh + 2 * Dc, ql + 2 * Dc, 3 * Dc, (long)Sc * 3 * Dc, DH, Hc,
            cqh, cql, Dc, (long)Sc * Dc, DH, Hc, Sc);

        // out proj + residual
        gemm_tc<3, false><<<dim3(Dc / 128, BS / 128), 128, TCS>>>(
            cqh, cql, Dc, 0, 0, 1,
            whi + OFF_SAOUT + (long)l * Dc * Dc, wlo + OFF_SAOUT + (long)l * Dc * Dc, Dc, 0, 0, 1,
            sa_out_b + (long)l * Dc, gx,
            gx, nullptr, nullptr, Dc, 0, 0, 1, Dc, 1.f, 0);

        // ===== cross-attention =====
        ln_k<<<BS, 256>>>(gx, ln_g + (long)(l * 3 + 1) * Dc, ln_b + (long)(l * 3 + 1) * Dc, hh, hl);

        gemm_tc<1, true><<<dim3(Dc / 128, BS / 128), 128, TCS>>>(
            hh, hl, Dc, 0, 0, 1,
            whi + OFF_CAIN + (long)l * 3 * Dc * Dc, wlo + OFF_CAIN + (long)l * 3 * Dc * Dc, Dc, 0, 0, 1,
            ca_in_b + (long)l * 3 * Dc, nullptr,
            nullptr, cqh, cql, Dc, 0, 0, 1, Dc, 1.f, 0);

        gemm_tc<1, true><<<dim3(2 * Dc / 128, (Bc * Pc) / 128), 128, TCS>>>(
            prh, prl, Dc, 0, 0, 1,
            whi + OFF_CAIN + (long)l * 3 * Dc * Dc + (long)Dc * Dc,
            wlo + OFF_CAIN + (long)l * 3 * Dc * Dc + (long)Dc * Dc, Dc, 0, 0, 1,
            ca_in_b + (long)l * 3 * Dc + Dc, nullptr,
            nullptr, ckh, ckl, 2 * Dc, 0, 0, 1, Dc, 1.f, 0);

        // CA scores
        gemm_tc<0, false><<<dim3(Pc / 128, Sc / 128, Bc * Hc), 128, TCS>>>(
            cqh, cql, Dc,     (long)Sc * Dc,     DH, Hc,
            ckh, ckl, 2 * Dc, (long)Pc * 2 * Dc, DH, Hc,
            nullptr, nullptr,
            gsc, nullptr, nullptr, Pc, (long)Sc * Pc, 0, 1,
            DH, 0.125f, 0);

        smax_ca<<<dim3(Sc, Bc * Hc), 64>>>(gsc, gpidx, sph, spl);

        gemm_pv<false><<<dim3(1, Sc / 128, Bc * Hc), 128, PVS>>>(
            sph, spl, Pc, (long)Sc * Pc,
            ckh + Dc, ckl + Dc, 2 * Dc, (long)Pc * 2 * Dc, DH, Hc,
            cqh, cql, Dc, (long)Sc * Dc, DH, Hc, Pc);

        gemm_tc<3, false><<<dim3(Dc / 128, BS / 128), 128, TCS>>>(
            cqh, cql, Dc, 0, 0, 1,
            whi + OFF_CAOUT + (long)l * Dc * Dc, wlo + OFF_CAOUT + (long)l * Dc * Dc, Dc, 0, 0, 1,
            ca_out_b + (long)l * Dc, gx,
            gx, nullptr, nullptr, Dc, 0, 0, 1, Dc, 1.f, 0);

        // ===== FFN =====
        ln_k<<<BS, 256>>>(gx, ln_g + (long)(l * 3 + 2) * Dc, ln_b + (long)(l * 3 + 2) * Dc, hh, hl);

        gemm_tc<2, true><<<dim3(4 * Dc / 128, BS / 128), 128, TCS>>>(
            hh, hl, Dc, 0, 0, 1,
            whi + OFF_FFN1 + (long)l * 4 * Dc * Dc, wlo + OFF_FFN1 + (long)l * 4 * Dc * Dc, Dc, 0, 0, 1,
            ffn_b1 + (long)l * 4 * Dc, nullptr,
            nullptr, fh, fl, 4 * Dc, 0, 0, 1, Dc, 1.f, 0);

        gemm_tc<3, false><<<dim3(Dc / 128, BS / 128), 128, TCS>>>(
            fh, fl, 4 * Dc, 0, 0, 1,
            whi + OFF_FFN2 + (long)l * Dc * 4 * Dc, wlo + OFF_FFN2 + (long)l * Dc * 4 * Dc, 4 * Dc, 0, 0, 1,
            ffn_b2 + (long)l * Dc, gx,
            gx, nullptr, nullptr, Dc, 0, 0, 1, 4 * Dc, 1.f, 0);
    }

    // final LN + vocab projection
    ln_k<<<BS, 256>>>(gx, norm_g, norm_b, hh, hl);
    gemm_tc<0, false><<<dim3(Vc / 128, BS / 128), 128, TCS>>>(
        hh, hl, Dc, 0, 0, 1,
        whi + OFF_OUTW, wlo + OFF_OUTW, Dc, 0, 0, 1,
        nullptr, nullptr,
        out, nullptr, nullptr, Vc, 0, 0, 1, Dc, 1.f, 0);
}

// round 11
// speedup vs baseline: 1.7412x; 1.0314x over previous
#include <cuda_runtime.h>
#include <cuda_bf16.h>
#include <math.h>
#include <cstdint>

// ---------------- problem constants ----------------
constexpr int Bc = 2, Sc = 1024, Dc = 1024, Hc = 16, Lc = 9, Wc = 1024, Pc = 128, Vc = 256;
constexpr int DH = Dc / Hc;          // 64
constexpr int BS = Bc * Sc;          // 2048 rows

typedef unsigned long long ull;
typedef __nv_bfloat16 bf16;

// ---------------- device scratch ----------------
__device__ float g_x [BS * Dc];                       // residual stream (fp32)
__device__ float g_sc[(long)Bc * Hc * Sc * Sc];       // pre-softmax scores (fp32)
__device__ int   g_pidx[BS];

// weights mega-buffer offsets (elements)
constexpr long OFF_SAIN  = 0;
constexpr long OFF_SAOUT = OFF_SAIN  + (long)Lc * 3 * Dc * Dc;
constexpr long OFF_CAIN  = OFF_SAOUT + (long)Lc * Dc * Dc;
constexpr long OFF_CAOUT = OFF_CAIN  + (long)Lc * 3 * Dc * Dc;
constexpr long OFF_FFN1  = OFF_CAOUT + (long)Lc * Dc * Dc;
constexpr long OFF_FFN2  = OFF_FFN1  + (long)Lc * 4 * Dc * Dc;
constexpr long OFF_OUTW  = OFF_FFN2  + (long)Lc * 4 * Dc * Dc;
constexpr long W_TOTAL   = OFF_OUTW  + (long)Vc * Dc;

__device__ bf16 g_whi[W_TOTAL];
__device__ bf16 g_wlo[W_TOTAL];

__device__ bf16 g_hh [BS * Dc],          g_hl [BS * Dc];
__device__ bf16 g_qh [BS * 3 * Dc],      g_ql [BS * 3 * Dc];
__device__ bf16 g_cqh[BS * Dc],          g_cql[BS * Dc];
__device__ bf16 g_ckh[Bc * Pc * 2 * Dc], g_ckl[Bc * Pc * 2 * Dc];
__device__ bf16 g_fh [BS * 4 * Dc],      g_fl [BS * 4 * Dc];
__device__ bf16 g_prh[Bc * Pc * Dc],     g_prl[Bc * Pc * Dc];
__device__ bf16 g_sph[(long)Bc * Hc * Sc * Sc];
__device__ bf16 g_spl[(long)Bc * Hc * Sc * Sc];

// ---------------- reductions ----------------
__device__ __forceinline__ float block_sum(float v) {
    __shared__ float sh[32];
    int lane = threadIdx.x & 31, w = threadIdx.x >> 5;
    int nw = blockDim.x >> 5;
    #pragma unroll
    for (int o = 16; o; o >>= 1) v += __shfl_xor_sync(0xffffffffu, v, o);
    __syncthreads();
    if (lane == 0) sh[w] = v;
    __syncthreads();
    if (threadIdx.x == 0) {
        float t = 0.f;
        for (int i = 0; i < nw; i++) t += sh[i];
        sh[0] = t;
    }
    __syncthreads();
    return sh[0];
}

__device__ __forceinline__ float block_max(float v) {
    __shared__ float sh[32];
    int lane = threadIdx.x & 31, w = threadIdx.x >> 5;
    int nw = blockDim.x >> 5;
    #pragma unroll
    for (int o = 16; o; o >>= 1) v = fmaxf(v, __shfl_xor_sync(0xffffffffu, v, o));
    __syncthreads();
    if (lane == 0) sh[w] = v;
    __syncthreads();
    if (threadIdx.x == 0) {
        float t = -1e30f;
        for (int i = 0; i < nw; i++) t = fmaxf(t, sh[i]);
        sh[0] = t;
    }
    __syncthreads();
    return sh[0];
}

// ================= helpers =================
__device__ __forceinline__ uint32_t s2u(const void* p) {
    return (uint32_t)__cvta_generic_to_shared(p);
}
__device__ __forceinline__ void cp16(uint32_t dst, const void* src) {
    asm volatile("cp.async.cg.shared.global [%0], [%1], 16;" :: "r"(dst), "l"(src));
}

#define LDSM4(R, addr) \
    asm volatile("ldmatrix.sync.aligned.m8n8.x4.shared.b16 {%0,%1,%2,%3}, [%4];" \
        : "=r"((R)[0]), "=r"((R)[1]), "=r"((R)[2]), "=r"((R)[3]) : "r"(addr))

#define LDSM4T(R, addr) \
    asm volatile("ldmatrix.sync.aligned.m8n8.x4.trans.shared.b16 {%0,%1,%2,%3}, [%4];" \
        : "=r"((R)[0]), "=r"((R)[1]), "=r"((R)[2]), "=r"((R)[3]) : "r"(addr))

#define MMA16816(d, a, b0, b1) \
    asm volatile("mma.sync.aligned.m16n8k16.row.col.f32.bf16.bf16.f32 " \
        "{%0,%1,%2,%3}, {%4,%5,%6,%7}, {%8,%9}, {%0,%1,%2,%3};" \
        : "+f"((d)[0]), "+f"((d)[1]), "+f"((d)[2]), "+f"((d)[3]) \
        : "r"((a)[0]), "r"((a)[1]), "r"((a)[2]), "r"((a)[3]), "r"(b0), "r"(b1))

__device__ __forceinline__ void split2(float x0, float x1, uint32_t& h, uint32_t& l) {
    __nv_bfloat162 hh = __floats2bfloat162_rn(x0, x1);
    float2 hf = __bfloat1622float2(hh);
    __nv_bfloat162 ll = __floats2bfloat162_rn(x0 - hf.x, x1 - hf.y);
    h = *(uint32_t*)&hh; l = *(uint32_t*)&ll;
}

// ================= pipelined bf16x3 mma.sync GEMM (A @ B^T) =================
// BM = 128 (warp tile 64x64) or 64 (warp tile 32x64). BN fixed 128, BK=32.
constexpr int RS = 40;
constexpr int tcs_bytes(int BM) { return 2 * (2 * BM + 2 * 128) * RS * 2; }  // 81920 / 61440

template<int EPI, bool OUTBF, int BM>
__global__ __launch_bounds__(128, (BM == 64 ? 3 : 2))
void gemm_tc(const bf16* __restrict__ Ah, const bf16* __restrict__ Al, int lda, long hiA, long loA, int nloA,
             const bf16* __restrict__ Bh, const bf16* __restrict__ Bl, int ldb, long hiB, long loB, int nloB,
             const float* __restrict__ bias, const float* __restrict__ Res,
             float* __restrict__ C, bf16* __restrict__ Chi, bf16* __restrict__ Clo,
             int ldc, long hiC, long loC, int nloC, int K, float scale, int tri)
{
    extern __shared__ __align__(16) bf16 sbuf[];

    constexpr int MT = BM / 32;              // per-warp 16-row tiles (4 or 2)
    constexpr int TPR = 128 / BM;            // threads per A row (1 or 2)
    constexpr int QA = BM / 32;              // 16B transfers per A plane per thread
    constexpr int STAGE_E = (2 * BM + 2 * 128) * RS;

    const int m0 = blockIdx.y * BM, n0 = blockIdx.x * 128;
    if (tri && n0 > m0 + BM - 1) return;

    const int tid = threadIdx.x, lane = tid & 31, wid = tid >> 5;
    const int wm = wid >> 1, wn = wid & 1;
    const int z = blockIdx.z;
    Ah += (long)(z / nloA) * hiA + (long)(z % nloA) * loA;
    Al += (long)(z / nloA) * hiA + (long)(z % nloA) * loA;
    Bh += (long)(z / nloB) * hiB + (long)(z % nloB) * loB;
    Bl += (long)(z / nloB) * hiB + (long)(z % nloB) * loB;
    const long coff = (long)(z / nloC) * hiC + (long)(z % nloC) * loC;

    const uint32_t sbase = s2u(sbuf);

    const int arow = tid / TPR;
    const int akoff = (tid % TPR) * 16;      // elements
    const bf16* pAh = Ah + (size_t)(m0 + arow) * lda + akoff;
    const bf16* pAl = Al + (size_t)(m0 + arow) * lda + akoff;
    const bf16* pBh = Bh + (size_t)(n0 + tid) * ldb;
    const bf16* pBl = Bl + (size_t)(n0 + tid) * ldb;

    float acc[MT][8][4];
    #pragma unroll
    for (int i = 0; i < MT; i++)
        #pragma unroll
        for (int j = 0; j < 8; j++)
            #pragma unroll
            for (int q = 0; q < 4; q++) acc[i][j][q] = 0.f;

    const int nk = K / 32;

    auto issue = [&](int c) {
        uint32_t base = sbase + (uint32_t)(c & 1) * (STAGE_E * 2);
        // A planes
        {
            uint32_t dst = base + (uint32_t)(arow * RS + akoff) * 2;
            const bf16* sa = pAh + c * 32;
            const bf16* sl = pAl + c * 32;
            #pragma unroll
            for (int q = 0; q < QA; q++) {
                cp16(dst + q * 16, sa + q * 8);
                cp16(dst + BM * RS * 2 + q * 16, sl + q * 8);
            }
        }
        // B planes (128 rows, one per thread)
        {
            uint32_t dst = base + (uint32_t)(2 * BM * RS + tid * RS) * 2;
            const bf16* sb = pBh + c * 32;
            const bf16* sl = pBl + c * 32;
            #pragma unroll
            for (int q = 0; q < 4; q++) {
                cp16(dst + q * 16, sb + q * 8);
                cp16(dst + 128 * RS * 2 + q * 16, sl + q * 8);
            }
        }
        asm volatile("cp.async.commit_group;");
    };

    issue(0);

    const int lrow = lane & 15, lko = (lane >> 4) * 8;

    for (int k0 = 0; k0 < nk; k0++) {
        asm volatile("cp.async.wait_group 0;");
        __syncthreads();
        if (k0 + 1 < nk) issue(k0 + 1);

        const bf16* bAh = sbuf + (size_t)(k0 & 1) * STAGE_E;
        const bf16* bAl = bAh + BM * RS;
        const bf16* bBh = bAh + 2 * BM * RS;
        const bf16* bBl = bBh + 128 * RS;

        #pragma unroll
        for (int kk = 0; kk < 32; kk += 16) {
            uint32_t Afh[MT][4], Afl[MT][4];
            #pragma unroll
            for (int mt = 0; mt < MT; mt++)
                LDSM4(Afh[mt], s2u(&bAh[(wm * (BM / 2) + mt * 16 + lrow) * RS + kk + lko]));
            #pragma unroll
            for (int mt = 0; mt < MT; mt++)
                LDSM4(Afl[mt], s2u(&bAl[(wm * (BM / 2) + mt * 16 + lrow) * RS + kk + lko]));

            #pragma unroll
            for (int p = 0; p < 4; p++) {
                uint32_t Bfh[4], Bfl[4];
                LDSM4(Bfh, s2u(&bBh[(wn * 64 + p * 16 + lrow) * RS + kk + lko]));
                LDSM4(Bfl, s2u(&bBl[(wn * 64 + p * 16 + lrow) * RS + kk + lko]));
                #pragma unroll
                for (int mt = 0; mt < MT; mt++) {
                    MMA16816(acc[mt][2 * p + 0], Afh[mt], Bfh[0], Bfh[2]);
                    MMA16816(acc[mt][2 * p + 1], Afh[mt], Bfh[1], Bfh[3]);
                    MMA16816(acc[mt][2 * p + 0], Afh[mt], Bfl[0], Bfl[2]);
                    MMA16816(acc[mt][2 * p + 1], Afh[mt], Bfl[1], Bfl[3]);
                    MMA16816(acc[mt][2 * p + 0], Afl[mt], Bfh[0], Bfh[2]);
                    MMA16816(acc[mt][2 * p + 1], Afl[mt], Bfh[1], Bfh[3]);
                }
            }
        }
    }

    // ---- epilogue
    float* Cb = C ? (C + coff) : nullptr;
    const float* Rb = (EPI == 3) ? (Res + coff) : nullptr;
    bf16* Hb = OUTBF ? (Chi + coff) : nullptr;
    bf16* Lb = OUTBF ? (Clo + coff) : nullptr;
    const int rb = lane >> 2, cbl = (lane & 3) * 2;
    #pragma unroll
    for (int mt = 0; mt < MT; mt++) {
        #pragma unroll
        for (int half = 0; half < 2; half++) {
            int r = m0 + wm * (BM / 2) + mt * 16 + rb + half * 8;
            #pragma unroll
            for (int j = 0; j < 8; j++) {
                int cc = n0 + wn * 64 + (j >> 1) * 16 + (j & 1) * 8 + cbl;
                float x0 = acc[mt][j][half * 2 + 0] * scale;
                float x1 = acc[mt][j][half * 2 + 1] * scale;
                if (EPI >= 1) { x0 += bias[cc]; x1 += bias[cc + 1]; }
                if (EPI == 2) {
                    x0 = 0.5f * x0 * (1.f + erff(x0 * 0.70710678118654752f));
                    x1 = 0.5f * x1 * (1.f + erff(x1 * 0.70710678118654752f));
                }
                if (EPI == 3) {
                    float2 rv = *(const float2*)(Rb + (size_t)r * ldc + cc);
                    x0 += rv.x; x1 += rv.y;
                }
                if (Cb) *(float2*)(Cb + (size_t)r * ldc + cc) = make_float2(x0, x1);
                if (OUTBF) {
                    uint32_t h, l;
                    split2(x0, x1, h, l);
                    *(uint32_t*)(Hb + (size_t)r * ldc + cc) = h;
                    *(uint32_t*)(Lb + (size_t)r * ldc + cc) = l;
                }
            }
        }
    }
}

// ================= P @ V tensor GEMM (B non-transposed, trans-ldmatrix) =================
constexpr int RSN = 72;
constexpr int PV_BUFE = 2 * 128 * RS + 2 * 32 * RSN;
constexpr int PVS = 2 * PV_BUFE * 2;

template<bool TRI>
__global__ __launch_bounds__(128, 2)
void gemm_pv(const bf16* __restrict__ Ph, const bf16* __restrict__ Pl, int lda, long strideAz,
             const bf16* __restrict__ Vh, const bf16* __restrict__ Vl, int ldb, long hiB, long loB, int nloB,
             bf16* __restrict__ Chi, bf16* __restrict__ Clo, int ldc, long hiC, long loC, int nloC,
             int K)
{
    extern __shared__ __align__(16) bf16 sbuf[];

    const int tid = threadIdx.x, lane = tid & 31, wid = tid >> 5;
    const int wm = wid >> 1, wn = wid & 1;
    const int z = blockIdx.z;
    const int m0 = blockIdx.y * 128;

    Ph += (long)z * strideAz;
    Pl += (long)z * strideAz;
    Vh += (long)(z / nloB) * hiB + (long)(z % nloB) * loB;
    Vl += (long)(z / nloB) * hiB + (long)(z % nloB) * loB;
    const long coff = (long)(z / nloC) * hiC + (long)(z % nloC) * loC;

    const uint32_t sbase = s2u(sbuf);
    const bf16* pAh = Ph + (size_t)(m0 + tid) * lda;
    const bf16* pAl = Pl + (size_t)(m0 + tid) * lda;
    const int vr = tid >> 2, vsub = tid & 3;
    const int vplane = vsub >> 1, vhalf = vsub & 1;
    const bf16* pV = (vplane ? Vl : Vh);

    float acc[4][4][4];
    #pragma unroll
    for (int i = 0; i < 4; i++)
        #pragma unroll
        for (int j = 0; j < 4; j++)
            #pragma unroll
            for (int q = 0; q < 4; q++) acc[i][j][q] = 0.f;

    const int nk = TRI ? (m0 / 32 + 4) : (K / 32);

    auto issue = [&](int c) {
        uint32_t base = sbase + (uint32_t)(c & 1) * (PV_BUFE * 2);
        {
            uint32_t dA = base + (uint32_t)tid * (RS * 2);
            const bf16* sa = pAh + c * 32;
            const bf16* sl = pAl + c * 32;
            #pragma unroll
            for (int q = 0; q < 4; q++) {
                cp16(dA + q * 16, sa + q * 8);
                cp16(dA + 128 * RS * 2 + q * 16, sl + q * 8);
            }
        }
        {
            uint32_t dV = base + (uint32_t)(2 * 128 * RS + vplane * 32 * RSN + vr * RSN + vhalf * 32) * 2;
            const bf16* sv = pV + (size_t)(c * 32 + vr) * ldb + vhalf * 32;
            #pragma unroll
            for (int q = 0; q < 4; q++)
                cp16(dV + q * 16, sv + q * 8);
        }
        asm volatile("cp.async.commit_group;");
    };

    issue(0);

    const int lrow = lane & 15, lko = (lane >> 4) * 8;
    const int tkrow = (lane & 7) + ((lane >> 4) << 3);
    const int tncol = ((lane >> 3) & 1) * 8;

    for (int k0 = 0; k0 < nk; k0++) {
        asm volatile("cp.async.wait_group 0;");
        __syncthreads();
        if (k0 + 1 < nk) issue(k0 + 1);

        const bf16* bAh = sbuf + (size_t)(k0 & 1) * PV_BUFE;
        const bf16* bAl = bAh + 128 * RS;
        const bf16* bVh = bAh + 2 * 128 * RS;
        const bf16* bVl = bVh + 32 * RSN;

        #pragma unroll
        for (int kk = 0; kk < 32; kk += 16) {
            uint32_t Afh[4][4], Afl[4][4];
            #pragma unroll
            for (int mt = 0; mt < 4; mt++)
                LDSM4(Afh[mt], s2u(&bAh[(wm * 64 + mt * 16 + lrow) * RS + kk + lko]));
            #pragma unroll
            for (int mt = 0; mt < 4; mt++)
                LDSM4(Afl[mt], s2u(&bAl[(wm * 64 + mt * 16 + lrow) * RS + kk + lko]));

            #pragma unroll
            for (int p = 0; p < 2; p++) {
                uint32_t Bfh[4], Bfl[4];
                LDSM4T(Bfh, s2u(&bVh[(kk + tkrow) * RSN + wn * 32 + p * 16 + tncol]));
                LDSM4T(Bfl, s2u(&bVl[(kk + tkrow) * RSN + wn * 32 + p * 16 + tncol]));
                #pragma unroll
                for (int mt = 0; mt < 4; mt++) {
                    MMA16816(acc[mt][2 * p + 0], Afh[mt], Bfh[0], Bfh[2]);
                    MMA16816(acc[mt][2 * p + 1], Afh[mt], Bfh[1], Bfh[3]);
                    MMA16816(acc[mt][2 * p + 0], Afh[mt], Bfl[0], Bfl[2]);
                    MMA16816(acc[mt][2 * p + 1], Afh[mt], Bfl[1], Bfl[3]);
                    MMA16816(acc[mt][2 * p + 0], Afl[mt], Bfh[0], Bfh[2]);
                    MMA16816(acc[mt][2 * p + 1], Afl[mt], Bfh[1], Bfh[3]);
                }
            }
        }
    }

    bf16* Hb = Chi + coff;
    bf16* Lb = Clo + coff;
    const int rb = lane >> 2, cbl = (lane & 3) * 2;
    #pragma unroll
    for (int mt = 0; mt < 4; mt++) {
        #pragma unroll
        for (int half = 0; half < 2; half++) {
            int r = m0 + wm * 64 + mt * 16 + rb + half * 8;
            #pragma unroll
            for (int j = 0; j < 4; j++) {
                int cc = wn * 32 + (j >> 1) * 16 + (j & 1) * 8 + cbl;
                float x0 = acc[mt][j][half * 2 + 0];
                float x1 = acc[mt][j][half * 2 + 1];
                uint32_t h, l;
                split2(x0, x1, h, l);
                *(uint32_t*)(Hb + (size_t)r * ldc + cc) = h;
                *(uint32_t*)(Lb + (size_t)r * ldc + cc) = l;
            }
        }
    }
}

// ---------------- fp32 -> bf16 hi/lo conversion ----------------
__global__ void cvt_k(const float* __restrict__ x, bf16* __restrict__ hi,
                      bf16* __restrict__ lo, long n)
{
    long i = ((long)blockIdx.x * blockDim.x + threadIdx.x) * 4;
    if (i >= n) return;
    float4 v = *(const float4*)(x + i);
    uint32_t h0, l0, h1, l1;
    split2(v.x, v.y, h0, l0);
    split2(v.z, v.w, h1, l1);
    *(uint2*)(hi + i) = make_uint2(h0, h1);
    *(uint2*)(lo + i) = make_uint2(l0, l1);
}

// ---------------- embedding ----------------
__global__ void embed_k(const int* __restrict__ seq, const float* __restrict__ bemb,
                        const float* __restrict__ pemb, float* __restrict__ x)
{
    int r = blockIdx.x;
    int s = r % Sc;
    int tok = seq[r];
    int c = threadIdx.x * 4;
    float4 e = *(const float4*)(bemb + (long)tok * Dc + c);
    float4 p = *(const float4*)(pemb + (long)s * Dc + c);
    e.x += p.x; e.y += p.y; e.z += p.z; e.w += p.w;
    *(float4*)(x + (long)r * Dc + c) = e;
}

// ---------------- layernorm -> bf16 hi/lo planes ----------------
__global__ void ln_k(const float* __restrict__ x, const float* __restrict__ g,
                     const float* __restrict__ b, bf16* __restrict__ hi,
                     bf16* __restrict__ lo)
{
    const int row = blockIdx.x;
    const int tid = threadIdx.x;
    const float* xr = x + (long)row * Dc;
    float4 v = *(const float4*)(xr + tid * 4);
    float s = v.x + v.y + v.z + v.w;
    float tot = block_sum(s);
    float m = tot * (1.f / Dc);
    float dx0 = v.x - m, dx1 = v.y - m, dx2 = v.z - m, dx3 = v.w - m;
    float q = dx0 * dx0 + dx1 * dx1 + dx2 * dx2 + dx3 * dx3;
    float totq = block_sum(q);
    float rs = rsqrtf(totq * (1.f / Dc) + 1e-5f);
    float4 gg = *(const float4*)(g + tid * 4);
    float4 bb = *(const float4*)(b + tid * 4);
    float o0 = dx0 * rs * gg.x + bb.x;
    float o1 = dx1 * rs * gg.y + bb.y;
    float o2 = dx2 * rs * gg.z + bb.z;
    float o3 = dx3 * rs * gg.w + bb.w;
    uint32_t h0, l0, h1, l1;
    split2(o0, o1, h0, l0);
    split2(o2, o3, h1, l1);
    *(uint2*)(hi + (long)row * Dc + tid * 4) = make_uint2(h0, h1);
    *(uint2*)(lo + (long)row * Dc + tid * 4) = make_uint2(l0, l1);
}

// ---------------- self-attn softmax (causal; W==S) -> bf16 P planes ----------------
__global__ void smax_sa(const float* __restrict__ sc, bf16* __restrict__ ph,
                        bf16* __restrict__ pl)
{
    const int i = blockIdx.x;
    const int z = blockIdx.y;
    const float* row = sc + ((long)z * Sc + i) * Sc;
    const int tid = threadIdx.x;     // 256
    const int j0 = tid * 4;
    float v[4] = {-1e30f, -1e30f, -1e30f, -1e30f};
    if (j0 <= i) {
        float4 v4 = *(const float4*)(row + j0);
        v[0] = v4.x; v[1] = v4.y; v[2] = v4.z; v[3] = v4.w;
    }
    float mx = -1e30f;
    #pragma unroll
    for (int e = 0; e < 4; e++) {
        if (j0 + e > i) v[e] = -1e30f;
        mx = fmaxf(mx, v[e]);
    }
    mx = block_max(mx);
    float s = 0.f;
    #pragma unroll
    for (int e = 0; e < 4; e++) {
        v[e] = (j0 + e <= i) ? expf(v[e] - mx) : 0.f;
        s += v[e];
    }
    s = block_sum(s);
    float inv = 1.f / s;
    uint32_t h0, l0, h1, l1;
    split2(v[0] * inv, v[1] * inv, h0, l0);
    split2(v[2] * inv, v[3] * inv, h1, l1);
    long base = ((long)z * Sc + i) * Sc + j0;
    *(uint2*)(ph + base) = make_uint2(h0, h1);
    *(uint2*)(pl + base) = make_uint2(l0, l1);
}

// ---------------- cross-attn softmax -> bf16 P planes ----------------
__global__ void smax_ca(const float* __restrict__ sc, const int* __restrict__ pidx,
                        bf16* __restrict__ ph, bf16* __restrict__ pl)
{
    const int i = blockIdx.x;
    const int z = blockIdx.y;
    const int b = z / Hc;
    const float* row = sc + ((long)z * Sc + i) * Pc;
    const int tid = threadIdx.x;     // 64
    const int j0 = tid * 2;
    const int lim = pidx[b * Sc + i];
    float2 v2 = *(const float2*)(row + j0);
    float v0 = (j0 <= lim)     ? v2.x : -1e30f;
    float v1 = (j0 + 1 <= lim) ? v2.y : -1e30f;
    float mx = block_max(fmaxf(v0, v1));
    v0 = (j0 <= lim)     ? expf(v0 - mx) : 0.f;
    v1 = (j0 + 1 <= lim) ? expf(v1 - mx) : 0.f;
    float s = block_sum(v0 + v1);
    float inv = 1.f / s;
    uint32_t h, l;
    split2(v0 * inv, v1 * inv, h, l);
    long base = ((long)z * Sc + i) * Pc + j0;
    *(uint32_t*)(ph + base) = h;
    *(uint32_t*)(pl + base) = l;
}

// ---------------- inclusive cumsum ----------------
__global__ void cumsum_k(const int* __restrict__ bd, int* __restrict__ pidx)
{
    __shared__ int s[Sc];
    const int b = blockIdx.x, t = threadIdx.x;
    s[t] = bd[b * Sc + t];
    __syncthreads();
    for (int off = 1; off < Sc; off <<= 1) {
        int v = (t >= off) ? s[t - off] : 0;
        __syncthreads();
        s[t] += v;
        __syncthreads();
    }
    pidx[b * Sc + t] = s[t];
}

// ---------------- launcher ----------------
extern "C" void kernel_launch(void* const* d_in, const int* in_sizes, int n_in,
                              void* d_out, int out_size)
{
    const int*   byte_seq  = (const int*)  d_in[0];
    const float* patch_rep = (const float*)d_in[1];
    const int*   patch_bd  = (const int*)  d_in[2];
    const float* byte_emb  = (const float*)d_in[3];
    const float* pos_emb   = (const float*)d_in[4];
    const float* sa_in_w   = (const float*)d_in[5];
    const float* sa_in_b   = (const float*)d_in[6];
    const float* sa_out_w  = (const float*)d_in[7];
    const float* sa_out_b  = (const float*)d_in[8];
    const float* ca_in_w   = (const float*)d_in[9];
    const float* ca_in_b   = (const float*)d_in[10];
    const float* ca_out_w  = (const float*)d_in[11];
    const float* ca_out_b  = (const float*)d_in[12];
    const float* ffn_w1    = (const float*)d_in[13];
    const float* ffn_b1    = (const float*)d_in[14];
    const float* ffn_w2    = (const float*)d_in[15];
    const float* ffn_b2    = (const float*)d_in[16];
    const float* ln_g      = (const float*)d_in[17];
    const float* ln_b      = (const float*)d_in[18];
    const float* norm_g    = (const float*)d_in[19];
    const float* norm_b    = (const float*)d_in[20];
    const float* out_w     = (const float*)d_in[21];
    float* out = (float*)d_out;

    float *gx, *gsc;
    int* gpidx;
    bf16 *whi, *wlo, *hh, *hl, *qh, *ql, *cqh, *cql, *ckh, *ckl, *fh, *fl, *prh, *prl, *sph, *spl;
    cudaGetSymbolAddress((void**)&gx,   g_x);
    cudaGetSymbolAddress((void**)&gsc,  g_sc);
    cudaGetSymbolAddress((void**)&gpidx, g_pidx);
    cudaGetSymbolAddress((void**)&whi, g_whi);
    cudaGetSymbolAddress((void**)&wlo, g_wlo);
    cudaGetSymbolAddress((void**)&hh,  g_hh);
    cudaGetSymbolAddress((void**)&hl,  g_hl);
    cudaGetSymbolAddress((void**)&qh,  g_qh);
    cudaGetSymbolAddress((void**)&ql,  g_ql);
    cudaGetSymbolAddress((void**)&cqh, g_cqh);
    cudaGetSymbolAddress((void**)&cql, g_cql);
    cudaGetSymbolAddress((void**)&ckh, g_ckh);
    cudaGetSymbolAddress((void**)&ckl, g_ckl);
    cudaGetSymbolAddress((void**)&fh,  g_fh);
    cudaGetSymbolAddress((void**)&fl,  g_fl);
    cudaGetSymbolAddress((void**)&prh, g_prh);
    cudaGetSymbolAddress((void**)&prl, g_prl);
    cudaGetSymbolAddress((void**)&sph, g_sph);
    cudaGetSymbolAddress((void**)&spl, g_spl);

    constexpr int T128 = tcs_bytes(128);   // 81920
    constexpr int T64  = tcs_bytes(64);    // 61440
    cudaFuncSetAttribute(gemm_tc<0, false, 128>, cudaFuncAttributeMaxDynamicSharedMemorySize, T128);
    cudaFuncSetAttribute(gemm_tc<1, true, 128>,  cudaFuncAttributeMaxDynamicSharedMemorySize, T128);
    cudaFuncSetAttribute(gemm_tc<2, true, 128>,  cudaFuncAttributeMaxDynamicSharedMemorySize, T128);
    cudaFuncSetAttribute(gemm_tc<0, false, 64>,  cudaFuncAttributeMaxDynamicSharedMemorySize, T64);
    cudaFuncSetAttribute(gemm_tc<1, true, 64>,   cudaFuncAttributeMaxDynamicSharedMemorySize, T64);
    cudaFuncSetAttribute(gemm_tc<3, false, 64>,  cudaFuncAttributeMaxDynamicSharedMemorySize, T64);
    cudaFuncSetAttribute(gemm_pv<true>,  cudaFuncAttributeMaxDynamicSharedMemorySize, PVS);
    cudaFuncSetAttribute(gemm_pv<false>, cudaFuncAttributeMaxDynamicSharedMemorySize, PVS);

    auto cvt = [&](const float* src, bf16* dh, bf16* dl, long n) {
        cvt_k<<<(unsigned)((n / 4 + 255) / 256), 256>>>(src, dh, dl, n);
    };
    cvt(sa_in_w,  whi + OFF_SAIN,  wlo + OFF_SAIN,  (long)Lc * 3 * Dc * Dc);
    cvt(sa_out_w, whi + OFF_SAOUT, wlo + OFF_SAOUT, (long)Lc * Dc * Dc);
    cvt(ca_in_w,  whi + OFF_CAIN,  wlo + OFF_CAIN,  (long)Lc * 3 * Dc * Dc);
    cvt(ca_out_w, whi + OFF_CAOUT, wlo + OFF_CAOUT, (long)Lc * Dc * Dc);
    cvt(ffn_w1,   whi + OFF_FFN1,  wlo + OFF_FFN1,  (long)Lc * 4 * Dc * Dc);
    cvt(ffn_w2,   whi + OFF_FFN2,  wlo + OFF_FFN2,  (long)Lc * 4 * Dc * Dc);
    cvt(out_w,    whi + OFF_OUTW,  wlo + OFF_OUTW,  (long)Vc * Dc);
    cvt(patch_rep, prh, prl, (long)Bc * Pc * Dc);

    embed_k<<<BS, 256>>>(byte_seq, byte_emb, pos_emb, gx);
    cumsum_k<<<Bc, Sc>>>(patch_bd, gpidx);

    for (int l = 0; l < Lc; l++) {
        // ===== self-attention =====
        ln_k<<<BS, 256>>>(gx, ln_g + (long)(l * 3 + 0) * Dc, ln_b + (long)(l * 3 + 0) * Dc, hh, hl);

        // QKV (fat: BM=128)
        gemm_tc<1, true, 128><<<dim3(3 * Dc / 128, BS / 128), 128, T128>>>(
            hh, hl, Dc, 0, 0, 1,
            whi + OFF_SAIN + (long)l * 3 * Dc * Dc, wlo + OFF_SAIN + (long)l * 3 * Dc * Dc, Dc, 0, 0, 1,
            sa_in_b + (long)l * 3 * Dc, nullptr,
            nullptr, qh, ql, 3 * Dc, 0, 0, 1, Dc, 1.f, 0);

        // scores (BM=128, triangular skip)
        gemm_tc<0, false, 128><<<dim3(Sc / 128, Sc / 128, Bc * Hc), 128, T128>>>(
            qh,      ql,      3 * Dc, (long)Sc * 3 * Dc, DH, Hc,
            qh + Dc, ql + Dc, 3 * Dc, (long)Sc * 3 * Dc, DH, Hc,
            nullptr, nullptr,
            gsc, nullptr, nullptr, Sc, (long)Sc * Sc, 0, 1,
            DH, 0.125f, 1);

        smax_sa<<<dim3(Sc, Bc * Hc), 256>>>(gsc, sph, spl);

        gemm_pv<true><<<dim3(1, Sc / 128, Bc * Hc), 128, PVS>>>(
            sph, spl, Sc, (long)Sc * Sc,
            qh + 2 * Dc, ql + 2 * Dc, 3 * Dc, (long)Sc * 3 * Dc, DH, Hc,
            cqh, cql, Dc, (long)Sc * Dc, DH, Hc, Sc);

        // out proj + residual (small grid -> BM=64)
        gemm_tc<3, false, 64><<<dim3(Dc / 128, BS / 64), 128, T64>>>(
            cqh, cql, Dc, 0, 0, 1,
            whi + OFF_SAOUT + (long)l * Dc * Dc, wlo + OFF_SAOUT + (long)l * Dc * Dc, Dc, 0, 0, 1,
            sa_out_b + (long)l * Dc, gx,
            gx, nullptr, nullptr, Dc, 0, 0, 1, Dc, 1.f, 0);

        // ===== cross-attention =====
        ln_k<<<BS, 256>>>(gx, ln_g + (long)(l * 3 + 1) * Dc, ln_b + (long)(l * 3 + 1) * Dc, hh, hl);

        // CA q proj (BM=64)
        gemm_tc<1, true, 64><<<dim3(Dc / 128, BS / 64), 128, T64>>>(
            hh, hl, Dc, 0, 0, 1,
            whi + OFF_CAIN + (long)l * 3 * Dc * Dc, wlo + OFF_CAIN + (long)l * 3 * Dc * Dc, Dc, 0, 0, 1,
            ca_in_b + (long)l * 3 * Dc, nullptr,
            nullptr, cqh, cql, Dc, 0, 0, 1, Dc, 1.f, 0);

        // CA kv proj (M=256 -> BM=64 for 4x CTAs)
        gemm_tc<1, true, 64><<<dim3(2 * Dc / 128, (Bc * Pc) / 64), 128, T64>>>(
            prh, prl, Dc, 0, 0, 1,
            whi + OFF_CAIN + (long)l * 3 * Dc * Dc + (long)Dc * Dc,
            wlo + OFF_CAIN + (long)l * 3 * Dc * Dc + (long)Dc * Dc, Dc, 0, 0, 1,
            ca_in_b + (long)l * 3 * Dc + Dc, nullptr,
            nullptr, ckh, ckl, 2 * Dc, 0, 0, 1, Dc, 1.f, 0);

        // CA scores (BM=128)
        gemm_tc<0, false, 128><<<dim3(Pc / 128, Sc / 128, Bc * Hc), 128, T128>>>(
            cqh, cql, Dc,     (long)Sc * Dc,     DH, Hc,
            ckh, ckl, 2 * Dc, (long)Pc * 2 * Dc, DH, Hc,
            nullptr, nullptr,
            gsc, nullptr, nullptr, Pc, (long)Sc * Pc, 0, 1,
            DH, 0.125f, 0);

        smax_ca<<<dim3(Sc, Bc * Hc), 64>>>(gsc, gpidx, sph, spl);

        gemm_pv<false><<<dim3(1, Sc / 128, Bc * Hc), 128, PVS>>>(
            sph, spl, Pc, (long)Sc * Pc,
            ckh + Dc, ckl + Dc, 2 * Dc, (long)Pc * 2 * Dc, DH, Hc,
            cqh, cql, Dc, (long)Sc * Dc, DH, Hc, Pc);

        // CA out proj + residual (BM=64)
        gemm_tc<3, false, 64><<<dim3(Dc / 128, BS / 64), 128, T64>>>(
            cqh, cql, Dc, 0, 0, 1,
            whi + OFF_CAOUT + (long)l * Dc * Dc, wlo + OFF_CAOUT + (long)l * Dc * Dc, Dc, 0, 0, 1,
            ca_out_b + (long)l * Dc, gx,
            gx, nullptr, nullptr, Dc, 0, 0, 1, Dc, 1.f, 0);

        // ===== FFN =====
        ln_k<<<BS, 256>>>(gx, ln_g + (long)(l * 3 + 2) * Dc, ln_b + (long)(l * 3 + 2) * Dc, hh, hl);

        // FFN1 (fat: BM=128)
        gemm_tc<2, true, 128><<<dim3(4 * Dc / 128, BS / 128), 128, T128>>>(
            hh, hl, Dc, 0, 0, 1,
            whi + OFF_FFN1 + (long)l * 4 * Dc * Dc, wlo + OFF_FFN1 + (long)l * 4 * Dc * Dc, Dc, 0, 0, 1,
            ffn_b1 + (long)l * 4 * Dc, nullptr,
            nullptr, fh, fl, 4 * Dc, 0, 0, 1, Dc, 1.f, 0);

        // FFN2 (BM=64)
        gemm_tc<3, false, 64><<<dim3(Dc / 128, BS / 64), 128, T64>>>(
            fh, fl, 4 * Dc, 0, 0, 1,
            whi + OFF_FFN2 + (long)l * Dc * 4 * Dc, wlo + OFF_FFN2 + (long)l * Dc * 4 * Dc, 4 * Dc, 0, 0, 1,
            ffn_b2 + (long)l * Dc, gx,
            gx, nullptr, nullptr, Dc, 0, 0, 1, 4 * Dc, 1.f, 0);
    }

    // final LN + vocab projection (BM=64)
    ln_k<<<BS, 256>>>(gx, norm_g, norm_b, hh, hl);
    gemm_tc<0, false, 64><<<dim3(Vc / 128, BS / 64), 128, T64>>>(
        hh, hl, Dc, 0, 0, 1,
        whi + OFF_OUTW, wlo + OFF_OUTW, Dc, 0, 0, 1,
        nullptr, nullptr,
        out, nullptr, nullptr, Vc, 0, 0, 1, Dc, 1.f, 0);
}

// round 14
// speedup vs baseline: 1.8997x; 1.0910x over previous
#include <cuda_runtime.h>
#include <cuda_bf16.h>
#include <math.h>
#include <cstdint>

// ---------------- problem constants ----------------
constexpr int Bc = 2, Sc = 1024, Dc = 1024, Hc = 16, Lc = 9, Wc = 1024, Pc = 128, Vc = 256;
constexpr int DH = Dc / Hc;          // 64
constexpr int BS = Bc * Sc;          // 2048 rows

typedef unsigned long long ull;
typedef __nv_bfloat16 bf16;

// ---------------- device scratch ----------------
__device__ float g_x [BS * Dc];                       // residual stream (fp32)
__device__ int   g_pidx[BS];

// weights mega-buffer offsets (elements)
constexpr long OFF_SAIN  = 0;
constexpr long OFF_SAOUT = OFF_SAIN  + (long)Lc * 3 * Dc * Dc;
constexpr long OFF_CAIN  = OFF_SAOUT + (long)Lc * Dc * Dc;
constexpr long OFF_CAOUT = OFF_CAIN  + (long)Lc * 3 * Dc * Dc;
constexpr long OFF_FFN1  = OFF_CAOUT + (long)Lc * Dc * Dc;
constexpr long OFF_FFN2  = OFF_FFN1  + (long)Lc * 4 * Dc * Dc;
constexpr long OFF_OUTW  = OFF_FFN2  + (long)Lc * 4 * Dc * Dc;
constexpr long W_TOTAL   = OFF_OUTW  + (long)Vc * Dc;

__device__ bf16 g_whi[W_TOTAL];
__device__ bf16 g_wlo[W_TOTAL];

__device__ bf16 g_hh [BS * Dc],          g_hl [BS * Dc];
__device__ bf16 g_qh [BS * 3 * Dc],      g_ql [BS * 3 * Dc];
__device__ bf16 g_cqh[BS * Dc],          g_cql[BS * Dc];
__device__ bf16 g_ckh[Bc * Pc * 2 * Dc], g_ckl[Bc * Pc * 2 * Dc];
__device__ bf16 g_fh [BS * 4 * Dc],      g_fl [BS * 4 * Dc];
__device__ bf16 g_prh[Bc * Pc * Dc],     g_prl[Bc * Pc * Dc];

// ---------------- reductions ----------------
__device__ __forceinline__ float block_sum(float v) {
    __shared__ float sh[32];
    int lane = threadIdx.x & 31, w = threadIdx.x >> 5;
    int nw = blockDim.x >> 5;
    #pragma unroll
    for (int o = 16; o; o >>= 1) v += __shfl_xor_sync(0xffffffffu, v, o);
    __syncthreads();
    if (lane == 0) sh[w] = v;
    __syncthreads();
    if (threadIdx.x == 0) {
        float t = 0.f;
        for (int i = 0; i < nw; i++) t += sh[i];
        sh[0] = t;
    }
    __syncthreads();
    return sh[0];
}

// ================= helpers =================
__device__ __forceinline__ uint32_t s2u(const void* p) {
    return (uint32_t)__cvta_generic_to_shared(p);
}
__device__ __forceinline__ void cp16(uint32_t dst, const void* src) {
    asm volatile("cp.async.cg.shared.global [%0], [%1], 16;" :: "r"(dst), "l"(src));
}

#define LDSM4(R, addr) \
    asm volatile("ldmatrix.sync.aligned.m8n8.x4.shared.b16 {%0,%1,%2,%3}, [%4];" \
        : "=r"((R)[0]), "=r"((R)[1]), "=r"((R)[2]), "=r"((R)[3]) : "r"(addr))

#define LDSM4T(R, addr) \
    asm volatile("ldmatrix.sync.aligned.m8n8.x4.trans.shared.b16 {%0,%1,%2,%3}, [%4];" \
        : "=r"((R)[0]), "=r"((R)[1]), "=r"((R)[2]), "=r"((R)[3]) : "r"(addr))

#define MMA16816(d, a, b0, b1) \
    asm volatile("mma.sync.aligned.m16n8k16.row.col.f32.bf16.bf16.f32 " \
        "{%0,%1,%2,%3}, {%4,%5,%6,%7}, {%8,%9}, {%0,%1,%2,%3};" \
        : "+f"((d)[0]), "+f"((d)[1]), "+f"((d)[2]), "+f"((d)[3]) \
        : "r"((a)[0]), "r"((a)[1]), "r"((a)[2]), "r"((a)[3]), "r"(b0), "r"(b1))

__device__ __forceinline__ void split2(float x0, float x1, uint32_t& h, uint32_t& l) {
    __nv_bfloat162 hh = __floats2bfloat162_rn(x0, x1);
    float2 hf = __bfloat1622float2(hh);
    __nv_bfloat162 ll = __floats2bfloat162_rn(x0 - hf.x, x1 - hf.y);
    h = *(uint32_t*)&hh; l = *(uint32_t*)&ll;
}

// ================= pipelined bf16x3 mma.sync GEMM (A @ B^T) =================
constexpr int RS = 40;
constexpr int tcs_bytes(int BM) { return 2 * (2 * BM + 2 * 128) * RS * 2; }

template<int EPI, bool OUTBF, int BM>
__global__ __launch_bounds__(128, (BM == 64 ? 3 : 2))
void gemm_tc(const bf16* __restrict__ Ah, const bf16* __restrict__ Al, int lda, long hiA, long loA, int nloA,
             const bf16* __restrict__ Bh, const bf16* __restrict__ Bl, int ldb, long hiB, long loB, int nloB,
             const float* __restrict__ bias, const float* __restrict__ Res,
             float* __restrict__ C, bf16* __restrict__ Chi, bf16* __restrict__ Clo,
             int ldc, long hiC, long loC, int nloC, int K, float scale)
{
    extern __shared__ __align__(16) bf16 sbuf[];

    constexpr int MT = BM / 32;
    constexpr int TPR = 128 / BM;
    constexpr int QA = BM / 32;
    constexpr int STAGE_E = (2 * BM + 2 * 128) * RS;

    const int m0 = blockIdx.y * BM, n0 = blockIdx.x * 128;

    const int tid = threadIdx.x, lane = tid & 31, wid = tid >> 5;
    const int wm = wid >> 1, wn = wid & 1;
    const int z = blockIdx.z;
    Ah += (long)(z / nloA) * hiA + (long)(z % nloA) * loA;
    Al += (long)(z / nloA) * hiA + (long)(z % nloA) * loA;
    Bh += (long)(z / nloB) * hiB + (long)(z % nloB) * loB;
    Bl += (long)(z / nloB) * hiB + (long)(z % nloB) * loB;
    const long coff = (long)(z / nloC) * hiC + (long)(z % nloC) * loC;

    const uint32_t sbase = s2u(sbuf);

    const int arow = tid / TPR;
    const int akoff = (tid % TPR) * 16;
    const bf16* pAh = Ah + (size_t)(m0 + arow) * lda + akoff;
    const bf16* pAl = Al + (size_t)(m0 + arow) * lda + akoff;
    const bf16* pBh = Bh + (size_t)(n0 + tid) * ldb;
    const bf16* pBl = Bl + (size_t)(n0 + tid) * ldb;

    float acc[MT][8][4];
    #pragma unroll
    for (int i = 0; i < MT; i++)
        #pragma unroll
        for (int j = 0; j < 8; j++)
            #pragma unroll
            for (int q = 0; q < 4; q++) acc[i][j][q] = 0.f;

    const int nk = K / 32;

    auto issue = [&](int c) {
        uint32_t base = sbase + (uint32_t)(c & 1) * (STAGE_E * 2);
        {
            uint32_t dst = base + (uint32_t)(arow * RS + akoff) * 2;
            const bf16* sa = pAh + c * 32;
            const bf16* sl = pAl + c * 32;
            #pragma unroll
            for (int q = 0; q < QA; q++) {
                cp16(dst + q * 16, sa + q * 8);
                cp16(dst + BM * RS * 2 + q * 16, sl + q * 8);
            }
        }
        {
            uint32_t dst = base + (uint32_t)(2 * BM * RS + tid * RS) * 2;
            const bf16* sb = pBh + c * 32;
            const bf16* sl = pBl + c * 32;
            #pragma unroll
            for (int q = 0; q < 4; q++) {
                cp16(dst + q * 16, sb + q * 8);
                cp16(dst + 128 * RS * 2 + q * 16, sl + q * 8);
            }
        }
        asm volatile("cp.async.commit_group;");
    };

    issue(0);

    const int lrow = lane & 15, lko = (lane >> 4) * 8;

    for (int k0 = 0; k0 < nk; k0++) {
        asm volatile("cp.async.wait_group 0;");
        __syncthreads();
        if (k0 + 1 < nk) issue(k0 + 1);

        const bf16* bAh = sbuf + (size_t)(k0 & 1) * STAGE_E;
        const bf16* bAl = bAh + BM * RS;
        const bf16* bBh = bAh + 2 * BM * RS;
        const bf16* bBl = bBh + 128 * RS;

        #pragma unroll
        for (int kk = 0; kk < 32; kk += 16) {
            uint32_t Afh[MT][4], Afl[MT][4];
            #pragma unroll
            for (int mt = 0; mt < MT; mt++)
                LDSM4(Afh[mt], s2u(&bAh[(wm * (BM / 2) + mt * 16 + lrow) * RS + kk + lko]));
            #pragma unroll
            for (int mt = 0; mt < MT; mt++)
                LDSM4(Afl[mt], s2u(&bAl[(wm * (BM / 2) + mt * 16 + lrow) * RS + kk + lko]));

            #pragma unroll
            for (int p = 0; p < 4; p++) {
                uint32_t Bfh[4], Bfl[4];
                LDSM4(Bfh, s2u(&bBh[(wn * 64 + p * 16 + lrow) * RS + kk + lko]));
                LDSM4(Bfl, s2u(&bBl[(wn * 64 + p * 16 + lrow) * RS + kk + lko]));
                #pragma unroll
                for (int mt = 0; mt < MT; mt++) {
                    MMA16816(acc[mt][2 * p + 0], Afh[mt], Bfh[0], Bfh[2]);
                    MMA16816(acc[mt][2 * p + 1], Afh[mt], Bfh[1], Bfh[3]);
                    MMA16816(acc[mt][2 * p + 0], Afh[mt], Bfl[0], Bfl[2]);
                    MMA16816(acc[mt][2 * p + 1], Afh[mt], Bfl[1], Bfl[3]);
                    MMA16816(acc[mt][2 * p + 0], Afl[mt], Bfh[0], Bfh[2]);
                    MMA16816(acc[mt][2 * p + 1], Afl[mt], Bfh[1], Bfh[3]);
                }
            }
        }
    }

    float* Cb = C ? (C + coff) : nullptr;
    const float* Rb = (EPI == 3) ? (Res + coff) : nullptr;
    bf16* Hb = OUTBF ? (Chi + coff) : nullptr;
    bf16* Lb = OUTBF ? (Clo + coff) : nullptr;
    const int rb = lane >> 2, cbl = (lane & 3) * 2;
    #pragma unroll
    for (int mt = 0; mt < MT; mt++) {
        #pragma unroll
        for (int half = 0; half < 2; half++) {
            int r = m0 + wm * (BM / 2) + mt * 16 + rb + half * 8;
            #pragma unroll
            for (int j = 0; j < 8; j++) {
                int cc = n0 + wn * 64 + (j >> 1) * 16 + (j & 1) * 8 + cbl;
                float x0 = acc[mt][j][half * 2 + 0] * scale;
                float x1 = acc[mt][j][half * 2 + 1] * scale;
                if (EPI >= 1) { x0 += bias[cc]; x1 += bias[cc + 1]; }
                if (EPI == 2) {
                    x0 = 0.5f * x0 * (1.f + erff(x0 * 0.70710678118654752f));
                    x1 = 0.5f * x1 * (1.f + erff(x1 * 0.70710678118654752f));
                }
                if (EPI == 3) {
                    float2 rv = *(const float2*)(Rb + (size_t)r * ldc + cc);
                    x0 += rv.x; x1 += rv.y;
                }
                if (Cb) *(float2*)(Cb + (size_t)r * ldc + cc) = make_float2(x0, x1);
                if (OUTBF) {
                    uint32_t h, l;
                    split2(x0, x1, h, l);
                    *(uint32_t*)(Hb + (size_t)r * ldc + cc) = h;
                    *(uint32_t*)(Lb + (size_t)r * ldc + cc) = l;
                }
            }
        }
    }
}

// ================= fused flash attention =================
// Q block 64 rows/CTA; K/V blocks of 64 keys, cp.async double-buffered.
// MASK 0: causal (limit = row). MASK 1: patch (limit = pidx[row]).
// DH = 64. 4 warps; warp w owns Q rows [w*16, w*16+16).
constexpr int FR = 72;                         // smem row stride (bf16)
constexpr int FQE = 2 * 64 * FR;               // Q elems (hi+lo)
constexpr int FSTE = 4 * 64 * FR;              // per-stage elems (Khi,Klo,Vhi,Vlo)
constexpr int FSZ = (FQE + 2 * FSTE) * 2;      // bytes = 92160

template<int MASK>
__global__ __launch_bounds__(128, 2)
void flash_att(const bf16* __restrict__ Qh, const bf16* __restrict__ Ql, int ldq, long hiQ, long loQ,
               const bf16* __restrict__ Kh, const bf16* __restrict__ Kl,
               const bf16* __restrict__ Vh, const bf16* __restrict__ Vl, int ldk, long hiK, long loK,
               const int* __restrict__ pidx,
               bf16* __restrict__ Ohp, bf16* __restrict__ Olp, int ldo, long hiO, long loO,
               int nKeys)
{
    extern __shared__ __align__(16) bf16 sbuf[];

    const int tid = threadIdx.x, lane = tid & 31, wid = tid >> 5;
    const int z = blockIdx.y;
    const int m0 = blockIdx.x * 64;
    const int b = z / Hc;

    const long qoff = (long)(z / Hc) * hiQ + (long)(z % Hc) * loQ;
    const long koff = (long)(z / Hc) * hiK + (long)(z % Hc) * loK;
    const long ooff = (long)(z / Hc) * hiO + (long)(z % Hc) * loO;

    const bf16* pQh = Qh + qoff;
    const bf16* pQl = Ql + qoff;
    const bf16* pKh = Kh + koff;
    const bf16* pKl = Kl + koff;
    const bf16* pVh = Vh + koff;
    const bf16* pVl = Vl + koff;

    const uint32_t sbase = s2u(sbuf);
    const int lrow2 = tid >> 1, lhalf = (tid & 1) * 32;   // loader mapping

    // load Q block (rows m0..m0+63, 64 cols) hi/lo
    {
        uint32_t dq = sbase + (uint32_t)(lrow2 * FR + lhalf) * 2;
        const bf16* sq = pQh + (size_t)(m0 + lrow2) * ldq + lhalf;
        const bf16* sl = pQl + (size_t)(m0 + lrow2) * ldq + lhalf;
        #pragma unroll
        for (int q = 0; q < 4; q++) {
            cp16(dq + q * 16, sq + q * 8);
            cp16(dq + 64 * FR * 2 + q * 16, sl + q * 8);
        }
    }

    auto issueKV = [&](int jb) {
        uint32_t base = sbase + (uint32_t)(FQE + (jb & 1) * FSTE) * 2;
        const bf16* srcs[4];
        srcs[0] = pKh + (size_t)(jb * 64 + lrow2) * ldk + lhalf;
        srcs[1] = pKl + (size_t)(jb * 64 + lrow2) * ldk + lhalf;
        srcs[2] = pVh + (size_t)(jb * 64 + lrow2) * ldk + lhalf;
        srcs[3] = pVl + (size_t)(jb * 64 + lrow2) * ldk + lhalf;
        #pragma unroll
        for (int t = 0; t < 4; t++) {
            uint32_t dst = base + (uint32_t)(t * 64 * FR + lrow2 * FR + lhalf) * 2;
            #pragma unroll
            for (int q = 0; q < 4; q++)
                cp16(dst + q * 16, srcs[t] + q * 8);
        }
        asm volatile("cp.async.commit_group;");
    };

    issueKV(0);

    const int nb = (MASK == 0) ? (m0 / 64 + 1) : (nKeys / 64);

    // per-lane row limits
    const int gr0 = m0 + wid * 16 + (lane >> 2);
    int lim0, lim1;
    if (MASK == 0) { lim0 = gr0; lim1 = gr0 + 8; }
    else           { lim0 = pidx[b * Sc + gr0]; lim1 = pidx[b * Sc + gr0 + 8]; }

    float o[8][4];
    #pragma unroll
    for (int g = 0; g < 8; g++)
        #pragma unroll
        for (int q = 0; q < 4; q++) o[g][q] = 0.f;
    float mr0 = -1e30f, mr1 = -1e30f, lr0 = 0.f, lr1 = 0.f;

    const int lrow = lane & 15, lko = (lane >> 4) * 8;
    const int tkrow = (lane & 7) + ((lane >> 4) << 3);
    const int tncol = ((lane >> 3) & 1) * 8;
    const int cbl = (lane & 3) * 2;

    for (int jb = 0; jb < nb; jb++) {
        asm volatile("cp.async.wait_group 0;");
        __syncthreads();
        if (jb + 1 < nb) issueKV(jb + 1);

        const bf16* sQh = sbuf;
        const bf16* sQl = sQh + 64 * FR;
        const bf16* sKh = sbuf + FQE + (size_t)(jb & 1) * FSTE;
        const bf16* sKl = sKh + 64 * FR;
        const bf16* sVh = sKh + 2 * 64 * FR;
        const bf16* sVl = sKh + 3 * 64 * FR;

        // ---- S = Q @ K^T (bf16x3)
        float s[8][4];
        #pragma unroll
        for (int g = 0; g < 8; g++)
            #pragma unroll
            for (int q = 0; q < 4; q++) s[g][q] = 0.f;

        #pragma unroll
        for (int kk = 0; kk < 64; kk += 16) {
            uint32_t qfh[4], qfl[4];
            LDSM4(qfh, s2u(&sQh[(wid * 16 + lrow) * FR + kk + lko]));
            LDSM4(qfl, s2u(&sQl[(wid * 16 + lrow) * FR + kk + lko]));
            #pragma unroll
            for (int p = 0; p < 4; p++) {
                uint32_t kfh[4], kfl[4];
                LDSM4(kfh, s2u(&sKh[(p * 16 + lrow) * FR + kk + lko]));
                LDSM4(kfl, s2u(&sKl[(p * 16 + lrow) * FR + kk + lko]));
                MMA16816(s[2 * p + 0], qfh, kfh[0], kfh[2]);
                MMA16816(s[2 * p + 1], qfh, kfh[1], kfh[3]);
                MMA16816(s[2 * p + 0], qfh, kfl[0], kfl[2]);
                MMA16816(s[2 * p + 1], qfh, kfl[1], kfl[3]);
                MMA16816(s[2 * p + 0], qfl, kfh[0], kfh[2]);
                MMA16816(s[2 * p + 1], qfl, kfh[1], kfh[3]);
            }
        }

        // ---- scale + mask
        const int jbase = jb * 64;
        #pragma unroll
        for (int g = 0; g < 8; g++) {
            #pragma unroll
            for (int q = 0; q < 4; q++) {
                int col = jbase + g * 8 + cbl + (q & 1);
                int lim = (q < 2) ? lim0 : lim1;
                float v = s[g][q] * 0.125f;
                s[g][q] = (col > lim) ? -1e30f : v;
            }
        }

        // ---- online softmax
        float mx0 = -1e30f, mx1 = -1e30f;
        #pragma unroll
        for (int g = 0; g < 8; g++) {
            mx0 = fmaxf(mx0, fmaxf(s[g][0], s[g][1]));
            mx1 = fmaxf(mx1, fmaxf(s[g][2], s[g][3]));
        }
        mx0 = fmaxf(mx0, __shfl_xor_sync(0xffffffffu, mx0, 1));
        mx0 = fmaxf(mx0, __shfl_xor_sync(0xffffffffu, mx0, 2));
        mx1 = fmaxf(mx1, __shfl_xor_sync(0xffffffffu, mx1, 1));
        mx1 = fmaxf(mx1, __shfl_xor_sync(0xffffffffu, mx1, 2));

        float nm0 = fmaxf(mr0, mx0), nm1 = fmaxf(mr1, mx1);
        float c0 = expf(mr0 - nm0), c1 = expf(mr1 - nm1);

        float sum0 = 0.f, sum1 = 0.f;
        #pragma unroll
        for (int g = 0; g < 8; g++) {
            s[g][0] = expf(s[g][0] - nm0); sum0 += s[g][0];
            s[g][1] = expf(s[g][1] - nm0); sum0 += s[g][1];
            s[g][2] = expf(s[g][2] - nm1); sum1 += s[g][2];
            s[g][3] = expf(s[g][3] - nm1); sum1 += s[g][3];
        }
        sum0 += __shfl_xor_sync(0xffffffffu, sum0, 1);
        sum0 += __shfl_xor_sync(0xffffffffu, sum0, 2);
        sum1 += __shfl_xor_sync(0xffffffffu, sum1, 1);
        sum1 += __shfl_xor_sync(0xffffffffu, sum1, 2);

        lr0 = lr0 * c0 + sum0;
        lr1 = lr1 * c1 + sum1;
        mr0 = nm0; mr1 = nm1;

        #pragma unroll
        for (int g = 0; g < 8; g++) {
            o[g][0] *= c0; o[g][1] *= c0;
            o[g][2] *= c1; o[g][3] *= c1;
        }

        // ---- O += P @ V (P fragments from S accumulators; bf16x3)
        #pragma unroll
        for (int t = 0; t < 4; t++) {
            uint32_t Pa_h[4], Pa_l[4];
            split2(s[2 * t][0],     s[2 * t][1],     Pa_h[0], Pa_l[0]);
            split2(s[2 * t][2],     s[2 * t][3],     Pa_h[1], Pa_l[1]);
            split2(s[2 * t + 1][0], s[2 * t + 1][1], Pa_h[2], Pa_l[2]);
            split2(s[2 * t + 1][2], s[2 * t + 1][3], Pa_h[3], Pa_l[3]);
            #pragma unroll
            for (int p = 0; p < 4; p++) {
                uint32_t vfh[4], vfl[4];
                LDSM4T(vfh, s2u(&sVh[(t * 16 + tkrow) * FR + p * 16 + tncol]));
                LDSM4T(vfl, s2u(&sVl[(t * 16 + tkrow) * FR + p * 16 + tncol]));
                MMA16816(o[2 * p + 0], Pa_h, vfh[0], vfh[2]);
                MMA16816(o[2 * p + 1], Pa_h, vfh[1], vfh[3]);
                MMA16816(o[2 * p + 0], Pa_h, vfl[0], vfl[2]);
                MMA16816(o[2 * p + 1], Pa_h, vfl[1], vfl[3]);
                MMA16816(o[2 * p + 0], Pa_l, vfh[0], vfh[2]);
                MMA16816(o[2 * p + 1], Pa_l, vfh[1], vfh[3]);
            }
        }
    }

    // ---- epilogue: normalize + write bf16 hi/lo planes
    float inv0 = 1.f / lr0, inv1 = 1.f / lr1;
    bf16* Ob_h = Ohp + ooff;
    bf16* Ob_l = Olp + ooff;
    const int r0 = m0 + wid * 16 + (lane >> 2);
    #pragma unroll
    for (int g = 0; g < 8; g++) {
        int cc = g * 8 + cbl;
        uint32_t h, l;
        split2(o[g][0] * inv0, o[g][1] * inv0, h, l);
        *(uint32_t*)(Ob_h + (size_t)r0 * ldo + cc) = h;
        *(uint32_t*)(Ob_l + (size_t)r0 * ldo + cc) = l;
        split2(o[g][2] * inv1, o[g][3] * inv1, h, l);
        *(uint32_t*)(Ob_h + (size_t)(r0 + 8) * ldo + cc) = h;
        *(uint32_t*)(Ob_l + (size_t)(r0 + 8) * ldo + cc) = l;
    }
}

// ---------------- fp32 -> bf16 hi/lo conversion ----------------
__global__ void cvt_k(const float* __restrict__ x, bf16* __restrict__ hi,
                      bf16* __restrict__ lo, long n)
{
    long i = ((long)blockIdx.x * blockDim.x + threadIdx.x) * 4;
    if (i >= n) return;
    float4 v = *(const float4*)(x + i);
    uint32_t h0, l0, h1, l1;
    split2(v.x, v.y, h0, l0);
    split2(v.z, v.w, h1, l1);
    *(uint2*)(hi + i) = make_uint2(h0, h1);
    *(uint2*)(lo + i) = make_uint2(l0, l1);
}

// ---------------- embedding ----------------
__global__ void embed_k(const int* __restrict__ seq, const float* __restrict__ bemb,
                        const float* __restrict__ pemb, float* __restrict__ x)
{
    int r = blockIdx.x;
    int s = r % Sc;
    int tok = seq[r];
    int c = threadIdx.x * 4;
    float4 e = *(const float4*)(bemb + (long)tok * Dc + c);
    float4 p = *(const float4*)(pemb + (long)s * Dc + c);
    e.x += p.x; e.y += p.y; e.z += p.z; e.w += p.w;
    *(float4*)(x + (long)r * Dc + c) = e;
}

// ---------------- layernorm -> bf16 hi/lo planes ----------------
__global__ void ln_k(const float* __restrict__ x, const float* __restrict__ g,
                     const float* __restrict__ b, bf16* __restrict__ hi,
                     bf16* __restrict__ lo)
{
    const int row = blockIdx.x;
    const int tid = threadIdx.x;
    const float* xr = x + (long)row * Dc;
    float4 v = *(const float4*)(xr + tid * 4);
    float s = v.x + v.y + v.z + v.w;
    float tot = block_sum(s);
    float m = tot * (1.f / Dc);
    float dx0 = v.x - m, dx1 = v.y - m, dx2 = v.z - m, dx3 = v.w - m;
    float q = dx0 * dx0 + dx1 * dx1 + dx2 * dx2 + dx3 * dx3;
    float totq = block_sum(q);
    float rs = rsqrtf(totq * (1.f / Dc) + 1e-5f);
    float4 gg = *(const float4*)(g + tid * 4);
    float4 bb = *(const float4*)(b + tid * 4);
    float o0 = dx0 * rs * gg.x + bb.x;
    float o1 = dx1 * rs * gg.y + bb.y;
    float o2 = dx2 * rs * gg.z + bb.z;
    float o3 = dx3 * rs * gg.w + bb.w;
    uint32_t h0, l0, h1, l1;
    split2(o0, o1, h0, l0);
    split2(o2, o3, h1, l1);
    *(uint2*)(hi + (long)row * Dc + tid * 4) = make_uint2(h0, h1);
    *(uint2*)(lo + (long)row * Dc + tid * 4) = make_uint2(l0, l1);
}

// ---------------- inclusive cumsum ----------------
__global__ void cumsum_k(const int* __restrict__ bd, int* __restrict__ pidx)
{
    __shared__ int s[Sc];
    const int b = blockIdx.x, t = threadIdx.x;
    s[t] = bd[b * Sc + t];
    __syncthreads();
    for (int off = 1; off < Sc; off <<= 1) {
        int v = (t >= off) ? s[t - off] : 0;
        __syncthreads();
        s[t] += v;
        __syncthreads();
    }
    pidx[b * Sc + t] = s[t];
}

// ---------------- launcher ----------------
extern "C" void kernel_launch(void* const* d_in, const int* in_sizes, int n_in,
                              void* d_out, int out_size)
{
    const int*   byte_seq  = (const int*)  d_in[0];
    const float* patch_rep = (const float*)d_in[1];
    const int*   patch_bd  = (const int*)  d_in[2];
    const float* byte_emb  = (const float*)d_in[3];
    const float* pos_emb   = (const float*)d_in[4];
    const float* sa_in_w   = (const float*)d_in[5];
    const float* sa_in_b   = (const float*)d_in[6];
    const float* sa_out_w  = (const float*)d_in[7];
    const float* sa_out_b  = (const float*)d_in[8];
    const float* ca_in_w   = (const float*)d_in[9];
    const float* ca_in_b   = (const float*)d_in[10];
    const float* ca_out_w  = (const float*)d_in[11];
    const float* ca_out_b  = (const float*)d_in[12];
    const float* ffn_w1    = (const float*)d_in[13];
    const float* ffn_b1    = (const float*)d_in[14];
    const float* ffn_w2    = (const float*)d_in[15];
    const float* ffn_b2    = (const float*)d_in[16];
    const float* ln_g      = (const float*)d_in[17];
    const float* ln_b      = (const float*)d_in[18];
    const float* norm_g    = (const float*)d_in[19];
    const float* norm_b    = (const float*)d_in[20];
    const float* out_w     = (const float*)d_in[21];
    float* out = (float*)d_out;

    float* gx;
    int* gpidx;
    bf16 *whi, *wlo, *hh, *hl, *qh, *ql, *cqh, *cql, *ckh, *ckl, *fh, *fl, *prh, *prl;
    cudaGetSymbolAddress((void**)&gx,   g_x);
    cudaGetSymbolAddress((void**)&gpidx, g_pidx);
    cudaGetSymbolAddress((void**)&whi, g_whi);
    cudaGetSymbolAddress((void**)&wlo, g_wlo);
    cudaGetSymbolAddress((void**)&hh,  g_hh);
    cudaGetSymbolAddress((void**)&hl,  g_hl);
    cudaGetSymbolAddress((void**)&qh,  g_qh);
    cudaGetSymbolAddress((void**)&ql,  g_ql);
    cudaGetSymbolAddress((void**)&cqh, g_cqh);
    cudaGetSymbolAddress((void**)&cql, g_cql);
    cudaGetSymbolAddress((void**)&ckh, g_ckh);
    cudaGetSymbolAddress((void**)&ckl, g_ckl);
    cudaGetSymbolAddress((void**)&fh,  g_fh);
    cudaGetSymbolAddress((void**)&fl,  g_fl);
    cudaGetSymbolAddress((void**)&prh, g_prh);
    cudaGetSymbolAddress((void**)&prl, g_prl);

    constexpr int T128 = tcs_bytes(128);
    constexpr int T64  = tcs_bytes(64);
    cudaFuncSetAttribute(gemm_tc<1, true, 128>,  cudaFuncAttributeMaxDynamicSharedMemorySize, T128);
    cudaFuncSetAttribute(gemm_tc<2, true, 128>,  cudaFuncAttributeMaxDynamicSharedMemorySize, T128);
    cudaFuncSetAttribute(gemm_tc<0, false, 64>,  cudaFuncAttributeMaxDynamicSharedMemorySize, T64);
    cudaFuncSetAttribute(gemm_tc<1, true, 64>,   cudaFuncAttributeMaxDynamicSharedMemorySize, T64);
    cudaFuncSetAttribute(gemm_tc<3, false, 64>,  cudaFuncAttributeMaxDynamicSharedMemorySize, T64);
    cudaFuncSetAttribute(flash_att<0>, cudaFuncAttributeMaxDynamicSharedMemorySize, FSZ);
    cudaFuncSetAttribute(flash_att<1>, cudaFuncAttributeMaxDynamicSharedMemorySize, FSZ);

    auto cvt = [&](const float* src, bf16* dh, bf16* dl, long n) {
        cvt_k<<<(unsigned)((n / 4 + 255) / 256), 256>>>(src, dh, dl, n);
    };
    cvt(sa_in_w,  whi + OFF_SAIN,  wlo + OFF_SAIN,  (long)Lc * 3 * Dc * Dc);
    cvt(sa_out_w, whi + OFF_SAOUT, wlo + OFF_SAOUT, (long)Lc * Dc * Dc);
    cvt(ca_in_w,  whi + OFF_CAIN,  wlo + OFF_CAIN,  (long)Lc * 3 * Dc * Dc);
    cvt(ca_out_w, whi + OFF_CAOUT, wlo + OFF_CAOUT, (long)Lc * Dc * Dc);
    cvt(ffn_w1,   whi + OFF_FFN1,  wlo + OFF_FFN1,  (long)Lc * 4 * Dc * Dc);
    cvt(ffn_w2,   whi + OFF_FFN2,  wlo + OFF_FFN2,  (long)Lc * 4 * Dc * Dc);
    cvt(out_w,    whi + OFF_OUTW,  wlo + OFF_OUTW,  (long)Vc * Dc);
    cvt(patch_rep, prh, prl, (long)Bc * Pc * Dc);

    embed_k<<<BS, 256>>>(byte_seq, byte_emb, pos_emb, gx);
    cumsum_k<<<Bc, Sc>>>(patch_bd, gpidx);

    for (int l = 0; l < Lc; l++) {
        // ===== self-attention =====
        ln_k<<<BS, 256>>>(gx, ln_g + (long)(l * 3 + 0) * Dc, ln_b + (long)(l * 3 + 0) * Dc, hh, hl);

        gemm_tc<1, true, 128><<<dim3(3 * Dc / 128, BS / 128), 128, T128>>>(
            hh, hl, Dc, 0, 0, 1,
            whi + OFF_SAIN + (long)l * 3 * Dc * Dc, wlo + OFF_SAIN + (long)l * 3 * Dc * Dc, Dc, 0, 0, 1,
            sa_in_b + (long)l * 3 * Dc, nullptr,
            nullptr, qh, ql, 3 * Dc, 0, 0, 1, Dc, 1.f);

        // fused attention: scores + softmax + PV
        flash_att<0><<<dim3(Sc / 64, Bc * Hc), 128, FSZ>>>(
            qh, ql, 3 * Dc, (long)Sc * 3 * Dc, DH,
            qh + Dc, ql + Dc, qh + 2 * Dc, ql + 2 * Dc, 3 * Dc, (long)Sc * 3 * Dc, DH,
            nullptr,
            cqh, cql, Dc, (long)Sc * Dc, DH, Sc);

        gemm_tc<3, false, 64><<<dim3(Dc / 128, BS / 64), 128, T64>>>(
            cqh, cql, Dc, 0, 0, 1,
            whi + OFF_SAOUT + (long)l * Dc * Dc, wlo + OFF_SAOUT + (long)l * Dc * Dc, Dc, 0, 0, 1,
            sa_out_b + (long)l * Dc, gx,
            gx, nullptr, nullptr, Dc, 0, 0, 1, Dc, 1.f);

        // ===== cross-attention =====
        ln_k<<<BS, 256>>>(gx, ln_g + (long)(l * 3 + 1) * Dc, ln_b + (long)(l * 3 + 1) * Dc, hh, hl);

        gemm_tc<1, true, 64><<<dim3(Dc / 128, BS / 64), 128, T64>>>(
            hh, hl, Dc, 0, 0, 1,
            whi + OFF_CAIN + (long)l * 3 * Dc * Dc, wlo + OFF_CAIN + (long)l * 3 * Dc * Dc, Dc, 0, 0, 1,
            ca_in_b + (long)l * 3 * Dc, nullptr,
            nullptr, cqh, cql, Dc, 0, 0, 1, Dc, 1.f);

        gemm_tc<1, true, 64><<<dim3(2 * Dc / 128, (Bc * Pc) / 64), 128, T64>>>(
            prh, prl, Dc, 0, 0, 1,
            whi + OFF_CAIN + (long)l * 3 * Dc * Dc + (long)Dc * Dc,
            wlo + OFF_CAIN + (long)l * 3 * Dc * Dc + (long)Dc * Dc, Dc, 0, 0, 1,
            ca_in_b + (long)l * 3 * Dc + Dc, nullptr,
            nullptr, ckh, ckl, 2 * Dc, 0, 0, 1, Dc, 1.f);

        flash_att<1><<<dim3(Sc / 64, Bc * Hc), 128, FSZ>>>(
            cqh, cql, Dc, (long)Sc * Dc, DH,
            ckh, ckl, ckh + Dc, ckl + Dc, 2 * Dc, (long)Pc * 2 * Dc, DH,
            gpidx,
            cqh, cql, Dc, (long)Sc * Dc, DH, Pc);

        gemm_tc<3, false, 64><<<dim3(Dc / 128, BS / 64), 128, T64>>>(
            cqh, cql, Dc, 0, 0, 1,
            whi + OFF_CAOUT + (long)l * Dc * Dc, wlo + OFF_CAOUT + (long)l * Dc * Dc, Dc, 0, 0, 1,
            ca_out_b + (long)l * Dc, gx,
            gx, nullptr, nullptr, Dc, 0, 0, 1, Dc, 1.f);

        // ===== FFN =====
        ln_k<<<BS, 256>>>(gx, ln_g + (long)(l * 3 + 2) * Dc, ln_b + (long)(l * 3 + 2) * Dc, hh, hl);

        gemm_tc<2, true, 128><<<dim3(4 * Dc / 128, BS / 128), 128, T128>>>(
            hh, hl, Dc, 0, 0, 1,
            whi + OFF_FFN1 + (long)l * 4 * Dc * Dc, wlo + OFF_FFN1 + (long)l * 4 * Dc * Dc, Dc, 0, 0, 1,
            ffn_b1 + (long)l * 4 * Dc, nullptr,
            nullptr, fh, fl, 4 * Dc, 0, 0, 1, Dc, 1.f);

        gemm_tc<3, false, 64><<<dim3(Dc / 128, BS / 64), 128, T64>>>(
            fh, fl, 4 * Dc, 0, 0, 1,
            whi + OFF_FFN2 + (long)l * Dc * 4 * Dc, wlo + OFF_FFN2 + (long)l * Dc * 4 * Dc, 4 * Dc, 0, 0, 1,
            ffn_b2 + (long)l * Dc, gx,
            gx, nullptr, nullptr, Dc, 0, 0, 1, 4 * Dc, 1.f);
    }

    // final LN + vocab projection
    ln_k<<<BS, 256>>>(gx, norm_g, norm_b, hh, hl);
    gemm_tc<0, false, 64><<<dim3(Vc / 128, BS / 64), 128, T64>>>(
        hh, hl, Dc, 0, 0, 1,
        whi + OFF_OUTW, wlo + OFF_OUTW, Dc, 0, 0, 1,
        nullptr, nullptr,
        out, nullptr, nullptr, Vc, 0, 0, 1, Dc, 1.f);
}

// round 15
// speedup vs baseline: 1.9089x; 1.0049x over previous
#include <cuda_runtime.h>
#include <cuda_bf16.h>
#include <math.h>
#include <cstdint>

// ---------------- problem constants ----------------
constexpr int Bc = 2, Sc = 1024, Dc = 1024, Hc = 16, Lc = 9, Wc = 1024, Pc = 128, Vc = 256;
constexpr int DH = Dc / Hc;          // 64
constexpr int BS = Bc * Sc;          // 2048 rows

typedef unsigned long long ull;
typedef __nv_bfloat16 bf16;

// ---------------- device scratch ----------------
__device__ float g_x [BS * Dc];
__device__ int   g_pidx[BS];

constexpr long OFF_SAIN  = 0;
constexpr long OFF_SAOUT = OFF_SAIN  + (long)Lc * 3 * Dc * Dc;
constexpr long OFF_CAIN  = OFF_SAOUT + (long)Lc * Dc * Dc;
constexpr long OFF_CAOUT = OFF_CAIN  + (long)Lc * 3 * Dc * Dc;
constexpr long OFF_FFN1  = OFF_CAOUT + (long)Lc * Dc * Dc;
constexpr long OFF_FFN2  = OFF_FFN1  + (long)Lc * 4 * Dc * Dc;
constexpr long OFF_OUTW  = OFF_FFN2  + (long)Lc * 4 * Dc * Dc;
constexpr long W_TOTAL   = OFF_OUTW  + (long)Vc * Dc;

__device__ bf16 g_whi[W_TOTAL];
__device__ bf16 g_wlo[W_TOTAL];

__device__ bf16 g_hh [BS * Dc],          g_hl [BS * Dc];
__device__ bf16 g_qh [BS * 3 * Dc],      g_ql [BS * 3 * Dc];
__device__ bf16 g_cqh[BS * Dc],          g_cql[BS * Dc];
__device__ bf16 g_ckh[Bc * Pc * 2 * Dc], g_ckl[Bc * Pc * 2 * Dc];
__device__ bf16 g_fh [BS * 4 * Dc],      g_fl [BS * 4 * Dc];
__device__ bf16 g_prh[Bc * Pc * Dc],     g_prl[Bc * Pc * Dc];

// ---------------- reductions ----------------
__device__ __forceinline__ float block_sum(float v) {
    __shared__ float sh[32];
    int lane = threadIdx.x & 31, w = threadIdx.x >> 5;
    int nw = blockDim.x >> 5;
    #pragma unroll
    for (int o = 16; o; o >>= 1) v += __shfl_xor_sync(0xffffffffu, v, o);
    __syncthreads();
    if (lane == 0) sh[w] = v;
    __syncthreads();
    if (threadIdx.x == 0) {
        float t = 0.f;
        for (int i = 0; i < nw; i++) t += sh[i];
        sh[0] = t;
    }
    __syncthreads();
    return sh[0];
}

// ================= helpers =================
__device__ __forceinline__ uint32_t s2u(const void* p) {
    return (uint32_t)__cvta_generic_to_shared(p);
}
__device__ __forceinline__ void cp16(uint32_t dst, const void* src) {
    asm volatile("cp.async.cg.shared.global [%0], [%1], 16;" :: "r"(dst), "l"(src));
}

#define LDSM4(R, addr) \
    asm volatile("ldmatrix.sync.aligned.m8n8.x4.shared.b16 {%0,%1,%2,%3}, [%4];" \
        : "=r"((R)[0]), "=r"((R)[1]), "=r"((R)[2]), "=r"((R)[3]) : "r"(addr))

#define LDSM4T(R, addr) \
    asm volatile("ldmatrix.sync.aligned.m8n8.x4.trans.shared.b16 {%0,%1,%2,%3}, [%4];" \
        : "=r"((R)[0]), "=r"((R)[1]), "=r"((R)[2]), "=r"((R)[3]) : "r"(addr))

#define MMA16816(d, a, b0, b1) \
    asm volatile("mma.sync.aligned.m16n8k16.row.col.f32.bf16.bf16.f32 " \
        "{%0,%1,%2,%3}, {%4,%5,%6,%7}, {%8,%9}, {%0,%1,%2,%3};" \
        : "+f"((d)[0]), "+f"((d)[1]), "+f"((d)[2]), "+f"((d)[3]) \
        : "r"((a)[0]), "r"((a)[1]), "r"((a)[2]), "r"((a)[3]), "r"(b0), "r"(b1))

__device__ __forceinline__ void split2(float x0, float x1, uint32_t& h, uint32_t& l) {
    __nv_bfloat162 hh = __floats2bfloat162_rn(x0, x1);
    float2 hf = __bfloat1622float2(hh);
    __nv_bfloat162 ll = __floats2bfloat162_rn(x0 - hf.x, x1 - hf.y);
    h = *(uint32_t*)&hh; l = *(uint32_t*)&ll;
}

// ================= pipelined bf16x3 mma.sync GEMM (A @ B^T) =================
constexpr int RS = 40;
constexpr int tcs_bytes(int BM) { return 2 * (2 * BM + 2 * 128) * RS * 2; }

template<int EPI, bool OUTBF, int BM>
__global__ __launch_bounds__(128, (BM == 64 ? 3 : 2))
void gemm_tc(const bf16* __restrict__ Ah, const bf16* __restrict__ Al, int lda, long hiA, long loA, int nloA,
             const bf16* __restrict__ Bh, const bf16* __restrict__ Bl, int ldb, long hiB, long loB, int nloB,
             const float* __restrict__ bias, const float* __restrict__ Res,
             float* __restrict__ C, bf16* __restrict__ Chi, bf16* __restrict__ Clo,
             int ldc, long hiC, long loC, int nloC, int K, float scale)
{
    extern __shared__ __align__(16) bf16 sbuf[];

    constexpr int MT = BM / 32;
    constexpr int TPR = 128 / BM;
    constexpr int QA = BM / 32;
    constexpr int STAGE_E = (2 * BM + 2 * 128) * RS;

    const int m0 = blockIdx.y * BM, n0 = blockIdx.x * 128;

    const int tid = threadIdx.x, lane = tid & 31, wid = tid >> 5;
    const int wm = wid >> 1, wn = wid & 1;
    const int z = blockIdx.z;
    Ah += (long)(z / nloA) * hiA + (long)(z % nloA) * loA;
    Al += (long)(z / nloA) * hiA + (long)(z % nloA) * loA;
    Bh += (long)(z / nloB) * hiB + (long)(z % nloB) * loB;
    Bl += (long)(z / nloB) * hiB + (long)(z % nloB) * loB;
    const long coff = (long)(z / nloC) * hiC + (long)(z % nloC) * loC;

    const uint32_t sbase = s2u(sbuf);

    const int arow = tid / TPR;
    const int akoff = (tid % TPR) * 16;
    const bf16* pAh = Ah + (size_t)(m0 + arow) * lda + akoff;
    const bf16* pAl = Al + (size_t)(m0 + arow) * lda + akoff;
    const bf16* pBh = Bh + (size_t)(n0 + tid) * ldb;
    const bf16* pBl = Bl + (size_t)(n0 + tid) * ldb;

    float acc[MT][8][4];
    #pragma unroll
    for (int i = 0; i < MT; i++)
        #pragma unroll
        for (int j = 0; j < 8; j++)
            #pragma unroll
            for (int q = 0; q < 4; q++) acc[i][j][q] = 0.f;

    const int nk = K / 32;

    auto issue = [&](int c) {
        uint32_t base = sbase + (uint32_t)(c & 1) * (STAGE_E * 2);
        {
            uint32_t dst = base + (uint32_t)(arow * RS + akoff) * 2;
            const bf16* sa = pAh + c * 32;
            const bf16* sl = pAl + c * 32;
            #pragma unroll
            for (int q = 0; q < QA; q++) {
                cp16(dst + q * 16, sa + q * 8);
                cp16(dst + BM * RS * 2 + q * 16, sl + q * 8);
            }
        }
        {
            uint32_t dst = base + (uint32_t)(2 * BM * RS + tid * RS) * 2;
            const bf16* sb = pBh + c * 32;
            const bf16* sl = pBl + c * 32;
            #pragma unroll
            for (int q = 0; q < 4; q++) {
                cp16(dst + q * 16, sb + q * 8);
                cp16(dst + 128 * RS * 2 + q * 16, sl + q * 8);
            }
        }
        asm volatile("cp.async.commit_group;");
    };

    issue(0);

    const int lrow = lane & 15, lko = (lane >> 4) * 8;

    for (int k0 = 0; k0 < nk; k0++) {
        asm volatile("cp.async.wait_group 0;");
        __syncthreads();
        if (k0 + 1 < nk) issue(k0 + 1);

        const bf16* bAh = sbuf + (size_t)(k0 & 1) * STAGE_E;
        const bf16* bAl = bAh + BM * RS;
        const bf16* bBh = bAh + 2 * BM * RS;
        const bf16* bBl = bBh + 128 * RS;

        #pragma unroll
        for (int kk = 0; kk < 32; kk += 16) {
            uint32_t Afh[MT][4], Afl[MT][4];
            #pragma unroll
            for (int mt = 0; mt < MT; mt++)
                LDSM4(Afh[mt], s2u(&bAh[(wm * (BM / 2) + mt * 16 + lrow) * RS + kk + lko]));
            #pragma unroll
            for (int mt = 0; mt < MT; mt++)
                LDSM4(Afl[mt], s2u(&bAl[(wm * (BM / 2) + mt * 16 + lrow) * RS + kk + lko]));

            #pragma unroll
            for (int p = 0; p < 4; p++) {
                uint32_t Bfh[4], Bfl[4];
                LDSM4(Bfh, s2u(&bBh[(wn * 64 + p * 16 + lrow) * RS + kk + lko]));
                LDSM4(Bfl, s2u(&bBl[(wn * 64 + p * 16 + lrow) * RS + kk + lko]));
                #pragma unroll
                for (int mt = 0; mt < MT; mt++) {
                    MMA16816(acc[mt][2 * p + 0], Afh[mt], Bfh[0], Bfh[2]);
                    MMA16816(acc[mt][2 * p + 1], Afh[mt], Bfh[1], Bfh[3]);
                    MMA16816(acc[mt][2 * p + 0], Afh[mt], Bfl[0], Bfl[2]);
                    MMA16816(acc[mt][2 * p + 1], Afh[mt], Bfl[1], Bfl[3]);
                    MMA16816(acc[mt][2 * p + 0], Afl[mt], Bfh[0], Bfh[2]);
                    MMA16816(acc[mt][2 * p + 1], Afl[mt], Bfh[1], Bfh[3]);
                }
            }
        }
    }

    float* Cb = C ? (C + coff) : nullptr;
    const float* Rb = (EPI == 3) ? (Res + coff) : nullptr;
    bf16* Hb = OUTBF ? (Chi + coff) : nullptr;
    bf16* Lb = OUTBF ? (Clo + coff) : nullptr;
    const int rb = lane >> 2, cbl = (lane & 3) * 2;
    #pragma unroll
    for (int mt = 0; mt < MT; mt++) {
        #pragma unroll
        for (int half = 0; half < 2; half++) {
            int r = m0 + wm * (BM / 2) + mt * 16 + rb + half * 8;
            #pragma unroll
            for (int j = 0; j < 8; j++) {
                int cc = n0 + wn * 64 + (j >> 1) * 16 + (j & 1) * 8 + cbl;
                float x0 = acc[mt][j][half * 2 + 0] * scale;
                float x1 = acc[mt][j][half * 2 + 1] * scale;
                if (EPI >= 1) { x0 += bias[cc]; x1 += bias[cc + 1]; }
                if (EPI == 2) {
                    x0 = 0.5f * x0 * (1.f + erff(x0 * 0.70710678118654752f));
                    x1 = 0.5f * x1 * (1.f + erff(x1 * 0.70710678118654752f));
                }
                if (EPI == 3) {
                    float2 rv = *(const float2*)(Rb + (size_t)r * ldc + cc);
                    x0 += rv.x; x1 += rv.y;
                }
                if (Cb) *(float2*)(Cb + (size_t)r * ldc + cc) = make_float2(x0, x1);
                if (OUTBF) {
                    uint32_t h, l;
                    split2(x0, x1, h, l);
                    *(uint32_t*)(Hb + (size_t)r * ldc + cc) = h;
                    *(uint32_t*)(Lb + (size_t)r * ldc + cc) = l;
                }
            }
        }
    }
}

// ================= fused flash attention (128-row Q blocks, 256 threads) =================
// MASK 0: causal. MASK 1: patch. DH=64. 8 warps; warp w owns Q rows [w*16, w*16+16).
constexpr int FR = 72;
constexpr int FQE = 2 * 128 * FR;              // Q hi+lo elems (128 rows)
constexpr int FSTE = 4 * 64 * FR;              // per KV stage (Khi,Klo,Vhi,Vlo)
constexpr int FSZ = (FQE + 2 * FSTE) * 2;      // bytes = 110592

template<int MASK>
__global__ __launch_bounds__(256, 2)
void flash_att(const bf16* __restrict__ Qh, const bf16* __restrict__ Ql, int ldq, long hiQ, long loQ,
               const bf16* __restrict__ Kh, const bf16* __restrict__ Kl,
               const bf16* __restrict__ Vh, const bf16* __restrict__ Vl, int ldk, long hiK, long loK,
               const int* __restrict__ pidx,
               bf16* __restrict__ Ohp, bf16* __restrict__ Olp, int ldo, long hiO, long loO,
               int nKeys)
{
    extern __shared__ __align__(16) bf16 sbuf[];

    const int tid = threadIdx.x, lane = tid & 31, wid = tid >> 5;
    const int z = blockIdx.y;
    const int m0 = ((int)gridDim.x - 1 - (int)blockIdx.x) * 128;   // heavy-first
    const int b = z / Hc;

    const long qoff = (long)(z / Hc) * hiQ + (long)(z % Hc) * loQ;
    const long koff = (long)(z / Hc) * hiK + (long)(z % Hc) * loK;
    const long ooff = (long)(z / Hc) * hiO + (long)(z % Hc) * loO;

    const bf16* pQh = Qh + qoff;
    const bf16* pQl = Ql + qoff;
    const bf16* pKh = Kh + koff;
    const bf16* pKl = Kl + koff;
    const bf16* pVh = Vh + koff;
    const bf16* pVl = Vl + koff;

    const uint32_t sbase = s2u(sbuf);

    // Q loader mapping: 256 threads over 128 rows x 2 halves
    const int qrow = tid >> 1, qhalf = (tid & 1) * 32;
    {
        uint32_t dq = sbase + (uint32_t)(qrow * FR + qhalf) * 2;
        const bf16* sq = pQh + (size_t)(m0 + qrow) * ldq + qhalf;
        const bf16* sl = pQl + (size_t)(m0 + qrow) * ldq + qhalf;
        #pragma unroll
        for (int q = 0; q < 4; q++) {
            cp16(dq + q * 16, sq + q * 8);
            cp16(dq + 128 * FR * 2 + q * 16, sl + q * 8);
        }
    }

    // KV loader mapping: 256 threads over 64 rows x 4 quarters
    const int kvrow = tid >> 2, kvq = (tid & 3) * 16;
    auto issueKV = [&](int jb) {
        uint32_t base = sbase + (uint32_t)(FQE + (jb & 1) * FSTE) * 2;
        const bf16* srcs[4];
        srcs[0] = pKh + (size_t)(jb * 64 + kvrow) * ldk + kvq;
        srcs[1] = pKl + (size_t)(jb * 64 + kvrow) * ldk + kvq;
        srcs[2] = pVh + (size_t)(jb * 64 + kvrow) * ldk + kvq;
        srcs[3] = pVl + (size_t)(jb * 64 + kvrow) * ldk + kvq;
        #pragma unroll
        for (int t = 0; t < 4; t++) {
            uint32_t dst = base + (uint32_t)(t * 64 * FR + kvrow * FR + kvq) * 2;
            #pragma unroll
            for (int q = 0; q < 2; q++)
                cp16(dst + q * 16, srcs[t] + q * 8);
        }
        asm volatile("cp.async.commit_group;");
    };

    issueKV(0);

    int nb;
    if (MASK == 0) {
        nb = m0 / 64 + 2;
        int nbmax = nKeys / 64;
        if (nb > nbmax) nb = nbmax;
    } else {
        nb = nKeys / 64;
    }

    const int gr0 = m0 + wid * 16 + (lane >> 2);
    int lim0, lim1;
    if (MASK == 0) { lim0 = gr0; lim1 = gr0 + 8; }
    else           { lim0 = pidx[b * Sc + gr0]; lim1 = pidx[b * Sc + gr0 + 8]; }

    float o[8][4];
    #pragma unroll
    for (int g = 0; g < 8; g++)
        #pragma unroll
        for (int q = 0; q < 4; q++) o[g][q] = 0.f;
    float mr0 = -1e30f, mr1 = -1e30f, lr0 = 0.f, lr1 = 0.f;

    const int lrow = lane & 15, lko = (lane >> 4) * 8;
    const int tkrow = (lane & 7) + ((lane >> 4) << 3);
    const int tncol = ((lane >> 3) & 1) * 8;
    const int cbl = (lane & 3) * 2;

    for (int jb = 0; jb < nb; jb++) {
        asm volatile("cp.async.wait_group 0;");
        __syncthreads();
        if (jb + 1 < nb) issueKV(jb + 1);

        const bf16* sQh = sbuf;
        const bf16* sQl = sQh + 128 * FR;
        const bf16* sKh = sbuf + FQE + (size_t)(jb & 1) * FSTE;
        const bf16* sKl = sKh + 64 * FR;
        const bf16* sVh = sKh + 2 * 64 * FR;
        const bf16* sVl = sKh + 3 * 64 * FR;

        // ---- S = Q @ K^T (bf16x3)
        float s[8][4];
        #pragma unroll
        for (int g = 0; g < 8; g++)
            #pragma unroll
            for (int q = 0; q < 4; q++) s[g][q] = 0.f;

        #pragma unroll
        for (int kk = 0; kk < 64; kk += 16) {
            uint32_t qfh[4], qfl[4];
            LDSM4(qfh, s2u(&sQh[(wid * 16 + lrow) * FR + kk + lko]));
            LDSM4(qfl, s2u(&sQl[(wid * 16 + lrow) * FR + kk + lko]));
            #pragma unroll
            for (int p = 0; p < 4; p++) {
                uint32_t kfh[4], kfl[4];
                LDSM4(kfh, s2u(&sKh[(p * 16 + lrow) * FR + kk + lko]));
                LDSM4(kfl, s2u(&sKl[(p * 16 + lrow) * FR + kk + lko]));
                MMA16816(s[2 * p + 0], qfh, kfh[0], kfh[2]);
                MMA16816(s[2 * p + 1], qfh, kfh[1], kfh[3]);
                MMA16816(s[2 * p + 0], qfh, kfl[0], kfl[2]);
                MMA16816(s[2 * p + 1], qfh, kfl[1], kfl[3]);
                MMA16816(s[2 * p + 0], qfl, kfh[0], kfh[2]);
                MMA16816(s[2 * p + 1], qfl, kfh[1], kfh[3]);
            }
        }

        // ---- scale + mask
        const int jbase = jb * 64;
        #pragma unroll
        for (int g = 0; g < 8; g++) {
            #pragma unroll
            for (int q = 0; q < 4; q++) {
                int col = jbase + g * 8 + cbl + (q & 1);
                int lim = (q < 2) ? lim0 : lim1;
                float v = s[g][q] * 0.125f;
                s[g][q] = (col > lim) ? -1e30f : v;
            }
        }

        // ---- online softmax (fast exp)
        float mx0 = -1e30f, mx1 = -1e30f;
        #pragma unroll
        for (int g = 0; g < 8; g++) {
            mx0 = fmaxf(mx0, fmaxf(s[g][0], s[g][1]));
            mx1 = fmaxf(mx1, fmaxf(s[g][2], s[g][3]));
        }
        mx0 = fmaxf(mx0, __shfl_xor_sync(0xffffffffu, mx0, 1));
        mx0 = fmaxf(mx0, __shfl_xor_sync(0xffffffffu, mx0, 2));
        mx1 = fmaxf(mx1, __shfl_xor_sync(0xffffffffu, mx1, 1));
        mx1 = fmaxf(mx1, __shfl_xor_sync(0xffffffffu, mx1, 2));

        float nm0 = fmaxf(mr0, mx0), nm1 = fmaxf(mr1, mx1);
        float c0 = __expf(mr0 - nm0), c1 = __expf(mr1 - nm1);

        float sum0 = 0.f, sum1 = 0.f;
        #pragma unroll
        for (int g = 0; g < 8; g++) {
            s[g][0] = __expf(s[g][0] - nm0); sum0 += s[g][0];
            s[g][1] = __expf(s[g][1] - nm0); sum0 += s[g][1];
            s[g][2] = __expf(s[g][2] - nm1); sum1 += s[g][2];
            s[g][3] = __expf(s[g][3] - nm1); sum1 += s[g][3];
        }
        sum0 += __shfl_xor_sync(0xffffffffu, sum0, 1);
        sum0 += __shfl_xor_sync(0xffffffffu, sum0, 2);
        sum1 += __shfl_xor_sync(0xffffffffu, sum1, 1);
        sum1 += __shfl_xor_sync(0xffffffffu, sum1, 2);

        lr0 = lr0 * c0 + sum0;
        lr1 = lr1 * c1 + sum1;
        mr0 = nm0; mr1 = nm1;

        #pragma unroll
        for (int g = 0; g < 8; g++) {
            o[g][0] *= c0; o[g][1] *= c0;
            o[g][2] *= c1; o[g][3] *= c1;
        }

        // ---- O += P @ V
        #pragma unroll
        for (int t = 0; t < 4; t++) {
            uint32_t Pa_h[4], Pa_l[4];
            split2(s[2 * t][0],     s[2 * t][1],     Pa_h[0], Pa_l[0]);
            split2(s[2 * t][2],     s[2 * t][3],     Pa_h[1], Pa_l[1]);
            split2(s[2 * t + 1][0], s[2 * t + 1][1], Pa_h[2], Pa_l[2]);
            split2(s[2 * t + 1][2], s[2 * t + 1][3], Pa_h[3], Pa_l[3]);
            #pragma unroll
            for (int p = 0; p < 4; p++) {
                uint32_t vfh[4], vfl[4];
                LDSM4T(vfh, s2u(&sVh[(t * 16 + tkrow) * FR + p * 16 + tncol]));
                LDSM4T(vfl, s2u(&sVl[(t * 16 + tkrow) * FR + p * 16 + tncol]));
                MMA16816(o[2 * p + 0], Pa_h, vfh[0], vfh[2]);
                MMA16816(o[2 * p + 1], Pa_h, vfh[1], vfh[3]);
                MMA16816(o[2 * p + 0], Pa_h, vfl[0], vfl[2]);
                MMA16816(o[2 * p + 1], Pa_h, vfl[1], vfl[3]);
                MMA16816(o[2 * p + 0], Pa_l, vfh[0], vfh[2]);
                MMA16816(o[2 * p + 1], Pa_l, vfh[1], vfh[3]);
            }
        }
    }

    // ---- epilogue
    float inv0 = 1.f / lr0, inv1 = 1.f / lr1;
    bf16* Ob_h = Ohp + ooff;
    bf16* Ob_l = Olp + ooff;
    const int r0 = m0 + wid * 16 + (lane >> 2);
    #pragma unroll
    for (int g = 0; g < 8; g++) {
        int cc = g * 8 + cbl;
        uint32_t h, l;
        split2(o[g][0] * inv0, o[g][1] * inv0, h, l);
        *(uint32_t*)(Ob_h + (size_t)r0 * ldo + cc) = h;
        *(uint32_t*)(Ob_l + (size_t)r0 * ldo + cc) = l;
        split2(o[g][2] * inv1, o[g][3] * inv1, h, l);
        *(uint32_t*)(Ob_h + (size_t)(r0 + 8) * ldo + cc) = h;
        *(uint32_t*)(Ob_l + (size_t)(r0 + 8) * ldo + cc) = l;
    }
}

// ---------------- fp32 -> bf16 hi/lo conversion ----------------
__global__ void cvt_k(const float* __restrict__ x, bf16* __restrict__ hi,
                      bf16* __restrict__ lo, long n)
{
    long i = ((long)blockIdx.x * blockDim.x + threadIdx.x) * 4;
    if (i >= n) return;
    float4 v = *(const float4*)(x + i);
    uint32_t h0, l0, h1, l1;
    split2(v.x, v.y, h0, l0);
    split2(v.z, v.w, h1, l1);
    *(uint2*)(hi + i) = make_uint2(h0, h1);
    *(uint2*)(lo + i) = make_uint2(l0, l1);
}

// ---------------- embedding ----------------
__global__ void embed_k(const int* __restrict__ seq, const float* __restrict__ bemb,
                        const float* __restrict__ pemb, float* __restrict__ x)
{
    int r = blockIdx.x;
    int s = r % Sc;
    int tok = seq[r];
    int c = threadIdx.x * 4;
    float4 e = *(const float4*)(bemb + (long)tok * Dc + c);
    float4 p = *(const float4*)(pemb + (long)s * Dc + c);
    e.x += p.x; e.y += p.y; e.z += p.z; e.w += p.w;
    *(float4*)(x + (long)r * Dc + c) = e;
}

// ---------------- layernorm -> bf16 hi/lo planes ----------------
__global__ void ln_k(const float* __restrict__ x, const float* __restrict__ g,
                     const float* __restrict__ b, bf16* __restrict__ hi,
                     bf16* __restrict__ lo)
{
    const int row = blockIdx.x;
    const int tid = threadIdx.x;
    const float* xr = x + (long)row * Dc;
    float4 v = *(const float4*)(xr + tid * 4);
    float s = v.x + v.y + v.z + v.w;
    float tot = block_sum(s);
    float m = tot * (1.f / Dc);
    float dx0 = v.x - m, dx1 = v.y - m, dx2 = v.z - m, dx3 = v.w - m;
    float q = dx0 * dx0 + dx1 * dx1 + dx2 * dx2 + dx3 * dx3;
    float totq = block_sum(q);
    float rs = rsqrtf(totq * (1.f / Dc) + 1e-5f);
    float4 gg = *(const float4*)(g + tid * 4);
    float4 bb = *(const float4*)(b + tid * 4);
    float o0 = dx0 * rs * gg.x + bb.x;
    float o1 = dx1 * rs * gg.y + bb.y;
    float o2 = dx2 * rs * gg.z + bb.z;
    float o3 = dx3 * rs * gg.w + bb.w;
    uint32_t h0, l0, h1, l1;
    split2(o0, o1, h0, l0);
    split2(o2, o3, h1, l1);
    *(uint2*)(hi + (long)row * Dc + tid * 4) = make_uint2(h0, h1);
    *(uint2*)(lo + (long)row * Dc + tid * 4) = make_uint2(l0, l1);
}

// ---------------- inclusive cumsum ----------------
__global__ void cumsum_k(const int* __restrict__ bd, int* __restrict__ pidx)
{
    __shared__ int s[Sc];
    const int b = blockIdx.x, t = threadIdx.x;
    s[t] = bd[b * Sc + t];
    __syncthreads();
    for (int off = 1; off < Sc; off <<= 1) {
        int v = (t >= off) ? s[t - off] : 0;
        __syncthreads();
        s[t] += v;
        __syncthreads();
    }
    pidx[b * Sc + t] = s[t];
}

// ---------------- launcher ----------------
extern "C" void kernel_launch(void* const* d_in, const int* in_sizes, int n_in,
                              void* d_out, int out_size)
{
    const int*   byte_seq  = (const int*)  d_in[0];
    const float* patch_rep = (const float*)d_in[1];
    const int*   patch_bd  = (const int*)  d_in[2];
    const float* byte_emb  = (const float*)d_in[3];
    const float* pos_emb   = (const float*)d_in[4];
    const float* sa_in_w   = (const float*)d_in[5];
    const float* sa_in_b   = (const float*)d_in[6];
    const float* sa_out_w  = (const float*)d_in[7];
    const float* sa_out_b  = (const float*)d_in[8];
    const float* ca_in_w   = (const float*)d_in[9];
    const float* ca_in_b   = (const float*)d_in[10];
    const float* ca_out_w  = (const float*)d_in[11];
    const float* ca_out_b  = (const float*)d_in[12];
    const float* ffn_w1    = (const float*)d_in[13];
    const float* ffn_b1    = (const float*)d_in[14];
    const float* ffn_w2    = (const float*)d_in[15];
    const float* ffn_b2    = (const float*)d_in[16];
    const float* ln_g      = (const float*)d_in[17];
    const float* ln_b      = (const float*)d_in[18];
    const float* norm_g    = (const float*)d_in[19];
    const float* norm_b    = (const float*)d_in[20];
    const float* out_w     = (const float*)d_in[21];
    float* out = (float*)d_out;

    float* gx;
    int* gpidx;
    bf16 *whi, *wlo, *hh, *hl, *qh, *ql, *cqh, *cql, *ckh, *ckl, *fh, *fl, *prh, *prl;
    cudaGetSymbolAddress((void**)&gx,   g_x);
    cudaGetSymbolAddress((void**)&gpidx, g_pidx);
    cudaGetSymbolAddress((void**)&whi, g_whi);
    cudaGetSymbolAddress((void**)&wlo, g_wlo);
    cudaGetSymbolAddress((void**)&hh,  g_hh);
    cudaGetSymbolAddress((void**)&hl,  g_hl);
    cudaGetSymbolAddress((void**)&qh,  g_qh);
    cudaGetSymbolAddress((void**)&ql,  g_ql);
    cudaGetSymbolAddress((void**)&cqh, g_cqh);
    cudaGetSymbolAddress((void**)&cql, g_cql);
    cudaGetSymbolAddress((void**)&ckh, g_ckh);
    cudaGetSymbolAddress((void**)&ckl, g_ckl);
    cudaGetSymbolAddress((void**)&fh,  g_fh);
    cudaGetSymbolAddress((void**)&fl,  g_fl);
    cudaGetSymbolAddress((void**)&prh, g_prh);
    cudaGetSymbolAddress((void**)&prl, g_prl);

    constexpr int T128 = tcs_bytes(128);
    constexpr int T64  = tcs_bytes(64);
    cudaFuncSetAttribute(gemm_tc<1, true, 128>,  cudaFuncAttributeMaxDynamicSharedMemorySize, T128);
    cudaFuncSetAttribute(gemm_tc<2, true, 128>,  cudaFuncAttributeMaxDynamicSharedMemorySize, T128);
    cudaFuncSetAttribute(gemm_tc<0, false, 64>,  cudaFuncAttributeMaxDynamicSharedMemorySize, T64);
    cudaFuncSetAttribute(gemm_tc<1, true, 64>,   cudaFuncAttributeMaxDynamicSharedMemorySize, T64);
    cudaFuncSetAttribute(gemm_tc<3, false, 64>,  cudaFuncAttributeMaxDynamicSharedMemorySize, T64);
    cudaFuncSetAttribute(flash_att<0>, cudaFuncAttributeMaxDynamicSharedMemorySize, FSZ);
    cudaFuncSetAttribute(flash_att<1>, cudaFuncAttributeMaxDynamicSharedMemorySize, FSZ);

    auto cvt = [&](const float* src, bf16* dh, bf16* dl, long n) {
        cvt_k<<<(unsigned)((n / 4 + 255) / 256), 256>>>(src, dh, dl, n);
    };
    cvt(sa_in_w,  whi + OFF_SAIN,  wlo + OFF_SAIN,  (long)Lc * 3 * Dc * Dc);
    cvt(sa_out_w, whi + OFF_SAOUT, wlo + OFF_SAOUT, (long)Lc * Dc * Dc);
    cvt(ca_in_w,  whi + OFF_CAIN,  wlo + OFF_CAIN,  (long)Lc * 3 * Dc * Dc);
    cvt(ca_out_w, whi + OFF_CAOUT, wlo + OFF_CAOUT, (long)Lc * Dc * Dc);
    cvt(ffn_w1,   whi + OFF_FFN1,  wlo + OFF_FFN1,  (long)Lc * 4 * Dc * Dc);
    cvt(ffn_w2,   whi + OFF_FFN2,  wlo + OFF_FFN2,  (long)Lc * 4 * Dc * Dc);
    cvt(out_w,    whi + OFF_OUTW,  wlo + OFF_OUTW,  (long)Vc * Dc);
    cvt(patch_rep, prh, prl, (long)Bc * Pc * Dc);

    embed_k<<<BS, 256>>>(byte_seq, byte_emb, pos_emb, gx);
    cumsum_k<<<Bc, Sc>>>(patch_bd, gpidx);

    for (int l = 0; l < Lc; l++) {
        // ===== self-attention =====
        ln_k<<<BS, 256>>>(gx, ln_g + (long)(l * 3 + 0) * Dc, ln_b + (long)(l * 3 + 0) * Dc, hh, hl);

        gemm_tc<1, true, 128><<<dim3(3 * Dc / 128, BS / 128), 128, T128>>>(
            hh, hl, Dc, 0, 0, 1,
            whi + OFF_SAIN + (long)l * 3 * Dc * Dc, wlo + OFF_SAIN + (long)l * 3 * Dc * Dc, Dc, 0, 0, 1,
            sa_in_b + (long)l * 3 * Dc, nullptr,
            nullptr, qh, ql, 3 * Dc, 0, 0, 1, Dc, 1.f);

        flash_att<0><<<dim3(Sc / 128, Bc * Hc), 256, FSZ>>>(
            qh, ql, 3 * Dc, (long)Sc * 3 * Dc, DH,
            qh + Dc, ql + Dc, qh + 2 * Dc, ql + 2 * Dc, 3 * Dc, (long)Sc * 3 * Dc, DH,
            nullptr,
            cqh, cql, Dc, (long)Sc * Dc, DH, Sc);

        gemm_tc<3, false, 64><<<dim3(Dc / 128, BS / 64), 128, T64>>>(
            cqh, cql, Dc, 0, 0, 1,
            whi + OFF_SAOUT + (long)l * Dc * Dc, wlo + OFF_SAOUT + (long)l * Dc * Dc, Dc, 0, 0, 1,
            sa_out_b + (long)l * Dc, gx,
            gx, nullptr, nullptr, Dc, 0, 0, 1, Dc, 1.f);

        // ===== cross-attention =====
        ln_k<<<BS, 256>>>(gx, ln_g + (long)(l * 3 + 1) * Dc, ln_b + (long)(l * 3 + 1) * Dc, hh, hl);

        gemm_tc<1, true, 64><<<dim3(Dc / 128, BS / 64), 128, T64>>>(
            hh, hl, Dc, 0, 0, 1,
            whi + OFF_CAIN + (long)l * 3 * Dc * Dc, wlo + OFF_CAIN + (long)l * 3 * Dc * Dc, Dc, 0, 0, 1,
            ca_in_b + (long)l * 3 * Dc, nullptr,
            nullptr, cqh, cql, Dc, 0, 0, 1, Dc, 1.f);

        gemm_tc<1, true, 64><<<dim3(2 * Dc / 128, (Bc * Pc) / 64), 128, T64>>>(
            prh, prl, Dc, 0, 0, 1,
            whi + OFF_CAIN + (long)l * 3 * Dc * Dc + (long)Dc * Dc,
            wlo + OFF_CAIN + (long)l * 3 * Dc * Dc + (long)Dc * Dc, Dc, 0, 0, 1,
            ca_in_b + (long)l * 3 * Dc + Dc, nullptr,
            nullptr, ckh, ckl, 2 * Dc, 0, 0, 1, Dc, 1.f);

        flash_att<1><<<dim3(Sc / 128, Bc * Hc), 256, FSZ>>>(
            cqh, cql, Dc, (long)Sc * Dc, DH,
            ckh, ckl, ckh + Dc, ckl + Dc, 2 * Dc, (long)Pc * 2 * Dc, DH,
            gpidx,
            cqh, cql, Dc, (long)Sc * Dc, DH, Pc);

        gemm_tc<3, false, 64><<<dim3(Dc / 128, BS / 64), 128, T64>>>(
            cqh, cql, Dc, 0, 0, 1,
            whi + OFF_CAOUT + (long)l * Dc * Dc, wlo + OFF_CAOUT + (long)l * Dc * Dc, Dc, 0, 0, 1,
            ca_out_b + (long)l * Dc, gx,
            gx, nullptr, nullptr, Dc, 0, 0, 1, Dc, 1.f);

        // ===== FFN =====
        ln_k<<<BS, 256>>>(gx, ln_g + (long)(l * 3 + 2) * Dc, ln_b + (long)(l * 3 + 2) * Dc, hh, hl);

        gemm_tc<2, true, 128><<<dim3(4 * Dc / 128, BS / 128), 128, T128>>>(
            hh, hl, Dc, 0, 0, 1,
            whi + OFF_FFN1 + (long)l * 4 * Dc * Dc, wlo + OFF_FFN1 + (long)l * 4 * Dc * Dc, Dc, 0, 0, 1,
            ffn_b1 + (long)l * 4 * Dc, nullptr,
            nullptr, fh, fl, 4 * Dc, 0, 0, 1, Dc, 1.f);

        gemm_tc<3, false, 64><<<dim3(Dc / 128, BS / 64), 128, T64>>>(
            fh, fl, 4 * Dc, 0, 0, 1,
            whi + OFF_FFN2 + (long)l * Dc * 4 * Dc, wlo + OFF_FFN2 + (long)l * Dc * 4 * Dc, 4 * Dc, 0, 0, 1,
            ffn_b2 + (long)l * Dc, gx,
            gx, nullptr, nullptr, Dc, 0, 0, 1, 4 * Dc, 1.f);
    }

    // final LN + vocab projection
    ln_k<<<BS, 256>>>(gx, norm_g, norm_b, hh, hl);
    gemm_tc<0, false, 64><<<dim3(Vc / 128, BS / 64), 128, T64>>>(
        hh, hl, Dc, 0, 0, 1,
        whi + OFF_OUTW, wlo + OFF_OUTW, Dc, 0, 0, 1,
        nullptr, nullptr,
        out, nullptr, nullptr, Vc, 0, 0, 1, Dc, 1.f);
}